// round 1
// baseline (speedup 1.0000x reference)
#include <cuda_runtime.h>
#include <cuda_bf16.h>
#include <math.h>

// ---------------------------------------------------------------------------
// MS_MSA fused kernel set.
// Shapes fixed by the problem instance:
//   b=1, H=W=256 (N_TOK=65536), C=512, HEADS=8, D=64, CS=2
// ---------------------------------------------------------------------------

#define NTOK 65536
#define CCH  512
#define HH   256
#define WW   256

// ------------------------- scratch (device globals) ------------------------
__device__ float g_q[33554432];      // q_inp [n, c]
__device__ float g_k[33554432];      // k_inp [n, c]
__device__ float g_v[33554432];      // v_inp [n, c]
__device__ float g_mask[33554432];   // SAR mask [n, c]
__device__ float g_pemid[33554432];  // pe intermediate [n, c]
__device__ float g_a[131072];        // conv3 output [2, H, W]
__device__ float g_ss[131072];       // sar_sobel [2, H, W]
__device__ float g_bnp[4];           // per-channel BN scale/shift
__device__ float g_gpart[4194304];   // gram partials [128 chunks][8*64*64]
__device__ float g_gram[32768];      // G [8][64][64]
__device__ float g_npart[262144];    // norm partials [256][1024]
__device__ float g_norms[1024];      // nk[512], nq[512]
__device__ float g_attn[32768];      // attn [8][64][64]
__device__ float g_wpeff[262144];    // Wp_eff [512][512]

// ------------------------------ SAR path -----------------------------------

// conv3: 3x3 conv, 2->2 channels, pad=1
__global__ void conv3_kernel(const float* __restrict__ sar,
                             const float* __restrict__ w,
                             const float* __restrict__ b,
                             float* __restrict__ a) {
    int n = blockIdx.x * 256 + threadIdx.x;
    if (n >= NTOK) return;
    int y = n >> 8, x = n & 255;
    #pragma unroll
    for (int co = 0; co < 2; co++) {
        float acc = b[co];
        #pragma unroll
        for (int ci = 0; ci < 2; ci++) {
            #pragma unroll
            for (int ky = 0; ky < 3; ky++) {
                int yy = y + ky - 1;
                if (yy < 0 || yy >= HH) continue;
                #pragma unroll
                for (int kx = 0; kx < 3; kx++) {
                    int xx = x + kx - 1;
                    if (xx < 0 || xx >= WW) continue;
                    acc += w[((co * 2 + ci) * 3 + ky) * 3 + kx] *
                           sar[ci * NTOK + (yy << 8) + xx];
                }
            }
        }
        a[co * NTOK + n] = acc;
    }
}

// BN batch statistics (training mode): per-channel scale/shift
__global__ void bnstats_kernel(const float* __restrict__ a,
                               const float* __restrict__ gg,
                               const float* __restrict__ bb,
                               float* __restrict__ bnp) {
    int c = blockIdx.x;
    __shared__ float sh[512], sh2[512];
    float s = 0.f, s2 = 0.f;
    for (int i = threadIdx.x; i < NTOK; i += 512) {
        float v = a[c * NTOK + i];
        s += v; s2 += v * v;
    }
    sh[threadIdx.x] = s; sh2[threadIdx.x] = s2;
    __syncthreads();
    for (int st = 256; st > 0; st >>= 1) {
        if (threadIdx.x < st) {
            sh[threadIdx.x] += sh[threadIdx.x + st];
            sh2[threadIdx.x] += sh2[threadIdx.x + st];
        }
        __syncthreads();
    }
    if (threadIdx.x == 0) {
        float mean = sh[0] * (1.f / NTOK);
        float var = sh2[0] * (1.f / NTOK) - mean * mean;
        float sc = gg[c] * rsqrtf(var + 1e-5f);
        bnp[c * 2] = sc;
        bnp[c * 2 + 1] = bb[c] - mean * sc;
    }
}

// bn + sobel + combine -> ss[2,H,W]
__global__ void sobel_ss_kernel(const float* __restrict__ a,
                                const float* __restrict__ bnp,
                                const float* __restrict__ sb,
                                float* __restrict__ ss) {
    int n = blockIdx.x * 256 + threadIdx.x;
    if (n >= NTOK) return;
    int y = n >> 8, x = n & 255;
    float sc0 = bnp[0], sh0 = bnp[1], sc1 = bnp[2], sh1 = bnp[3];
    float t[3][3];
    #pragma unroll
    for (int ky = 0; ky < 3; ky++) {
        int yy = y + ky - 1;
        #pragma unroll
        for (int kx = 0; kx < 3; kx++) {
            int xx = x + kx - 1;
            if (yy >= 0 && yy < HH && xx >= 0 && xx < WW) {
                int idx = (yy << 8) + xx;
                t[ky][kx] = a[idx] * sc0 + sh0 + a[NTOK + idx] * sc1 + sh1;
            } else t[ky][kx] = 0.f;
        }
    }
    float gy = -(t[0][0] + 2.f * t[0][1] + t[0][2]) + (t[2][0] + 2.f * t[2][1] + t[2][2]);
    float gx = -(t[0][0] + 2.f * t[1][0] + t[2][0]) + (t[0][2] + 2.f * t[1][2] + t[2][2]);
    float s0 = gy + sb[0], s1 = gx + sb[1], s2 = gy + sb[2], s3 = gx + sb[3];
    float bc0 = a[n] * sc0 + sh0;
    float bc1 = a[NTOK + n] * sc1 + sh1;
    ss[n]        = sqrtf(s0 * s0 + s1 * s1) + bc0;
    ss[NTOK + n] = sqrtf(s2 * s2 + s3 * s3) + bc1;
}

// mask = e1 + e2 + e3, e3 factored through the 1x1 conv.
// block: 512 threads = channels, 32 consecutive pixels per block (same row).
__global__ void __launch_bounds__(512) mask_kernel(
    const float* __restrict__ ss,
    const float* __restrict__ w2, const float* __restrict__ b2,
    const float* __restrict__ w32, const float* __restrict__ b32,
    const float* __restrict__ dw, const float* __restrict__ db,
    float* __restrict__ mask) {
    int c = threadIdx.x;
    int p0 = blockIdx.x * 32;
    int y = p0 >> 8, x0 = p0 & 255;

    __shared__ float ssp[2][5][36];
    for (int t = threadIdx.x; t < 360; t += 512) {
        int ch = t / 180, rem = t % 180;
        int ry = rem / 36, rx = rem % 36;
        int yy = y + ry - 2, xx = x0 + rx - 2;
        ssp[ch][ry][rx] = (yy >= 0 && yy < HH && xx >= 0 && xx < WW)
                          ? ss[ch * NTOK + (yy << 8) + xx] : 0.f;
    }
    __syncthreads();

    float w20 = w2[c * 2], w21 = w2[c * 2 + 1], bb2 = b2[c];
    float w32r[18];
    #pragma unroll
    for (int kk = 0; kk < 18; kk++) w32r[kk] = w32[c * 18 + kk];
    float bb32 = b32[c];
    float dwr[25];
    #pragma unroll
    for (int kk = 0; kk < 25; kk++) dwr[kk] = dw[c * 25 + kk];
    float bbd = db[c];

    for (int p = 0; p < 32; p++) {
        float S0 = 0.f, S1 = 0.f, Wsum = 0.f, e2acc = bb32;
        #pragma unroll
        for (int dy = 0; dy < 5; dy++) {
            int yy = y + dy - 2;
            bool yok = (yy >= 0 && yy < HH);
            #pragma unroll
            for (int dx = 0; dx < 5; dx++) {
                float w = dwr[dy * 5 + dx];
                float v0 = ssp[0][dy][p + dx];
                float v1 = ssp[1][dy][p + dx];
                S0 += w * v0; S1 += w * v1;
                int xx = x0 + p + dx - 2;
                if (yok && xx >= 0 && xx < WW) Wsum += w;
                if (dy >= 1 && dy < 4 && dx >= 1 && dx < 4) {
                    int kk = (dy - 1) * 3 + (dx - 1);
                    e2acc += w32r[kk] * v0 + w32r[9 + kk] * v1;
                }
            }
        }
        float c0 = ssp[0][2][p + 2], c1 = ssp[1][2][p + 2];
        float e1 = w20 * c0 + w21 * c1 + bb2;
        float e2 = 1.f / (1.f + expf(-e2acc));
        float e3 = w20 * S0 + w21 * S1 + bb2 * Wsum + bbd;
        mask[(size_t)(p0 + p) * CCH + c] = e1 + e2 + e3;
    }
}

// ------------------------------- SGEMM --------------------------------------
// C[M,N] = A[M,K] (optionally * Gt elementwise) @ B[K,N] (+ bias)
// 128x128x16 tiles, 256 threads, 8x8 per thread, double-buffered smem.

#define GEMM_LOAD_TILE(buf, kk)                                                   \
    do {                                                                          \
        for (int rr = 0; rr < 2; rr++) {                                          \
            int r = ar + (rr << 6);                                               \
            const float* ap = A + (size_t)(bm + r) * K + (kk) + ac;               \
            float4 va = *reinterpret_cast<const float4*>(ap);                     \
            if (GATED) {                                                          \
                const float* gp = Gt + (size_t)(bm + r) * K + (kk) + ac;          \
                float4 vg = *reinterpret_cast<const float4*>(gp);                 \
                va.x *= vg.x; va.y *= vg.y; va.z *= vg.z; va.w *= vg.w;           \
            }                                                                     \
            As[buf][ac + 0][r] = va.x; As[buf][ac + 1][r] = va.y;                 \
            As[buf][ac + 2][r] = va.z; As[buf][ac + 3][r] = va.w;                 \
        }                                                                         \
        for (int rr = 0; rr < 2; rr++) {                                          \
            int r = br + (rr << 3);                                               \
            const float* bp = B + (size_t)((kk) + r) * N + bn + bc;               \
            *reinterpret_cast<float4*>(&Bs[buf][r][bc]) =                         \
                *reinterpret_cast<const float4*>(bp);                             \
        }                                                                         \
    } while (0)

template <int GATED, int BIAS>
__global__ void __launch_bounds__(256, 2) sgemm128(
    const float* __restrict__ A, const float* __restrict__ Gt,
    const float* __restrict__ B, const float* __restrict__ bias,
    float* __restrict__ C, int M, int N, int K) {
    __shared__ float As[2][16][128];
    __shared__ float Bs[2][16][128];
    const int tid = threadIdx.x;
    const int bm = blockIdx.y << 7;
    const int bn = blockIdx.x << 7;
    const int ar = tid >> 2;
    const int ac = (tid & 3) << 2;
    const int br = tid >> 5;
    const int bc = (tid & 31) << 2;
    const int ty = tid >> 4, tx = tid & 15;
    const int row0 = ty << 3, col0 = tx << 3;

    float acc[8][8];
    #pragma unroll
    for (int i = 0; i < 8; i++)
        #pragma unroll
        for (int j = 0; j < 8; j++) acc[i][j] = 0.f;

    GEMM_LOAD_TILE(0, 0);
    __syncthreads();
    const int NK = K >> 4;
    for (int kt = 0; kt < NK; kt++) {
        int cur = kt & 1;
        if (kt + 1 < NK) {
            int nxt = cur ^ 1;
            GEMM_LOAD_TILE(nxt, (kt + 1) << 4);
        }
        #pragma unroll
        for (int k = 0; k < 16; k++) {
            float4 a0 = *reinterpret_cast<const float4*>(&As[cur][k][row0]);
            float4 a1 = *reinterpret_cast<const float4*>(&As[cur][k][row0 + 4]);
            float4 b0 = *reinterpret_cast<const float4*>(&Bs[cur][k][col0]);
            float4 b1 = *reinterpret_cast<const float4*>(&Bs[cur][k][col0 + 4]);
            float av[8] = {a0.x, a0.y, a0.z, a0.w, a1.x, a1.y, a1.z, a1.w};
            float bv[8] = {b0.x, b0.y, b0.z, b0.w, b1.x, b1.y, b1.z, b1.w};
            #pragma unroll
            for (int i = 0; i < 8; i++)
                #pragma unroll
                for (int j = 0; j < 8; j++) acc[i][j] += av[i] * bv[j];
        }
        __syncthreads();
    }

    #pragma unroll
    for (int i = 0; i < 8; i++) {
        float* cp = C + (size_t)(bm + row0 + i) * N + bn + col0;
        #pragma unroll
        for (int j = 0; j < 8; j += 4) {
            float4 v;
            v.x = acc[i][j]; v.y = acc[i][j + 1];
            v.z = acc[i][j + 2]; v.w = acc[i][j + 3];
            if (BIAS) {
                v.x += bias[bn + col0 + j];
                v.y += bias[bn + col0 + j + 1];
                v.z += bias[bn + col0 + j + 2];
                v.w += bias[bn + col0 + j + 3];
            }
            *reinterpret_cast<float4*>(cp + j) = v;
        }
    }
}

// ------------------------ norms (column sum-of-squares) ---------------------
__global__ void norm_part_kernel(const float* __restrict__ Km,
                                 const float* __restrict__ Qm,
                                 float* __restrict__ part) {
    int b = blockIdx.x;     // 256 blocks, 256 rows each
    int t = threadIdx.x;    // 256 threads
    float k0 = 0.f, k1 = 0.f, q0 = 0.f, q1 = 0.f;
    int base = b * 256;
    for (int r = 0; r < 256; r++) {
        const float* kr = Km + (size_t)(base + r) * CCH;
        const float* qr = Qm + (size_t)(base + r) * CCH;
        float a;
        a = kr[t];       k0 += a * a;
        a = kr[t + 256]; k1 += a * a;
        a = qr[t];       q0 += a * a;
        a = qr[t + 256]; q1 += a * a;
    }
    float* pp = part + (size_t)b * 1024;
    pp[t] = k0; pp[t + 256] = k1; pp[512 + t] = q0; pp[768 + t] = q1;
}

__global__ void norm_reduce_kernel(const float* __restrict__ part,
                                   float* __restrict__ norms) {
    int c = blockIdx.x * 512 + threadIdx.x;  // 0..1023
    float s = 0.f;
    for (int b = 0; b < 256; b++) s += part[(size_t)b * 1024 + c];
    norms[c] = sqrtf(s);
}

// --------------------------- per-head Gram matrices -------------------------
// G[h] = K_h^T Q_h, chunked over tokens. grid (128 chunks, 8 heads).
__global__ void __launch_bounds__(256) gram_part_kernel(
    const float* __restrict__ Km, const float* __restrict__ Qm,
    float* __restrict__ part) {
    int h = blockIdx.y;
    int chunk = blockIdx.x;
    __shared__ float ks[64][64];
    __shared__ float qs[64][64];
    int tid = threadIdx.x;
    int lt = tid >> 2;
    int lc = (tid & 3) * 16;
    int i0 = (tid >> 4) * 4;
    int j0 = (tid & 15) * 4;
    float acc[4][4];
    #pragma unroll
    for (int i = 0; i < 4; i++)
        #pragma unroll
        for (int j = 0; j < 4; j++) acc[i][j] = 0.f;

    int base = chunk * 512;
    for (int sub = 0; sub < 8; sub++) {
        int row = base + sub * 64 + lt;
        const float* kp = Km + (size_t)row * CCH + h * 64 + lc;
        const float* qp = Qm + (size_t)row * CCH + h * 64 + lc;
        #pragma unroll
        for (int u = 0; u < 4; u++) {
            *reinterpret_cast<float4*>(&ks[lt][lc + u * 4]) =
                *reinterpret_cast<const float4*>(kp + u * 4);
            *reinterpret_cast<float4*>(&qs[lt][lc + u * 4]) =
                *reinterpret_cast<const float4*>(qp + u * 4);
        }
        __syncthreads();
        #pragma unroll
        for (int t = 0; t < 64; t++) {
            float4 kv = *reinterpret_cast<const float4*>(&ks[t][i0]);
            float4 qv = *reinterpret_cast<const float4*>(&qs[t][j0]);
            float kr[4] = {kv.x, kv.y, kv.z, kv.w};
            float qr[4] = {qv.x, qv.y, qv.z, qv.w};
            #pragma unroll
            for (int i = 0; i < 4; i++)
                #pragma unroll
                for (int j = 0; j < 4; j++) acc[i][j] += kr[i] * qr[j];
        }
        __syncthreads();
    }
    float* pp = part + ((size_t)chunk * 8 + h) * 4096;
    #pragma unroll
    for (int i = 0; i < 4; i++)
        #pragma unroll
        for (int j = 0; j < 4; j++) pp[(i0 + i) * 64 + j0 + j] = acc[i][j];
}

__global__ void gram_reduce_kernel(const float* __restrict__ part,
                                   float* __restrict__ gram) {
    int e = blockIdx.x * 1024 + threadIdx.x;  // 0..32767
    float s = 0.f;
    for (int c = 0; c < 128; c++) s += part[(size_t)c * 32768 + e];
    gram[e] = s;
}

// --------------------------- attention + fold into Wp -----------------------
__global__ void attn_kernel(const float* __restrict__ G,
                            const float* __restrict__ norms,
                            const float* __restrict__ rescale,
                            float* __restrict__ attn) {
    int h = blockIdx.x;
    int i = threadIdx.x;
    __shared__ float row[64][64];
    float nk = fmaxf(norms[h * 64 + i], 1e-12f);
    float rs = rescale[h];
    float mx = -1e30f;
    for (int j = 0; j < 64; j++) {
        float nq = fmaxf(norms[512 + h * 64 + j], 1e-12f);
        float vv = G[h * 4096 + i * 64 + j] * rs / (nk * nq);
        row[i][j] = vv;
        mx = fmaxf(mx, vv);
    }
    float s = 0.f;
    for (int j = 0; j < 64; j++) {
        float e = expf(row[i][j] - mx);
        row[i][j] = e;
        s += e;
    }
    float inv = 1.f / s;
    for (int j = 0; j < 64; j++)
        attn[h * 4096 + i * 64 + j] = row[i][j] * inv;
}

// Wp_eff[h*64+j][m] = sum_i attn[h,i,j] * Wp[h*64+i][m]
__global__ void wpeff_kernel(const float* __restrict__ attn,
                             const float* __restrict__ Wp,
                             float* __restrict__ wpe) {
    int cp = blockIdx.x;          // 0..511
    int h = cp >> 6, j = cp & 63;
    int t = threadIdx.x;          // 128
    float a0 = 0.f, a1 = 0.f, a2 = 0.f, a3 = 0.f;
    const float* at = attn + h * 4096 + j;
    for (int i = 0; i < 64; i++) {
        float a = at[i * 64];
        const float* w = Wp + (size_t)((h << 6) + i) * CCH;
        a0 += a * w[t];
        a1 += a * w[t + 128];
        a2 += a * w[t + 256];
        a3 += a * w[t + 384];
    }
    float* o = wpe + (size_t)cp * CCH;
    o[t] = a0; o[t + 128] = a1; o[t + 256] = a2; o[t + 384] = a3;
}

// ------------------------------ positional branch ---------------------------
__global__ void pe1_kernel(const float* __restrict__ V,
                           const float* __restrict__ w,
                           float* __restrict__ outp) {
    int idx = blockIdx.x * 256 + threadIdx.x;
    int c = idx & 511;
    int n = idx >> 9;
    int y = n >> 8, x = n & 255;
    float wr[9];
    #pragma unroll
    for (int kk = 0; kk < 9; kk++) wr[kk] = w[c * 9 + kk];
    float acc = 0.f;
    #pragma unroll
    for (int ky = 0; ky < 3; ky++) {
        int yy = y + ky - 1;
        if (yy < 0 || yy >= HH) continue;
        #pragma unroll
        for (int kx = 0; kx < 3; kx++) {
            int xx = x + kx - 1;
            if (xx < 0 || xx >= WW) continue;
            acc += wr[ky * 3 + kx] * V[((size_t)(yy << 8) + xx) * CCH + c];
        }
    }
    outp[idx] = 0.5f * acc * (1.f + erff(acc * 0.70710678118654752f));
}

__global__ void pe2_kernel(const float* __restrict__ P,
                           const float* __restrict__ w,
                           float* __restrict__ outp) {
    int idx = blockIdx.x * 256 + threadIdx.x;
    int c = idx & 511;
    int n = idx >> 9;
    int y = n >> 8, x = n & 255;
    float wr[9];
    #pragma unroll
    for (int kk = 0; kk < 9; kk++) wr[kk] = w[c * 9 + kk];
    float acc = 0.f;
    #pragma unroll
    for (int ky = 0; ky < 3; ky++) {
        int yy = y + ky - 1;
        if (yy < 0 || yy >= HH) continue;
        #pragma unroll
        for (int kx = 0; kx < 3; kx++) {
            int xx = x + kx - 1;
            if (xx < 0 || xx >= WW) continue;
            acc += wr[ky * 3 + kx] * P[((size_t)(yy << 8) + xx) * CCH + c];
        }
    }
    outp[idx] += acc;
}

// --------------------------------- launch -----------------------------------
extern "C" void kernel_launch(void* const* d_in, const int* in_sizes, int n_in,
                              void* d_out, int out_size) {
    const float* x       = (const float*)d_in[0];
    const float* sar     = (const float*)d_in[1];
    const float* Wq      = (const float*)d_in[2];
    const float* Wk      = (const float*)d_in[3];
    const float* Wv      = (const float*)d_in[4];
    const float* rescale = (const float*)d_in[5];
    const float* Wp      = (const float*)d_in[6];
    const float* bp      = (const float*)d_in[7];
    const float* pe1w    = (const float*)d_in[8];
    const float* pe2w    = (const float*)d_in[9];
    const float* conv3w  = (const float*)d_in[10];
    const float* conv3b  = (const float*)d_in[11];
    const float* bng     = (const float*)d_in[12];
    const float* bnb     = (const float*)d_in[13];
    const float* sobelb  = (const float*)d_in[14];
    const float* conv2w  = (const float*)d_in[15];
    const float* conv2b  = (const float*)d_in[16];
    const float* conv32w = (const float*)d_in[17];
    const float* conv32b = (const float*)d_in[18];
    const float* dconvw  = (const float*)d_in[19];
    const float* dconvb  = (const float*)d_in[20];
    float* out = (float*)d_out;

    float *q, *k, *v, *mask, *pemid, *a, *ss, *bnp, *gpart, *gram;
    float *npart, *norms, *attn, *wpeff;
    cudaGetSymbolAddress((void**)&q, g_q);
    cudaGetSymbolAddress((void**)&k, g_k);
    cudaGetSymbolAddress((void**)&v, g_v);
    cudaGetSymbolAddress((void**)&mask, g_mask);
    cudaGetSymbolAddress((void**)&pemid, g_pemid);
    cudaGetSymbolAddress((void**)&a, g_a);
    cudaGetSymbolAddress((void**)&ss, g_ss);
    cudaGetSymbolAddress((void**)&bnp, g_bnp);
    cudaGetSymbolAddress((void**)&gpart, g_gpart);
    cudaGetSymbolAddress((void**)&gram, g_gram);
    cudaGetSymbolAddress((void**)&npart, g_npart);
    cudaGetSymbolAddress((void**)&norms, g_norms);
    cudaGetSymbolAddress((void**)&attn, g_attn);
    cudaGetSymbolAddress((void**)&wpeff, g_wpeff);

    // SAR mask path
    conv3_kernel<<<256, 256>>>(sar, conv3w, conv3b, a);
    bnstats_kernel<<<2, 512>>>(a, bng, bnb, bnp);
    sobel_ss_kernel<<<256, 256>>>(a, bnp, sobelb, ss);
    mask_kernel<<<2048, 512>>>(ss, conv2w, conv2b, conv32w, conv32b,
                               dconvw, dconvb, mask);

    // q/k/v projections
    dim3 gg(4, 512);
    sgemm128<0, 0><<<gg, 256>>>(x, nullptr, Wq, nullptr, q, NTOK, CCH, CCH);
    sgemm128<0, 0><<<gg, 256>>>(x, nullptr, Wk, nullptr, k, NTOK, CCH, CCH);
    sgemm128<0, 0><<<gg, 256>>>(x, nullptr, Wv, nullptr, v, NTOK, CCH, CCH);

    // norms + per-head Gram
    norm_part_kernel<<<256, 256>>>(k, q, npart);
    norm_reduce_kernel<<<2, 512>>>(npart, norms);
    gram_part_kernel<<<dim3(128, 8), 256>>>(k, q, gpart);
    gram_reduce_kernel<<<32, 1024>>>(gpart, gram);

    // attention weights folded into Wp
    attn_kernel<<<8, 64>>>(gram, norms, rescale, attn);
    wpeff_kernel<<<512, 128>>>(attn, Wp, wpeff);

    // out_c = (v * mask) @ Wp_eff + bp    -> d_out
    sgemm128<1, 1><<<gg, 256>>>(v, mask, wpeff, bp, out, NTOK, CCH, CCH);

    // positional branch: depthwise3x3 -> gelu -> depthwise3x3, added to d_out
    pe1_kernel<<<131072, 256>>>(v, pe1w, pemid);
    pe2_kernel<<<131072, 256>>>(pemid, pe2w, out);
}

// round 2
// speedup vs baseline: 1.8940x; 1.8940x over previous
#include <cuda_runtime.h>
#include <cuda_bf16.h>
#include <math.h>
#include <stdint.h>

// ---------------------------------------------------------------------------
// MS_MSA fused kernel set — round 2: TF32 tensor-core GEMMs (mma.sync m16n8k8)
// Shapes fixed: b=1, H=W=256 (NTOK=65536), C=512, HEADS=8, D=64, CS=2
// ---------------------------------------------------------------------------

#define NTOK 65536
#define CCH  512
#define HH   256
#define WW   256

// ------------------------- scratch (device globals) ------------------------
__device__ float g_q[33554432];      // q_inp [n, c]
__device__ float g_k[33554432];      // k_inp [n, c]
__device__ float g_v[33554432];      // v_inp [n, c]
__device__ float g_mask[33554432];   // SAR mask [n, c]
__device__ float g_pemid[33554432];  // pe intermediate [n, c]
__device__ float g_a[131072];        // conv3 output [2, H, W]
__device__ float g_ss[131072];       // sar_sobel [2, H, W]
__device__ float g_bnp[4];           // per-channel BN scale/shift
__device__ float g_gpart[4194304];   // gram partials [128 chunks][8*64*64]
__device__ float g_gram[32768];      // G [8][64][64]
__device__ float g_npart[262144];    // norm partials [256][1024]
__device__ float g_norms[1024];      // nk[512], nq[512]
__device__ float g_attn[32768];      // attn [8][64][64]
__device__ float g_wpeff[262144];    // Wp_eff [512][512]

// ------------------------------ SAR path -----------------------------------

__global__ void conv3_kernel(const float* __restrict__ sar,
                             const float* __restrict__ w,
                             const float* __restrict__ b,
                             float* __restrict__ a) {
    int n = blockIdx.x * 256 + threadIdx.x;
    if (n >= NTOK) return;
    int y = n >> 8, x = n & 255;
    #pragma unroll
    for (int co = 0; co < 2; co++) {
        float acc = b[co];
        #pragma unroll
        for (int ci = 0; ci < 2; ci++) {
            #pragma unroll
            for (int ky = 0; ky < 3; ky++) {
                int yy = y + ky - 1;
                if (yy < 0 || yy >= HH) continue;
                #pragma unroll
                for (int kx = 0; kx < 3; kx++) {
                    int xx = x + kx - 1;
                    if (xx < 0 || xx >= WW) continue;
                    acc += w[((co * 2 + ci) * 3 + ky) * 3 + kx] *
                           sar[ci * NTOK + (yy << 8) + xx];
                }
            }
        }
        a[co * NTOK + n] = acc;
    }
}

__global__ void bnstats_kernel(const float* __restrict__ a,
                               const float* __restrict__ gg,
                               const float* __restrict__ bb,
                               float* __restrict__ bnp) {
    int c = blockIdx.x;
    __shared__ float sh[512], sh2[512];
    float s = 0.f, s2 = 0.f;
    for (int i = threadIdx.x; i < NTOK; i += 512) {
        float v = a[c * NTOK + i];
        s += v; s2 += v * v;
    }
    sh[threadIdx.x] = s; sh2[threadIdx.x] = s2;
    __syncthreads();
    for (int st = 256; st > 0; st >>= 1) {
        if (threadIdx.x < st) {
            sh[threadIdx.x] += sh[threadIdx.x + st];
            sh2[threadIdx.x] += sh2[threadIdx.x + st];
        }
        __syncthreads();
    }
    if (threadIdx.x == 0) {
        float mean = sh[0] * (1.f / NTOK);
        float var = sh2[0] * (1.f / NTOK) - mean * mean;
        float sc = gg[c] * rsqrtf(var + 1e-5f);
        bnp[c * 2] = sc;
        bnp[c * 2 + 1] = bb[c] - mean * sc;
    }
}

__global__ void sobel_ss_kernel(const float* __restrict__ a,
                                const float* __restrict__ bnp,
                                const float* __restrict__ sb,
                                float* __restrict__ ss) {
    int n = blockIdx.x * 256 + threadIdx.x;
    if (n >= NTOK) return;
    int y = n >> 8, x = n & 255;
    float sc0 = bnp[0], sh0 = bnp[1], sc1 = bnp[2], sh1 = bnp[3];
    float t[3][3];
    #pragma unroll
    for (int ky = 0; ky < 3; ky++) {
        int yy = y + ky - 1;
        #pragma unroll
        for (int kx = 0; kx < 3; kx++) {
            int xx = x + kx - 1;
            if (yy >= 0 && yy < HH && xx >= 0 && xx < WW) {
                int idx = (yy << 8) + xx;
                t[ky][kx] = a[idx] * sc0 + sh0 + a[NTOK + idx] * sc1 + sh1;
            } else t[ky][kx] = 0.f;
        }
    }
    float gy = -(t[0][0] + 2.f * t[0][1] + t[0][2]) + (t[2][0] + 2.f * t[2][1] + t[2][2]);
    float gx = -(t[0][0] + 2.f * t[1][0] + t[2][0]) + (t[0][2] + 2.f * t[1][2] + t[2][2]);
    float s0 = gy + sb[0], s1 = gx + sb[1], s2 = gy + sb[2], s3 = gx + sb[3];
    float bc0 = a[n] * sc0 + sh0;
    float bc1 = a[NTOK + n] * sc1 + sh1;
    ss[n]        = sqrtf(s0 * s0 + s1 * s1) + bc0;
    ss[NTOK + n] = sqrtf(s2 * s2 + s3 * s3) + bc1;
}

// mask = e1 + e2 + e3 (e3 factored through the 1x1 conv)
__global__ void __launch_bounds__(512) mask_kernel(
    const float* __restrict__ ss,
    const float* __restrict__ w2, const float* __restrict__ b2,
    const float* __restrict__ w32, const float* __restrict__ b32,
    const float* __restrict__ dw, const float* __restrict__ db,
    float* __restrict__ mask) {
    int c = threadIdx.x;
    int p0 = blockIdx.x * 32;
    int y = p0 >> 8, x0 = p0 & 255;
    bool interior = (y >= 2 && y < 254 && x0 >= 2 && (x0 + 33) < 256);

    __shared__ float ssp[2][5][36];
    for (int t = threadIdx.x; t < 360; t += 512) {
        int ch = t / 180, rem = t % 180;
        int ry = rem / 36, rx = rem % 36;
        int yy = y + ry - 2, xx = x0 + rx - 2;
        ssp[ch][ry][rx] = (yy >= 0 && yy < HH && xx >= 0 && xx < WW)
                          ? ss[ch * NTOK + (yy << 8) + xx] : 0.f;
    }
    __syncthreads();

    float w20 = w2[c * 2], w21 = w2[c * 2 + 1], bb2 = b2[c];
    float w32r[18];
    #pragma unroll
    for (int kk = 0; kk < 18; kk++) w32r[kk] = w32[c * 18 + kk];
    float bb32 = b32[c];
    float dwr[25];
    float wtot = 0.f;
    #pragma unroll
    for (int kk = 0; kk < 25; kk++) { dwr[kk] = dw[c * 25 + kk]; wtot += dwr[kk]; }
    float bbd = db[c];

    for (int p = 0; p < 32; p++) {
        float S0 = 0.f, S1 = 0.f, Wsum = 0.f, e2acc = bb32;
        #pragma unroll
        for (int dy = 0; dy < 5; dy++) {
            int yy = y + dy - 2;
            bool yok = (yy >= 0 && yy < HH);
            #pragma unroll
            for (int dx = 0; dx < 5; dx++) {
                float w = dwr[dy * 5 + dx];
                float v0 = ssp[0][dy][p + dx];
                float v1 = ssp[1][dy][p + dx];
                S0 += w * v0; S1 += w * v1;
                if (!interior) {
                    int xx = x0 + p + dx - 2;
                    if (yok && xx >= 0 && xx < WW) Wsum += w;
                }
                if (dy >= 1 && dy < 4 && dx >= 1 && dx < 4) {
                    int kk = (dy - 1) * 3 + (dx - 1);
                    e2acc += w32r[kk] * v0 + w32r[9 + kk] * v1;
                }
            }
        }
        if (interior) Wsum = wtot;
        float c0 = ssp[0][2][p + 2], c1 = ssp[1][2][p + 2];
        float e1 = w20 * c0 + w21 * c1 + bb2;
        float e2 = 1.f / (1.f + expf(-e2acc));
        float e3 = w20 * S0 + w21 * S1 + bb2 * Wsum + bbd;
        mask[(size_t)(p0 + p) * CCH + c] = e1 + e2 + e3;
    }
}

// -------------------------- TF32 tensor-core GEMM ---------------------------
// C[M, 512] = A[M, K] (optionally elementwise-gated) @ B[K, 512] (+ bias).
// Up to 3 (B, C) pairs selected by blockIdx.x (fused QKV).
// 128x128 block tile, K-tile 16, 8 warps (2x4), warp tile 64x32, m16n8k8 TF32.

__device__ __forceinline__ float f2tf32(float x) {
    float r;
    asm("cvt.rna.tf32.f32 %0, %1;" : "=f"(r) : "f"(x));
    return r;
}

__device__ __forceinline__ void mma_tf32(float* c, const uint32_t* a,
                                         const uint32_t* b) {
    asm volatile(
        "mma.sync.aligned.m16n8k8.row.col.f32.tf32.tf32.f32 "
        "{%0,%1,%2,%3}, {%4,%5,%6,%7}, {%8,%9}, {%0,%1,%2,%3};"
        : "+f"(c[0]), "+f"(c[1]), "+f"(c[2]), "+f"(c[3])
        : "r"(a[0]), "r"(a[1]), "r"(a[2]), "r"(a[3]), "r"(b[0]), "r"(b[1]));
}

#define TG_LOAD(buf, kk)                                                        \
    do {                                                                        \
        _Pragma("unroll")                                                       \
        for (int rr = 0; rr < 2; rr++) {                                        \
            int r = ar + (rr << 6);                                             \
            const float* ap = A + (size_t)(bm + r) * K + (kk) + ac;             \
            float4 va = *reinterpret_cast<const float4*>(ap);                   \
            if (GATED) {                                                        \
                const float* gp = Gt + (size_t)(bm + r) * K + (kk) + ac;        \
                float4 vg = *reinterpret_cast<const float4*>(gp);               \
                va.x *= vg.x; va.y *= vg.y; va.z *= vg.z; va.w *= vg.w;         \
            }                                                                   \
            As[buf][ac + 0][r] = f2tf32(va.x);                                  \
            As[buf][ac + 1][r] = f2tf32(va.y);                                  \
            As[buf][ac + 2][r] = f2tf32(va.z);                                  \
            As[buf][ac + 3][r] = f2tf32(va.w);                                  \
        }                                                                       \
        _Pragma("unroll")                                                       \
        for (int rr = 0; rr < 2; rr++) {                                        \
            int r = br + (rr << 3);                                             \
            const float* bp = B + (size_t)((kk) + r) * CCH + bn + bc;           \
            float4 vb = *reinterpret_cast<const float4*>(bp);                   \
            float4 vc;                                                          \
            vc.x = f2tf32(vb.x); vc.y = f2tf32(vb.y);                           \
            vc.z = f2tf32(vb.z); vc.w = f2tf32(vb.w);                           \
            *reinterpret_cast<float4*>(&Bs[buf][r][bc]) = vc;                   \
        }                                                                       \
    } while (0)

template <int GATED, int BIAS>
__global__ void __launch_bounds__(256, 2) tgemm128(
    const float* __restrict__ A, const float* __restrict__ Gt,
    const float* __restrict__ B0, const float* __restrict__ B1,
    const float* __restrict__ B2, const float* __restrict__ bias,
    float* __restrict__ C0, float* __restrict__ C1, float* __restrict__ C2,
    int M, int K) {
    __shared__ __align__(16) float As[2][16][136];
    __shared__ __align__(16) float Bs[2][16][136];

    const int tid = threadIdx.x;
    const int which = blockIdx.x >> 2;
    const float* B = (which == 0) ? B0 : (which == 1) ? B1 : B2;
    float* C = (which == 0) ? C0 : (which == 1) ? C1 : C2;
    const int bn = (blockIdx.x & 3) << 7;
    const int bm = blockIdx.y << 7;

    const int lane = tid & 31;
    const int g = lane >> 2;        // 0..7
    const int tig = lane & 3;       // 0..3
    const int w = tid >> 5;         // 0..7
    const int wm = (w >> 2) * 64;   // 0 or 64
    const int wn = (w & 3) * 32;    // 0..96

    const int ar = tid >> 2;
    const int ac = (tid & 3) << 2;
    const int br = tid >> 5;
    const int bc = (tid & 31) << 2;

    float acc[4][4][4];
    #pragma unroll
    for (int i = 0; i < 4; i++)
        #pragma unroll
        for (int j = 0; j < 4; j++)
            #pragma unroll
            for (int e = 0; e < 4; e++) acc[i][j][e] = 0.f;

    TG_LOAD(0, 0);
    __syncthreads();
    const int NK = K >> 4;
    for (int kt = 0; kt < NK; kt++) {
        int cur = kt & 1;
        if (kt + 1 < NK) TG_LOAD(cur ^ 1, (kt + 1) << 4);
        #pragma unroll
        for (int ks = 0; ks < 2; ks++) {
            int kk = ks << 3;
            uint32_t af[4][4];
            #pragma unroll
            for (int mt = 0; mt < 4; mt++) {
                int m0 = wm + (mt << 4);
                af[mt][0] = __float_as_uint(As[cur][kk + tig][m0 + g]);
                af[mt][1] = __float_as_uint(As[cur][kk + tig][m0 + g + 8]);
                af[mt][2] = __float_as_uint(As[cur][kk + tig + 4][m0 + g]);
                af[mt][3] = __float_as_uint(As[cur][kk + tig + 4][m0 + g + 8]);
            }
            uint32_t bf[4][2];
            #pragma unroll
            for (int nt = 0; nt < 4; nt++) {
                int n0 = wn + (nt << 3);
                bf[nt][0] = __float_as_uint(Bs[cur][kk + tig][n0 + g]);
                bf[nt][1] = __float_as_uint(Bs[cur][kk + tig + 4][n0 + g]);
            }
            #pragma unroll
            for (int mt = 0; mt < 4; mt++)
                #pragma unroll
                for (int nt = 0; nt < 4; nt++)
                    mma_tf32(acc[mt][nt], af[mt], bf[nt]);
        }
        __syncthreads();
    }

    #pragma unroll
    for (int mt = 0; mt < 4; mt++) {
        int row = bm + wm + (mt << 4) + g;
        #pragma unroll
        for (int nt = 0; nt < 4; nt++) {
            int col = wn + (nt << 3) + (tig << 1);   // within [0,128)
            float b0 = 0.f, b1 = 0.f;
            if (BIAS) {
                b0 = bias[bn + col];
                b1 = bias[bn + col + 1];
            }
            float2 v0, v1;
            v0.x = acc[mt][nt][0] + b0; v0.y = acc[mt][nt][1] + b1;
            v1.x = acc[mt][nt][2] + b0; v1.y = acc[mt][nt][3] + b1;
            *reinterpret_cast<float2*>(C + (size_t)row * CCH + bn + col) = v0;
            *reinterpret_cast<float2*>(C + (size_t)(row + 8) * CCH + bn + col) = v1;
        }
    }
}

// ------------------------ norms (column sum-of-squares) ---------------------
__global__ void norm_part_kernel(const float* __restrict__ Km,
                                 const float* __restrict__ Qm,
                                 float* __restrict__ part) {
    int b = blockIdx.x;
    int t = threadIdx.x;
    float k0 = 0.f, k1 = 0.f, q0 = 0.f, q1 = 0.f;
    int base = b * 256;
    for (int r = 0; r < 256; r++) {
        const float* kr = Km + (size_t)(base + r) * CCH;
        const float* qr = Qm + (size_t)(base + r) * CCH;
        float a;
        a = kr[t];       k0 += a * a;
        a = kr[t + 256]; k1 += a * a;
        a = qr[t];       q0 += a * a;
        a = qr[t + 256]; q1 += a * a;
    }
    float* pp = part + (size_t)b * 1024;
    pp[t] = k0; pp[t + 256] = k1; pp[512 + t] = q0; pp[768 + t] = q1;
}

__global__ void norm_reduce_kernel(const float* __restrict__ part,
                                   float* __restrict__ norms) {
    int c = blockIdx.x * 512 + threadIdx.x;
    float s = 0.f;
    for (int b = 0; b < 256; b++) s += part[(size_t)b * 1024 + c];
    norms[c] = sqrtf(s);
}

// --------------------------- per-head Gram matrices -------------------------
__global__ void __launch_bounds__(256) gram_part_kernel(
    const float* __restrict__ Km, const float* __restrict__ Qm,
    float* __restrict__ part) {
    int h = blockIdx.y;
    int chunk = blockIdx.x;
    __shared__ float ks[64][64];
    __shared__ float qs[64][64];
    int tid = threadIdx.x;
    int lt = tid >> 2;
    int lc = (tid & 3) * 16;
    int i0 = (tid >> 4) * 4;
    int j0 = (tid & 15) * 4;
    float acc[4][4];
    #pragma unroll
    for (int i = 0; i < 4; i++)
        #pragma unroll
        for (int j = 0; j < 4; j++) acc[i][j] = 0.f;

    int base = chunk * 512;
    for (int sub = 0; sub < 8; sub++) {
        int row = base + sub * 64 + lt;
        const float* kp = Km + (size_t)row * CCH + h * 64 + lc;
        const float* qp = Qm + (size_t)row * CCH + h * 64 + lc;
        #pragma unroll
        for (int u = 0; u < 4; u++) {
            *reinterpret_cast<float4*>(&ks[lt][lc + u * 4]) =
                *reinterpret_cast<const float4*>(kp + u * 4);
            *reinterpret_cast<float4*>(&qs[lt][lc + u * 4]) =
                *reinterpret_cast<const float4*>(qp + u * 4);
        }
        __syncthreads();
        #pragma unroll
        for (int t = 0; t < 64; t++) {
            float4 kv = *reinterpret_cast<const float4*>(&ks[t][i0]);
            float4 qv = *reinterpret_cast<const float4*>(&qs[t][j0]);
            float kr[4] = {kv.x, kv.y, kv.z, kv.w};
            float qr[4] = {qv.x, qv.y, qv.z, qv.w};
            #pragma unroll
            for (int i = 0; i < 4; i++)
                #pragma unroll
                for (int j = 0; j < 4; j++) acc[i][j] += kr[i] * qr[j];
        }
        __syncthreads();
    }
    float* pp = part + ((size_t)chunk * 8 + h) * 4096;
    #pragma unroll
    for (int i = 0; i < 4; i++)
        #pragma unroll
        for (int j = 0; j < 4; j++) pp[(i0 + i) * 64 + j0 + j] = acc[i][j];
}

__global__ void gram_reduce_kernel(const float* __restrict__ part,
                                   float* __restrict__ gram) {
    int e = blockIdx.x * 1024 + threadIdx.x;
    float s = 0.f;
    for (int c = 0; c < 128; c++) s += part[(size_t)c * 32768 + e];
    gram[e] = s;
}

// --------------------------- attention + fold into Wp -----------------------
__global__ void attn_kernel(const float* __restrict__ G,
                            const float* __restrict__ norms,
                            const float* __restrict__ rescale,
                            float* __restrict__ attn) {
    int h = blockIdx.x;
    int i = threadIdx.x;
    __shared__ float row[64][64];
    float nk = fmaxf(norms[h * 64 + i], 1e-12f);
    float rs = rescale[h];
    float mx = -1e30f;
    for (int j = 0; j < 64; j++) {
        float nq = fmaxf(norms[512 + h * 64 + j], 1e-12f);
        float vv = G[h * 4096 + i * 64 + j] * rs / (nk * nq);
        row[i][j] = vv;
        mx = fmaxf(mx, vv);
    }
    float s = 0.f;
    for (int j = 0; j < 64; j++) {
        float e = expf(row[i][j] - mx);
        row[i][j] = e;
        s += e;
    }
    float inv = 1.f / s;
    for (int j = 0; j < 64; j++)
        attn[h * 4096 + i * 64 + j] = row[i][j] * inv;
}

__global__ void wpeff_kernel(const float* __restrict__ attn,
                             const float* __restrict__ Wp,
                             float* __restrict__ wpe) {
    int cp = blockIdx.x;
    int h = cp >> 6, j = cp & 63;
    int t = threadIdx.x;
    float a0 = 0.f, a1 = 0.f, a2 = 0.f, a3 = 0.f;
    const float* at = attn + h * 4096 + j;
    for (int i = 0; i < 64; i++) {
        float a = at[i * 64];
        const float* w = Wp + (size_t)((h << 6) + i) * CCH;
        a0 += a * w[t];
        a1 += a * w[t + 128];
        a2 += a * w[t + 256];
        a3 += a * w[t + 384];
    }
    float* o = wpe + (size_t)cp * CCH;
    o[t] = a0; o[t + 128] = a1; o[t + 256] = a2; o[t + 384] = a3;
}

// ------------------------------ positional branch ---------------------------
__global__ void pe1_kernel(const float* __restrict__ V,
                           const float* __restrict__ w,
                           float* __restrict__ outp) {
    int idx = blockIdx.x * 256 + threadIdx.x;
    int c = idx & 511;
    int n = idx >> 9;
    int y = n >> 8, x = n & 255;
    float wr[9];
    #pragma unroll
    for (int kk = 0; kk < 9; kk++) wr[kk] = w[c * 9 + kk];
    float acc = 0.f;
    #pragma unroll
    for (int ky = 0; ky < 3; ky++) {
        int yy = y + ky - 1;
        if (yy < 0 || yy >= HH) continue;
        #pragma unroll
        for (int kx = 0; kx < 3; kx++) {
            int xx = x + kx - 1;
            if (xx < 0 || xx >= WW) continue;
            acc += wr[ky * 3 + kx] * V[((size_t)(yy << 8) + xx) * CCH + c];
        }
    }
    outp[idx] = 0.5f * acc * (1.f + erff(acc * 0.70710678118654752f));
}

__global__ void pe2_kernel(const float* __restrict__ P,
                           const float* __restrict__ w,
                           float* __restrict__ outp) {
    int idx = blockIdx.x * 256 + threadIdx.x;
    int c = idx & 511;
    int n = idx >> 9;
    int y = n >> 8, x = n & 255;
    float wr[9];
    #pragma unroll
    for (int kk = 0; kk < 9; kk++) wr[kk] = w[c * 9 + kk];
    float acc = 0.f;
    #pragma unroll
    for (int ky = 0; ky < 3; ky++) {
        int yy = y + ky - 1;
        if (yy < 0 || yy >= HH) continue;
        #pragma unroll
        for (int kx = 0; kx < 3; kx++) {
            int xx = x + kx - 1;
            if (xx < 0 || xx >= WW) continue;
            acc += wr[ky * 3 + kx] * P[((size_t)(yy << 8) + xx) * CCH + c];
        }
    }
    outp[idx] += acc;
}

// --------------------------------- launch -----------------------------------
extern "C" void kernel_launch(void* const* d_in, const int* in_sizes, int n_in,
                              void* d_out, int out_size) {
    const float* x       = (const float*)d_in[0];
    const float* sar     = (const float*)d_in[1];
    const float* Wq      = (const float*)d_in[2];
    const float* Wk      = (const float*)d_in[3];
    const float* Wv      = (const float*)d_in[4];
    const float* rescale = (const float*)d_in[5];
    const float* Wp      = (const float*)d_in[6];
    const float* bp      = (const float*)d_in[7];
    const float* pe1w    = (const float*)d_in[8];
    const float* pe2w    = (const float*)d_in[9];
    const float* conv3w  = (const float*)d_in[10];
    const float* conv3b  = (const float*)d_in[11];
    const float* bng     = (const float*)d_in[12];
    const float* bnb     = (const float*)d_in[13];
    const float* sobelb  = (const float*)d_in[14];
    const float* conv2w  = (const float*)d_in[15];
    const float* conv2b  = (const float*)d_in[16];
    const float* conv32w = (const float*)d_in[17];
    const float* conv32b = (const float*)d_in[18];
    const float* dconvw  = (const float*)d_in[19];
    const float* dconvb  = (const float*)d_in[20];
    float* out = (float*)d_out;

    float *q, *k, *v, *mask, *pemid, *a, *ss, *bnp, *gpart, *gram;
    float *npart, *norms, *attn, *wpeff;
    cudaGetSymbolAddress((void**)&q, g_q);
    cudaGetSymbolAddress((void**)&k, g_k);
    cudaGetSymbolAddress((void**)&v, g_v);
    cudaGetSymbolAddress((void**)&mask, g_mask);
    cudaGetSymbolAddress((void**)&pemid, g_pemid);
    cudaGetSymbolAddress((void**)&a, g_a);
    cudaGetSymbolAddress((void**)&ss, g_ss);
    cudaGetSymbolAddress((void**)&bnp, g_bnp);
    cudaGetSymbolAddress((void**)&gpart, g_gpart);
    cudaGetSymbolAddress((void**)&gram, g_gram);
    cudaGetSymbolAddress((void**)&npart, g_npart);
    cudaGetSymbolAddress((void**)&norms, g_norms);
    cudaGetSymbolAddress((void**)&attn, g_attn);
    cudaGetSymbolAddress((void**)&wpeff, g_wpeff);

    // SAR mask path
    conv3_kernel<<<256, 256>>>(sar, conv3w, conv3b, a);
    bnstats_kernel<<<2, 512>>>(a, bng, bnb, bnp);
    sobel_ss_kernel<<<256, 256>>>(a, bnp, sobelb, ss);
    mask_kernel<<<2048, 512>>>(ss, conv2w, conv2b, conv32w, conv32b,
                               dconvw, dconvb, mask);

    // fused QKV projection: N = 3 x 512, TF32 tensor cores
    tgemm128<0, 0><<<dim3(12, 512), 256>>>(x, nullptr, Wq, Wk, Wv, nullptr,
                                           q, k, v, NTOK, CCH);

    // norms + per-head Gram
    norm_part_kernel<<<256, 256>>>(k, q, npart);
    norm_reduce_kernel<<<2, 512>>>(npart, norms);
    gram_part_kernel<<<dim3(128, 8), 256>>>(k, q, gpart);
    gram_reduce_kernel<<<32, 1024>>>(gpart, gram);

    // attention weights folded into Wp
    attn_kernel<<<8, 64>>>(gram, norms, rescale, attn);
    wpeff_kernel<<<512, 128>>>(attn, Wp, wpeff);

    // out_c = (v * mask) @ Wp_eff + bp    -> d_out
    tgemm128<1, 1><<<dim3(4, 512), 256>>>(v, mask, wpeff, wpeff, wpeff, bp,
                                          out, out, out, NTOK, CCH);

    // positional branch
    pe1_kernel<<<131072, 256>>>(v, pe1w, pemid);
    pe2_kernel<<<131072, 256>>>(pemid, pe2w, out);
}

// round 4
// speedup vs baseline: 2.7077x; 1.4296x over previous
#include <cuda_runtime.h>
#include <cuda_bf16.h>
#include <math.h>
#include <stdint.h>

// ---------------------------------------------------------------------------
// MS_MSA — round 4: round-3 design (S = X^T X gram path, K=80 mask GEMM,
// fused positional branch) with the pe halo zero-padding bug fixed.
// Shapes fixed: b=1, H=W=256 (NTOK=65536), C=512, HEADS=8, D=64, CS=2
// ---------------------------------------------------------------------------

#define NTOK 65536
#define CCH  512
#define HH   256
#define WW   256

// ------------------------- scratch (device globals) ------------------------
__device__ float g_v[33554432];      // v_inp [n, c]
__device__ float g_mask[33554432];   // SAR mask [n, c]
__device__ float g_F[5242880];       // mask features [n, 80]
__device__ float g_W1[40960];        // [80, 512] linear weights (e1+e3)
__device__ float g_W2[40960];        // [80, 512] sigmoid-branch weights (e2)
__device__ float g_a[131072];        // conv3 output [2, H, W]
__device__ float g_ss[131072];       // sar_sobel [2, H, W]
__device__ float g_bnp[4];           // per-channel BN scale/shift
__device__ float g_gpart[8388608];   // XtX partials [32][512*512]
__device__ float g_S[262144];        // S = X^T X [512, 512]
__device__ float g_U[262144];        // U  = S @ Wq
__device__ float g_T2[262144];       // T2 = S @ Wk
__device__ float g_gram[32768];      // G [8][64][64]
__device__ float g_norms[1024];      // nk[512], nq[512]
__device__ float g_attn[32768];      // attn [8][64][64]
__device__ float g_wpeff[262144];    // Wp_eff [512][512]

// ------------------------------ SAR path -----------------------------------

__global__ void conv3_kernel(const float* __restrict__ sar,
                             const float* __restrict__ w,
                             const float* __restrict__ b,
                             float* __restrict__ a) {
    int n = blockIdx.x * 256 + threadIdx.x;
    if (n >= NTOK) return;
    int y = n >> 8, x = n & 255;
    #pragma unroll
    for (int co = 0; co < 2; co++) {
        float acc = b[co];
        #pragma unroll
        for (int ci = 0; ci < 2; ci++) {
            #pragma unroll
            for (int ky = 0; ky < 3; ky++) {
                int yy = y + ky - 1;
                if (yy < 0 || yy >= HH) continue;
                #pragma unroll
                for (int kx = 0; kx < 3; kx++) {
                    int xx = x + kx - 1;
                    if (xx < 0 || xx >= WW) continue;
                    acc += w[((co * 2 + ci) * 3 + ky) * 3 + kx] *
                           sar[ci * NTOK + (yy << 8) + xx];
                }
            }
        }
        a[co * NTOK + n] = acc;
    }
}

__global__ void bnstats_kernel(const float* __restrict__ a,
                               const float* __restrict__ gg,
                               const float* __restrict__ bb,
                               float* __restrict__ bnp) {
    int c = blockIdx.x;
    __shared__ float sh[512], sh2[512];
    float s = 0.f, s2 = 0.f;
    for (int i = threadIdx.x; i < NTOK; i += 512) {
        float v = a[c * NTOK + i];
        s += v; s2 += v * v;
    }
    sh[threadIdx.x] = s; sh2[threadIdx.x] = s2;
    __syncthreads();
    for (int st = 256; st > 0; st >>= 1) {
        if (threadIdx.x < st) {
            sh[threadIdx.x] += sh[threadIdx.x + st];
            sh2[threadIdx.x] += sh2[threadIdx.x + st];
        }
        __syncthreads();
    }
    if (threadIdx.x == 0) {
        float mean = sh[0] * (1.f / NTOK);
        float var = sh2[0] * (1.f / NTOK) - mean * mean;
        float sc = gg[c] * rsqrtf(var + 1e-5f);
        bnp[c * 2] = sc;
        bnp[c * 2 + 1] = bb[c] - mean * sc;
    }
}

__global__ void sobel_ss_kernel(const float* __restrict__ a,
                                const float* __restrict__ bnp,
                                const float* __restrict__ sb,
                                float* __restrict__ ss) {
    int n = blockIdx.x * 256 + threadIdx.x;
    if (n >= NTOK) return;
    int y = n >> 8, x = n & 255;
    float sc0 = bnp[0], sh0 = bnp[1], sc1 = bnp[2], sh1 = bnp[3];
    float t[3][3];
    #pragma unroll
    for (int ky = 0; ky < 3; ky++) {
        int yy = y + ky - 1;
        #pragma unroll
        for (int kx = 0; kx < 3; kx++) {
            int xx = x + kx - 1;
            if (yy >= 0 && yy < HH && xx >= 0 && xx < WW) {
                int idx = (yy << 8) + xx;
                t[ky][kx] = a[idx] * sc0 + sh0 + a[NTOK + idx] * sc1 + sh1;
            } else t[ky][kx] = 0.f;
        }
    }
    float gy = -(t[0][0] + 2.f * t[0][1] + t[0][2]) + (t[2][0] + 2.f * t[2][1] + t[2][2]);
    float gx = -(t[0][0] + 2.f * t[1][0] + t[2][0]) + (t[0][2] + 2.f * t[1][2] + t[2][2]);
    float s0 = gy + sb[0], s1 = gx + sb[1], s2 = gy + sb[2], s3 = gx + sb[3];
    float bc0 = a[n] * sc0 + sh0;
    float bc1 = a[NTOK + n] * sc1 + sh1;
    ss[n]        = sqrtf(s0 * s0 + s1 * s1) + bc0;
    ss[NTOK + n] = sqrtf(s2 * s2 + s3 * s3) + bc1;
}

// Build mask feature matrix F[n][80]:
//   [0..24]  ss0 5x5 patch (zero-padded), [25..49] ss1 patch,
//   [50..74] tap validity, [78] = 1.0, rest 0.
__global__ void __launch_bounds__(256) fbuild_kernel(
    const float* __restrict__ ss, float* __restrict__ F) {
    __shared__ float Fs[64 * 80];
    int p0 = blockIdx.x * 64;
    int tid = threadIdx.x;
    int pix = tid >> 2;
    int t4 = tid & 3;
    int n = p0 + pix;
    int y = n >> 8, x = n & 255;
    for (int t = t4; t < 25; t += 4) {
        int dy = t / 5, dx = t % 5;
        int yy = y + dy - 2, xx = x + dx - 2;
        bool ok = (yy >= 0 && yy < HH && xx >= 0 && xx < WW);
        float s0 = 0.f, s1 = 0.f;
        if (ok) {
            int idx = (yy << 8) + xx;
            s0 = ss[idx];
            s1 = ss[NTOK + idx];
        }
        Fs[pix * 80 + t] = s0;
        Fs[pix * 80 + 25 + t] = s1;
        Fs[pix * 80 + 50 + t] = ok ? 1.f : 0.f;
    }
    if (t4 == 0) {
        Fs[pix * 80 + 75] = 0.f;
        Fs[pix * 80 + 76] = 0.f;
        Fs[pix * 80 + 77] = 0.f;
        Fs[pix * 80 + 78] = 1.f;
        Fs[pix * 80 + 79] = 0.f;
    }
    __syncthreads();
    float* dst = F + (size_t)p0 * 80;
    for (int e = tid; e < 64 * 80; e += 256) dst[e] = Fs[e];
}

// Build W1 (linear e1+e3) and W2 (pre-sigmoid e2), both [80][512] K-major.
__global__ void wbuild_kernel(const float* __restrict__ w2c, const float* __restrict__ b2,
                              const float* __restrict__ w32, const float* __restrict__ b32,
                              const float* __restrict__ dw, const float* __restrict__ db,
                              float* __restrict__ W1, float* __restrict__ W2) {
    int c = threadIdx.x;
    float w20 = w2c[c * 2], w21 = w2c[c * 2 + 1], bb2 = b2[c], bbd = db[c];
    for (int t = 0; t < 25; t++) {
        float d = dw[c * 25 + t];
        float a0 = d * w20, a1 = d * w21, a2 = d * bb2;
        if (t == 12) { a0 += w20; a1 += w21; a2 += bb2; }
        W1[t * 512 + c] = a0;
        W1[(25 + t) * 512 + c] = a1;
        W1[(50 + t) * 512 + c] = a2;
        float e0 = 0.f, e1 = 0.f;
        int dy = t / 5, dx = t % 5;
        if (dy >= 1 && dy <= 3 && dx >= 1 && dx <= 3) {
            int kk = (dy - 1) * 3 + (dx - 1);
            e0 = w32[c * 18 + kk];
            e1 = w32[c * 18 + 9 + kk];
        }
        W2[t * 512 + c] = e0;
        W2[(25 + t) * 512 + c] = e1;
        W2[(50 + t) * 512 + c] = 0.f;
    }
    for (int kk = 75; kk < 80; kk++) {
        W1[kk * 512 + c] = (kk == 78) ? bbd : 0.f;
        W2[kk * 512 + c] = (kk == 78) ? b32[c] : 0.f;
    }
}

// -------------------------- TF32 MMA helpers --------------------------------
__device__ __forceinline__ float f2tf32(float x) {
    float r;
    asm("cvt.rna.tf32.f32 %0, %1;" : "=f"(r) : "f"(x));
    return r;
}

__device__ __forceinline__ void mma_tf32(float* c, const uint32_t* a,
                                         const uint32_t* b) {
    asm volatile(
        "mma.sync.aligned.m16n8k8.row.col.f32.tf32.tf32.f32 "
        "{%0,%1,%2,%3}, {%4,%5,%6,%7}, {%8,%9}, {%0,%1,%2,%3};"
        : "+f"(c[0]), "+f"(c[1]), "+f"(c[2]), "+f"(c[3])
        : "r"(a[0]), "r"(a[1]), "r"(a[2]), "r"(a[3]), "r"(b[0]), "r"(b[1]));
}

// -------------------------- TF32 GEMM (generic) ------------------------------
#define TG_LOAD(buf, kk)                                                        \
    do {                                                                        \
        _Pragma("unroll")                                                       \
        for (int rr = 0; rr < 2; rr++) {                                        \
            int r = ar + (rr << 6);                                             \
            const float* ap = A + (size_t)(bm + r) * K + (kk) + ac;             \
            float4 va = *reinterpret_cast<const float4*>(ap);                   \
            if (GATED) {                                                        \
                const float* gp = Gt + (size_t)(bm + r) * K + (kk) + ac;        \
                float4 vg = *reinterpret_cast<const float4*>(gp);               \
                va.x *= vg.x; va.y *= vg.y; va.z *= vg.z; va.w *= vg.w;         \
            }                                                                   \
            As[buf][ac + 0][r] = f2tf32(va.x);                                  \
            As[buf][ac + 1][r] = f2tf32(va.y);                                  \
            As[buf][ac + 2][r] = f2tf32(va.z);                                  \
            As[buf][ac + 3][r] = f2tf32(va.w);                                  \
        }                                                                       \
        _Pragma("unroll")                                                       \
        for (int rr = 0; rr < 2; rr++) {                                        \
            int r = br + (rr << 3);                                             \
            const float* bp = B + (size_t)((kk) + r) * CCH + bn + bc;           \
            float4 vb = *reinterpret_cast<const float4*>(bp);                   \
            float4 vc;                                                          \
            vc.x = f2tf32(vb.x); vc.y = f2tf32(vb.y);                           \
            vc.z = f2tf32(vb.z); vc.w = f2tf32(vb.w);                           \
            *reinterpret_cast<float4*>(&Bs[buf][r][bc]) = vc;                   \
        }                                                                       \
    } while (0)

template <int GATED, int BIAS>
__global__ void __launch_bounds__(256, 2) tgemm128(
    const float* __restrict__ A, const float* __restrict__ Gt,
    const float* __restrict__ B0, const float* __restrict__ B1,
    const float* __restrict__ B2, const float* __restrict__ bias,
    float* __restrict__ C0, float* __restrict__ C1, float* __restrict__ C2,
    int M, int K) {
    __shared__ __align__(16) float As[2][16][136];
    __shared__ __align__(16) float Bs[2][16][136];

    const int tid = threadIdx.x;
    const int which = blockIdx.x >> 2;
    const float* B = (which == 0) ? B0 : (which == 1) ? B1 : B2;
    float* C = (which == 0) ? C0 : (which == 1) ? C1 : C2;
    const int bn = (blockIdx.x & 3) << 7;
    const int bm = blockIdx.y << 7;

    const int lane = tid & 31;
    const int g = lane >> 2;
    const int tig = lane & 3;
    const int w = tid >> 5;
    const int wm = (w >> 2) * 64;
    const int wn = (w & 3) * 32;

    const int ar = tid >> 2;
    const int ac = (tid & 3) << 2;
    const int br = tid >> 5;
    const int bc = (tid & 31) << 2;

    float acc[4][4][4];
    #pragma unroll
    for (int i = 0; i < 4; i++)
        #pragma unroll
        for (int j = 0; j < 4; j++)
            #pragma unroll
            for (int e = 0; e < 4; e++) acc[i][j][e] = 0.f;

    TG_LOAD(0, 0);
    __syncthreads();
    const int NK = K >> 4;
    for (int kt = 0; kt < NK; kt++) {
        int cur = kt & 1;
        if (kt + 1 < NK) TG_LOAD(cur ^ 1, (kt + 1) << 4);
        #pragma unroll
        for (int ks = 0; ks < 2; ks++) {
            int kk = ks << 3;
            uint32_t af[4][4];
            #pragma unroll
            for (int mt = 0; mt < 4; mt++) {
                int m0 = wm + (mt << 4);
                af[mt][0] = __float_as_uint(As[cur][kk + tig][m0 + g]);
                af[mt][1] = __float_as_uint(As[cur][kk + tig][m0 + g + 8]);
                af[mt][2] = __float_as_uint(As[cur][kk + tig + 4][m0 + g]);
                af[mt][3] = __float_as_uint(As[cur][kk + tig + 4][m0 + g + 8]);
            }
            uint32_t bf[4][2];
            #pragma unroll
            for (int nt = 0; nt < 4; nt++) {
                int n0 = wn + (nt << 3);
                bf[nt][0] = __float_as_uint(Bs[cur][kk + tig][n0 + g]);
                bf[nt][1] = __float_as_uint(Bs[cur][kk + tig + 4][n0 + g]);
            }
            #pragma unroll
            for (int mt = 0; mt < 4; mt++)
                #pragma unroll
                for (int nt = 0; nt < 4; nt++)
                    mma_tf32(acc[mt][nt], af[mt], bf[nt]);
        }
        __syncthreads();
    }

    #pragma unroll
    for (int mt = 0; mt < 4; mt++) {
        int row = bm + wm + (mt << 4) + g;
        #pragma unroll
        for (int nt = 0; nt < 4; nt++) {
            int col = wn + (nt << 3) + (tig << 1);
            float b0 = 0.f, b1 = 0.f;
            if (BIAS) {
                b0 = bias[bn + col];
                b1 = bias[bn + col + 1];
            }
            float2 v0, v1;
            v0.x = acc[mt][nt][0] + b0; v0.y = acc[mt][nt][1] + b1;
            v1.x = acc[mt][nt][2] + b0; v1.y = acc[mt][nt][3] + b1;
            *reinterpret_cast<float2*>(C + (size_t)row * CCH + bn + col) = v0;
            *reinterpret_cast<float2*>(C + (size_t)(row + 8) * CCH + bn + col) = v1;
        }
    }
}

// ----------------------- S = X^T X (split-K TF32 GEMM) -----------------------
__global__ void __launch_bounds__(256, 2) xtx_kernel(
    const float* __restrict__ X, float* __restrict__ part) {
    __shared__ __align__(16) float As[2][16][136];
    __shared__ __align__(16) float Bs[2][16][136];

    const int tid = threadIdx.x;
    const int m0 = (blockIdx.x & 3) << 7;
    const int n0 = (blockIdx.x >> 2) << 7;
    const int kbase = blockIdx.y * 2048;

    const int lane = tid & 31;
    const int g = lane >> 2;
    const int tig = lane & 3;
    const int w = tid >> 5;
    const int wm = (w >> 2) * 64;
    const int wn = (w & 3) * 32;

    const int lr = tid >> 4;
    const int lc = (tid & 15) << 3;

    float acc[4][4][4];
    #pragma unroll
    for (int i = 0; i < 4; i++)
        #pragma unroll
        for (int j = 0; j < 4; j++)
            #pragma unroll
            for (int e = 0; e < 4; e++) acc[i][j][e] = 0.f;

#define XTX_LOAD(buf, kk)                                                       \
    do {                                                                        \
        const float* xp = X + (size_t)(kbase + (kk) + lr) * CCH;                \
        float4 a0 = *reinterpret_cast<const float4*>(xp + m0 + lc);             \
        float4 a1 = *reinterpret_cast<const float4*>(xp + m0 + lc + 4);         \
        As[buf][lr][lc + 0] = f2tf32(a0.x); As[buf][lr][lc + 1] = f2tf32(a0.y); \
        As[buf][lr][lc + 2] = f2tf32(a0.z); As[buf][lr][lc + 3] = f2tf32(a0.w); \
        As[buf][lr][lc + 4] = f2tf32(a1.x); As[buf][lr][lc + 5] = f2tf32(a1.y); \
        As[buf][lr][lc + 6] = f2tf32(a1.z); As[buf][lr][lc + 7] = f2tf32(a1.w); \
        float4 b0 = *reinterpret_cast<const float4*>(xp + n0 + lc);             \
        float4 b1 = *reinterpret_cast<const float4*>(xp + n0 + lc + 4);         \
        Bs[buf][lr][lc + 0] = f2tf32(b0.x); Bs[buf][lr][lc + 1] = f2tf32(b0.y); \
        Bs[buf][lr][lc + 2] = f2tf32(b0.z); Bs[buf][lr][lc + 3] = f2tf32(b0.w); \
        Bs[buf][lr][lc + 4] = f2tf32(b1.x); Bs[buf][lr][lc + 5] = f2tf32(b1.y); \
        Bs[buf][lr][lc + 6] = f2tf32(b1.z); Bs[buf][lr][lc + 7] = f2tf32(b1.w); \
    } while (0)

    XTX_LOAD(0, 0);
    __syncthreads();
    for (int kt = 0; kt < 128; kt++) {
        int cur = kt & 1;
        if (kt + 1 < 128) XTX_LOAD(cur ^ 1, (kt + 1) << 4);
        #pragma unroll
        for (int ks = 0; ks < 2; ks++) {
            int kk = ks << 3;
            uint32_t af[4][4];
            #pragma unroll
            for (int mt = 0; mt < 4; mt++) {
                int mm = wm + (mt << 4);
                af[mt][0] = __float_as_uint(As[cur][kk + tig][mm + g]);
                af[mt][1] = __float_as_uint(As[cur][kk + tig][mm + g + 8]);
                af[mt][2] = __float_as_uint(As[cur][kk + tig + 4][mm + g]);
                af[mt][3] = __float_as_uint(As[cur][kk + tig + 4][mm + g + 8]);
            }
            uint32_t bf[4][2];
            #pragma unroll
            for (int nt = 0; nt < 4; nt++) {
                int nn = wn + (nt << 3);
                bf[nt][0] = __float_as_uint(Bs[cur][kk + tig][nn + g]);
                bf[nt][1] = __float_as_uint(Bs[cur][kk + tig + 4][nn + g]);
            }
            #pragma unroll
            for (int mt = 0; mt < 4; mt++)
                #pragma unroll
                for (int nt = 0; nt < 4; nt++)
                    mma_tf32(acc[mt][nt], af[mt], bf[nt]);
        }
        __syncthreads();
    }

    float* pp = part + (size_t)blockIdx.y * 262144;
    #pragma unroll
    for (int mt = 0; mt < 4; mt++) {
        int row = m0 + wm + (mt << 4) + g;
        #pragma unroll
        for (int nt = 0; nt < 4; nt++) {
            int col = n0 + wn + (nt << 3) + (tig << 1);
            float2 v0, v1;
            v0.x = acc[mt][nt][0]; v0.y = acc[mt][nt][1];
            v1.x = acc[mt][nt][2]; v1.y = acc[mt][nt][3];
            *reinterpret_cast<float2*>(pp + (size_t)row * 512 + col) = v0;
            *reinterpret_cast<float2*>(pp + (size_t)(row + 8) * 512 + col) = v1;
        }
    }
}

__global__ void xtx_reduce_kernel(const float* __restrict__ part,
                                  float* __restrict__ S) {
    int e = blockIdx.x * 1024 + threadIdx.x;
    float s = 0.f;
    #pragma unroll
    for (int c = 0; c < 32; c++) s += part[(size_t)c * 262144 + e];
    S[e] = s;
}

// ----------------------- mask GEMM: K=80, dual B, sigmoid --------------------
__global__ void __launch_bounds__(256) maskgemm_kernel(
    const float* __restrict__ F, const float* __restrict__ W1,
    const float* __restrict__ W2, float* __restrict__ mask) {
    __shared__ __align__(16) float As[2][16][136];
    __shared__ __align__(16) float Bs1[2][16][136];
    __shared__ __align__(16) float Bs2[2][16][136];

    const int tid = threadIdx.x;
    const int bn = blockIdx.x << 7;
    const int bm = blockIdx.y << 7;

    const int lane = tid & 31;
    const int g = lane >> 2;
    const int tig = lane & 3;
    const int w = tid >> 5;
    const int wm = (w >> 2) * 64;
    const int wn = (w & 3) * 32;

    const int ar = tid >> 2;
    const int ac = (tid & 3) << 2;
    const int br = tid >> 5;
    const int bc = (tid & 31) << 2;

    float acc1[4][4][4], acc2[4][4][4];
    #pragma unroll
    for (int i = 0; i < 4; i++)
        #pragma unroll
        for (int j = 0; j < 4; j++)
            #pragma unroll
            for (int e = 0; e < 4; e++) { acc1[i][j][e] = 0.f; acc2[i][j][e] = 0.f; }

#define MG_LOAD(buf, kk)                                                        \
    do {                                                                        \
        _Pragma("unroll")                                                       \
        for (int rr = 0; rr < 2; rr++) {                                        \
            int r = ar + (rr << 6);                                             \
            const float* ap = F + (size_t)(bm + r) * 80 + (kk) + ac;            \
            float4 va = *reinterpret_cast<const float4*>(ap);                   \
            As[buf][ac + 0][r] = f2tf32(va.x);                                  \
            As[buf][ac + 1][r] = f2tf32(va.y);                                  \
            As[buf][ac + 2][r] = f2tf32(va.z);                                  \
            As[buf][ac + 3][r] = f2tf32(va.w);                                  \
        }                                                                       \
        _Pragma("unroll")                                                       \
        for (int rr = 0; rr < 2; rr++) {                                        \
            int r = br + (rr << 3);                                             \
            const float* bp = W1 + (size_t)((kk) + r) * CCH + bn + bc;          \
            float4 vb = *reinterpret_cast<const float4*>(bp);                   \
            float4 vc;                                                          \
            vc.x = f2tf32(vb.x); vc.y = f2tf32(vb.y);                           \
            vc.z = f2tf32(vb.z); vc.w = f2tf32(vb.w);                           \
            *reinterpret_cast<float4*>(&Bs1[buf][r][bc]) = vc;                  \
            const float* bq = W2 + (size_t)((kk) + r) * CCH + bn + bc;          \
            float4 wb = *reinterpret_cast<const float4*>(bq);                   \
            float4 wc;                                                          \
            wc.x = f2tf32(wb.x); wc.y = f2tf32(wb.y);                           \
            wc.z = f2tf32(wb.z); wc.w = f2tf32(wb.w);                           \
            *reinterpret_cast<float4*>(&Bs2[buf][r][bc]) = wc;                  \
        }                                                                       \
    } while (0)

    MG_LOAD(0, 0);
    __syncthreads();
    for (int kt = 0; kt < 5; kt++) {
        int cur = kt & 1;
        if (kt + 1 < 5) MG_LOAD(cur ^ 1, (kt + 1) << 4);
        #pragma unroll
        for (int ks = 0; ks < 2; ks++) {
            int kk = ks << 3;
            uint32_t af[4][4];
            #pragma unroll
            for (int mt = 0; mt < 4; mt++) {
                int m0 = wm + (mt << 4);
                af[mt][0] = __float_as_uint(As[cur][kk + tig][m0 + g]);
                af[mt][1] = __float_as_uint(As[cur][kk + tig][m0 + g + 8]);
                af[mt][2] = __float_as_uint(As[cur][kk + tig + 4][m0 + g]);
                af[mt][3] = __float_as_uint(As[cur][kk + tig + 4][m0 + g + 8]);
            }
            #pragma unroll
            for (int nt = 0; nt < 4; nt++) {
                int n0 = wn + (nt << 3);
                uint32_t bf1[2], bf2[2];
                bf1[0] = __float_as_uint(Bs1[cur][kk + tig][n0 + g]);
                bf1[1] = __float_as_uint(Bs1[cur][kk + tig + 4][n0 + g]);
                bf2[0] = __float_as_uint(Bs2[cur][kk + tig][n0 + g]);
                bf2[1] = __float_as_uint(Bs2[cur][kk + tig + 4][n0 + g]);
                #pragma unroll
                for (int mt = 0; mt < 4; mt++) {
                    mma_tf32(acc1[mt][nt], af[mt], bf1);
                    mma_tf32(acc2[mt][nt], af[mt], bf2);
                }
            }
        }
        __syncthreads();
    }

    #pragma unroll
    for (int mt = 0; mt < 4; mt++) {
        int row = bm + wm + (mt << 4) + g;
        #pragma unroll
        for (int nt = 0; nt < 4; nt++) {
            int col = wn + (nt << 3) + (tig << 1);
            float2 v0, v1;
            v0.x = acc1[mt][nt][0] + 1.f / (1.f + expf(-acc2[mt][nt][0]));
            v0.y = acc1[mt][nt][1] + 1.f / (1.f + expf(-acc2[mt][nt][1]));
            v1.x = acc1[mt][nt][2] + 1.f / (1.f + expf(-acc2[mt][nt][2]));
            v1.y = acc1[mt][nt][3] + 1.f / (1.f + expf(-acc2[mt][nt][3]));
            *reinterpret_cast<float2*>(mask + (size_t)row * CCH + bn + col) = v0;
            *reinterpret_cast<float2*>(mask + (size_t)(row + 8) * CCH + bn + col) = v1;
        }
    }
}

// ---------------- per-head Gram from weights: G = Wk_h^T U_h ----------------
__global__ void __launch_bounds__(256) gramw_kernel(
    const float* __restrict__ Km, const float* __restrict__ Qm,
    float* __restrict__ gram) {
    int h = blockIdx.y;
    __shared__ float ks[64][64];
    __shared__ float qs[64][64];
    int tid = threadIdx.x;
    int lt = tid >> 2;
    int lc = (tid & 3) * 16;
    int i0 = (tid >> 4) * 4;
    int j0 = (tid & 15) * 4;
    float acc[4][4];
    #pragma unroll
    for (int i = 0; i < 4; i++)
        #pragma unroll
        for (int j = 0; j < 4; j++) acc[i][j] = 0.f;

    for (int sub = 0; sub < 8; sub++) {
        int row = sub * 64 + lt;
        const float* kp = Km + (size_t)row * CCH + h * 64 + lc;
        const float* qp = Qm + (size_t)row * CCH + h * 64 + lc;
        #pragma unroll
        for (int u = 0; u < 4; u++) {
            *reinterpret_cast<float4*>(&ks[lt][lc + u * 4]) =
                *reinterpret_cast<const float4*>(kp + u * 4);
            *reinterpret_cast<float4*>(&qs[lt][lc + u * 4]) =
                *reinterpret_cast<const float4*>(qp + u * 4);
        }
        __syncthreads();
        #pragma unroll
        for (int t = 0; t < 64; t++) {
            float4 kv = *reinterpret_cast<const float4*>(&ks[t][i0]);
            float4 qv = *reinterpret_cast<const float4*>(&qs[t][j0]);
            float kr[4] = {kv.x, kv.y, kv.z, kv.w};
            float qr[4] = {qv.x, qv.y, qv.z, qv.w};
            #pragma unroll
            for (int i = 0; i < 4; i++)
                #pragma unroll
                for (int j = 0; j < 4; j++) acc[i][j] += kr[i] * qr[j];
        }
        __syncthreads();
    }
    float* pp = gram + (size_t)h * 4096;
    #pragma unroll
    for (int i = 0; i < 4; i++)
        #pragma unroll
        for (int j = 0; j < 4; j++) pp[(i0 + i) * 64 + j0 + j] = acc[i][j];
}

__global__ void normdot_kernel(const float* __restrict__ Wk,
                               const float* __restrict__ T2,
                               const float* __restrict__ Wq,
                               const float* __restrict__ U,
                               float* __restrict__ norms) {
    int i = threadIdx.x;
    float s = 0.f;
    if (blockIdx.x == 0) {
        for (int c = 0; c < 512; c++) s += Wk[c * 512 + i] * T2[c * 512 + i];
        norms[i] = sqrtf(fmaxf(s, 0.f));
    } else {
        for (int c = 0; c < 512; c++) s += Wq[c * 512 + i] * U[c * 512 + i];
        norms[512 + i] = sqrtf(fmaxf(s, 0.f));
    }
}

// --------------------------- attention + fold into Wp -----------------------
__global__ void attn_kernel(const float* __restrict__ G,
                            const float* __restrict__ norms,
                            const float* __restrict__ rescale,
                            float* __restrict__ attn) {
    int h = blockIdx.x;
    int i = threadIdx.x;
    __shared__ float row[64][64];
    float nk = fmaxf(norms[h * 64 + i], 1e-12f);
    float rs = rescale[h];
    float mx = -1e30f;
    for (int j = 0; j < 64; j++) {
        float nq = fmaxf(norms[512 + h * 64 + j], 1e-12f);
        float vv = G[h * 4096 + i * 64 + j] * rs / (nk * nq);
        row[i][j] = vv;
        mx = fmaxf(mx, vv);
    }
    float s = 0.f;
    for (int j = 0; j < 64; j++) {
        float e = expf(row[i][j] - mx);
        row[i][j] = e;
        s += e;
    }
    float inv = 1.f / s;
    for (int j = 0; j < 64; j++)
        attn[h * 4096 + i * 64 + j] = row[i][j] * inv;
}

__global__ void wpeff_kernel(const float* __restrict__ attn,
                             const float* __restrict__ Wp,
                             float* __restrict__ wpe) {
    int cp = blockIdx.x;
    int h = cp >> 6, j = cp & 63;
    int t = threadIdx.x;
    float a0 = 0.f, a1 = 0.f, a2 = 0.f, a3 = 0.f;
    const float* at = attn + h * 4096 + j;
    for (int i = 0; i < 64; i++) {
        float a = at[i * 64];
        const float* w = Wp + (size_t)((h << 6) + i) * CCH;
        a0 += a * w[t];
        a1 += a * w[t + 128];
        a2 += a * w[t + 256];
        a3 += a * w[t + 384];
    }
    float* o = wpe + (size_t)cp * CCH;
    o[t] = a0; o[t + 128] = a1; o[t + 256] = a2; o[t + 384] = a3;
}

// --------------------- fused positional branch (dw-gelu-dw) ------------------
// tile: 16x16 pixels, 16 channels; halo 2 on v, 1 on mid.
// mid outside the 256x256 image is EXACTLY 0 (reference zero-pads conv1 output
// before conv2) — enforced by the inimg predicate below.
__global__ void __launch_bounds__(256) pe_fused_kernel(
    const float* __restrict__ V, const float* __restrict__ w1,
    const float* __restrict__ w2, float* __restrict__ out) {
    __shared__ float vt[20][20][16];
    __shared__ float mid[18][18][16];
    __shared__ float w1s[16][9], w2s[16][9];

    int x0 = blockIdx.x << 4, y0 = blockIdx.y << 4, c0 = blockIdx.z << 4;
    int tid = threadIdx.x;

    if (tid < 144) {
        int cc = tid / 9, kk = tid % 9;
        w1s[cc][kk] = w1[(c0 + cc) * 9 + kk];
        w2s[cc][kk] = w2[(c0 + cc) * 9 + kk];
    }
    for (int e = tid; e < 6400; e += 256) {
        int cc = e & 15;
        int rest = e >> 4;
        int px = rest % 20, py = rest / 20;
        int xx = x0 + px - 2, yy = y0 + py - 2;
        float v = 0.f;
        if (xx >= 0 && xx < WW && yy >= 0 && yy < HH)
            v = V[((size_t)(yy << 8) + xx) * CCH + c0 + cc];
        vt[py][px][cc] = v;
    }
    __syncthreads();
    for (int e = tid; e < 5184; e += 256) {
        int cc = e & 15;
        int rest = e >> 4;
        int mx = rest % 18, my = rest / 18;
        int gx = x0 + mx - 1, gy = y0 + my - 1;         // mid pixel coords
        bool inimg = (gx >= 0 && gx < WW && gy >= 0 && gy < HH);
        float r = 0.f;
        if (inimg) {
            float acc = 0.f;
            #pragma unroll
            for (int ky = 0; ky < 3; ky++)
                #pragma unroll
                for (int kx = 0; kx < 3; kx++)
                    acc += w1s[cc][ky * 3 + kx] * vt[my + ky][mx + kx][cc];
            r = 0.5f * acc * (1.f + erff(acc * 0.70710678118654752f));
        }
        mid[my][mx][cc] = r;
    }
    __syncthreads();
    for (int e = tid; e < 4096; e += 256) {
        int cc = e & 15;
        int ox = (e >> 4) & 15;
        int oy = e >> 8;
        float acc = 0.f;
        #pragma unroll
        for (int ky = 0; ky < 3; ky++)
            #pragma unroll
            for (int kx = 0; kx < 3; kx++)
                acc += w2s[cc][ky * 3 + kx] * mid[oy + ky][ox + kx][cc];
        size_t oi = ((size_t)((y0 + oy) << 8) + x0 + ox) * CCH + c0 + cc;
        out[oi] += acc;
    }
}

// --------------------------------- launch -----------------------------------
extern "C" void kernel_launch(void* const* d_in, const int* in_sizes, int n_in,
                              void* d_out, int out_size) {
    const float* x       = (const float*)d_in[0];
    const float* sar     = (const float*)d_in[1];
    const float* Wq      = (const float*)d_in[2];
    const float* Wk      = (const float*)d_in[3];
    const float* Wv      = (const float*)d_in[4];
    const float* rescale = (const float*)d_in[5];
    const float* Wp      = (const float*)d_in[6];
    const float* bp      = (const float*)d_in[7];
    const float* pe1w    = (const float*)d_in[8];
    const float* pe2w    = (const float*)d_in[9];
    const float* conv3w  = (const float*)d_in[10];
    const float* conv3b  = (const float*)d_in[11];
    const float* bng     = (const float*)d_in[12];
    const float* bnb     = (const float*)d_in[13];
    const float* sobelb  = (const float*)d_in[14];
    const float* conv2w  = (const float*)d_in[15];
    const float* conv2b  = (const float*)d_in[16];
    const float* conv32w = (const float*)d_in[17];
    const float* conv32b = (const float*)d_in[18];
    const float* dconvw  = (const float*)d_in[19];
    const float* dconvb  = (const float*)d_in[20];
    float* out = (float*)d_out;

    float *v, *mask, *F, *W1, *W2, *a, *ss, *bnp, *gpart, *S, *U, *T2;
    float *gram, *norms, *attn, *wpeff;
    cudaGetSymbolAddress((void**)&v, g_v);
    cudaGetSymbolAddress((void**)&mask, g_mask);
    cudaGetSymbolAddress((void**)&F, g_F);
    cudaGetSymbolAddress((void**)&W1, g_W1);
    cudaGetSymbolAddress((void**)&W2, g_W2);
    cudaGetSymbolAddress((void**)&a, g_a);
    cudaGetSymbolAddress((void**)&ss, g_ss);
    cudaGetSymbolAddress((void**)&bnp, g_bnp);
    cudaGetSymbolAddress((void**)&gpart, g_gpart);
    cudaGetSymbolAddress((void**)&S, g_S);
    cudaGetSymbolAddress((void**)&U, g_U);
    cudaGetSymbolAddress((void**)&T2, g_T2);
    cudaGetSymbolAddress((void**)&gram, g_gram);
    cudaGetSymbolAddress((void**)&norms, g_norms);
    cudaGetSymbolAddress((void**)&attn, g_attn);
    cudaGetSymbolAddress((void**)&wpeff, g_wpeff);

    // SAR path -> mask features -> mask (tensor-core GEMM + sigmoid epilogue)
    conv3_kernel<<<256, 256>>>(sar, conv3w, conv3b, a);
    bnstats_kernel<<<2, 512>>>(a, bng, bnb, bnp);
    sobel_ss_kernel<<<256, 256>>>(a, bnp, sobelb, ss);
    fbuild_kernel<<<1024, 256>>>(ss, F);
    wbuild_kernel<<<1, 512>>>(conv2w, conv2b, conv32w, conv32b,
                              dconvw, dconvb, W1, W2);
    maskgemm_kernel<<<dim3(4, 512), 256>>>(F, W1, W2, mask);

    // V projection (only projection that must be materialized)
    tgemm128<0, 0><<<dim3(4, 512), 256>>>(x, nullptr, Wv, Wv, Wv, nullptr,
                                          v, v, v, NTOK, CCH);

    // S = X^T X (split-K) ; U = S@Wq ; T2 = S@Wk
    xtx_kernel<<<dim3(16, 32), 256>>>(x, gpart);
    xtx_reduce_kernel<<<256, 1024>>>(gpart, S);
    tgemm128<0, 0><<<dim3(8, 4), 256>>>(S, nullptr, Wq, Wk, Wk, nullptr,
                                        U, T2, T2, 512, CCH);

    // per-head Gram + norms from weight-space quantities
    gramw_kernel<<<dim3(1, 8), 256>>>(Wk, U, gram);
    normdot_kernel<<<2, 512>>>(Wk, T2, Wq, U, norms);

    // attention weights folded into Wp
    attn_kernel<<<8, 64>>>(gram, norms, rescale, attn);
    wpeff_kernel<<<512, 128>>>(attn, Wp, wpeff);

    // out_c = (v * mask) @ Wp_eff + bp -> d_out
    tgemm128<1, 1><<<dim3(4, 512), 256>>>(v, mask, wpeff, wpeff, wpeff, bp,
                                          out, out, out, NTOK, CCH);

    // fused positional branch added into out
    pe_fused_kernel<<<dim3(16, 16, 32), 256>>>(v, pe1w, pe2w, out);
}

// round 5
// speedup vs baseline: 2.8479x; 1.0518x over previous
#include <cuda_runtime.h>
#include <cuda_bf16.h>
#include <math.h>
#include <stdint.h>

// ---------------------------------------------------------------------------
// MS_MSA — round 5: cp.async 3-stage pipelined TF32 GEMMs, symmetric XtX,
// v*mask fused into maskgemm epilogue.
// Shapes fixed: b=1, H=W=256 (NTOK=65536), C=512, HEADS=8, D=64, CS=2
// ---------------------------------------------------------------------------

#define NTOK 65536
#define CCH  512
#define HH   256
#define WW   256

// ------------------------- scratch (device globals) ------------------------
__device__ float g_v[33554432];      // v_inp [n, c]
__device__ float g_mask[33554432];   // vm = v * mask [n, c]
__device__ float g_F[5242880];       // mask features [n, 80]
__device__ float g_W1[40960];        // [80, 512]
__device__ float g_W2[40960];        // [80, 512]
__device__ float g_a[131072];        // conv3 output [2, H, W]
__device__ float g_ss[131072];       // sar_sobel [2, H, W]
__device__ float g_bnp[4];
__device__ float g_gpart[8388608];   // XtX partials [32][512*512]
__device__ float g_S[262144];        // S = X^T X
__device__ float g_U[262144];        // U  = S @ Wq
__device__ float g_T2[262144];       // T2 = S @ Wk
__device__ float g_gram[32768];
__device__ float g_norms[1024];
__device__ float g_attn[32768];
__device__ float g_wpeff[262144];

// ------------------------------ SAR path -----------------------------------

__global__ void conv3_kernel(const float* __restrict__ sar,
                             const float* __restrict__ w,
                             const float* __restrict__ b,
                             float* __restrict__ a) {
    int n = blockIdx.x * 256 + threadIdx.x;
    if (n >= NTOK) return;
    int y = n >> 8, x = n & 255;
    #pragma unroll
    for (int co = 0; co < 2; co++) {
        float acc = b[co];
        #pragma unroll
        for (int ci = 0; ci < 2; ci++) {
            #pragma unroll
            for (int ky = 0; ky < 3; ky++) {
                int yy = y + ky - 1;
                if (yy < 0 || yy >= HH) continue;
                #pragma unroll
                for (int kx = 0; kx < 3; kx++) {
                    int xx = x + kx - 1;
                    if (xx < 0 || xx >= WW) continue;
                    acc += w[((co * 2 + ci) * 3 + ky) * 3 + kx] *
                           sar[ci * NTOK + (yy << 8) + xx];
                }
            }
        }
        a[co * NTOK + n] = acc;
    }
}

__global__ void bnstats_kernel(const float* __restrict__ a,
                               const float* __restrict__ gg,
                               const float* __restrict__ bb,
                               float* __restrict__ bnp) {
    int c = blockIdx.x;
    __shared__ float sh[512], sh2[512];
    float s = 0.f, s2 = 0.f;
    for (int i = threadIdx.x; i < NTOK; i += 512) {
        float v = a[c * NTOK + i];
        s += v; s2 += v * v;
    }
    sh[threadIdx.x] = s; sh2[threadIdx.x] = s2;
    __syncthreads();
    for (int st = 256; st > 0; st >>= 1) {
        if (threadIdx.x < st) {
            sh[threadIdx.x] += sh[threadIdx.x + st];
            sh2[threadIdx.x] += sh2[threadIdx.x + st];
        }
        __syncthreads();
    }
    if (threadIdx.x == 0) {
        float mean = sh[0] * (1.f / NTOK);
        float var = sh2[0] * (1.f / NTOK) - mean * mean;
        float sc = gg[c] * rsqrtf(var + 1e-5f);
        bnp[c * 2] = sc;
        bnp[c * 2 + 1] = bb[c] - mean * sc;
    }
}

__global__ void sobel_ss_kernel(const float* __restrict__ a,
                                const float* __restrict__ bnp,
                                const float* __restrict__ sb,
                                float* __restrict__ ss) {
    int n = blockIdx.x * 256 + threadIdx.x;
    if (n >= NTOK) return;
    int y = n >> 8, x = n & 255;
    float sc0 = bnp[0], sh0 = bnp[1], sc1 = bnp[2], sh1 = bnp[3];
    float t[3][3];
    #pragma unroll
    for (int ky = 0; ky < 3; ky++) {
        int yy = y + ky - 1;
        #pragma unroll
        for (int kx = 0; kx < 3; kx++) {
            int xx = x + kx - 1;
            if (yy >= 0 && yy < HH && xx >= 0 && xx < WW) {
                int idx = (yy << 8) + xx;
                t[ky][kx] = a[idx] * sc0 + sh0 + a[NTOK + idx] * sc1 + sh1;
            } else t[ky][kx] = 0.f;
        }
    }
    float gy = -(t[0][0] + 2.f * t[0][1] + t[0][2]) + (t[2][0] + 2.f * t[2][1] + t[2][2]);
    float gx = -(t[0][0] + 2.f * t[1][0] + t[2][0]) + (t[0][2] + 2.f * t[1][2] + t[2][2]);
    float s0 = gy + sb[0], s1 = gx + sb[1], s2 = gy + sb[2], s3 = gx + sb[3];
    float bc0 = a[n] * sc0 + sh0;
    float bc1 = a[NTOK + n] * sc1 + sh1;
    ss[n]        = sqrtf(s0 * s0 + s1 * s1) + bc0;
    ss[NTOK + n] = sqrtf(s2 * s2 + s3 * s3) + bc1;
}

__global__ void __launch_bounds__(256) fbuild_kernel(
    const float* __restrict__ ss, float* __restrict__ F) {
    __shared__ float Fs[64 * 80];
    int p0 = blockIdx.x * 64;
    int tid = threadIdx.x;
    int pix = tid >> 2;
    int t4 = tid & 3;
    int n = p0 + pix;
    int y = n >> 8, x = n & 255;
    for (int t = t4; t < 25; t += 4) {
        int dy = t / 5, dx = t % 5;
        int yy = y + dy - 2, xx = x + dx - 2;
        bool ok = (yy >= 0 && yy < HH && xx >= 0 && xx < WW);
        float s0 = 0.f, s1 = 0.f;
        if (ok) {
            int idx = (yy << 8) + xx;
            s0 = ss[idx];
            s1 = ss[NTOK + idx];
        }
        Fs[pix * 80 + t] = s0;
        Fs[pix * 80 + 25 + t] = s1;
        Fs[pix * 80 + 50 + t] = ok ? 1.f : 0.f;
    }
    if (t4 == 0) {
        Fs[pix * 80 + 75] = 0.f;
        Fs[pix * 80 + 76] = 0.f;
        Fs[pix * 80 + 77] = 0.f;
        Fs[pix * 80 + 78] = 1.f;
        Fs[pix * 80 + 79] = 0.f;
    }
    __syncthreads();
    float* dst = F + (size_t)p0 * 80;
    for (int e = tid; e < 64 * 80; e += 256) dst[e] = Fs[e];
}

__global__ void wbuild_kernel(const float* __restrict__ w2c, const float* __restrict__ b2,
                              const float* __restrict__ w32, const float* __restrict__ b32,
                              const float* __restrict__ dw, const float* __restrict__ db,
                              float* __restrict__ W1, float* __restrict__ W2) {
    int c = threadIdx.x;
    float w20 = w2c[c * 2], w21 = w2c[c * 2 + 1], bb2 = b2[c], bbd = db[c];
    for (int t = 0; t < 25; t++) {
        float d = dw[c * 25 + t];
        float a0 = d * w20, a1 = d * w21, a2 = d * bb2;
        if (t == 12) { a0 += w20; a1 += w21; a2 += bb2; }
        W1[t * 512 + c] = a0;
        W1[(25 + t) * 512 + c] = a1;
        W1[(50 + t) * 512 + c] = a2;
        float e0 = 0.f, e1 = 0.f;
        int dy = t / 5, dx = t % 5;
        if (dy >= 1 && dy <= 3 && dx >= 1 && dx <= 3) {
            int kk = (dy - 1) * 3 + (dx - 1);
            e0 = w32[c * 18 + kk];
            e1 = w32[c * 18 + 9 + kk];
        }
        W2[t * 512 + c] = e0;
        W2[(25 + t) * 512 + c] = e1;
        W2[(50 + t) * 512 + c] = 0.f;
    }
    for (int kk = 75; kk < 80; kk++) {
        W1[kk * 512 + c] = (kk == 78) ? bbd : 0.f;
        W2[kk * 512 + c] = (kk == 78) ? b32[c] : 0.f;
    }
}

// -------------------------- TF32 MMA helpers --------------------------------
__device__ __forceinline__ float f2tf32(float x) {
    float r;
    asm("cvt.rna.tf32.f32 %0, %1;" : "=f"(r) : "f"(x));
    return r;
}

__device__ __forceinline__ uint32_t ld_tf32(const float* p) {
    return __float_as_uint(f2tf32(*p));
}

__device__ __forceinline__ void mma_tf32(float* c, const uint32_t* a,
                                         const uint32_t* b) {
    asm volatile(
        "mma.sync.aligned.m16n8k8.row.col.f32.tf32.tf32.f32 "
        "{%0,%1,%2,%3}, {%4,%5,%6,%7}, {%8,%9}, {%0,%1,%2,%3};"
        : "+f"(c[0]), "+f"(c[1]), "+f"(c[2]), "+f"(c[3])
        : "r"(a[0]), "r"(a[1]), "r"(a[2]), "r"(a[3]), "r"(b[0]), "r"(b[1]));
}

__device__ __forceinline__ uint32_t smaddr(const void* p) {
    return (uint32_t)__cvta_generic_to_shared(p);
}

__device__ __forceinline__ void cpasync16(uint32_t s, const void* g) {
    asm volatile("cp.async.cg.shared.global [%0], [%1], 16;" :: "r"(s), "l"(g));
}

__device__ __forceinline__ void cp_commit() {
    asm volatile("cp.async.commit_group;");
}

// ------------------ pipelined TF32 GEMM: C[M,512]=A[M,K]@B ------------------
// 128x128 tile, 256 thr, 3-stage cp.async pipeline, A smem [m][k] pad 20,
// B smem [k][n] pad 136. K multiple of 16. Up to 3 (B,C) pairs via blockIdx.x.
#define ASF 2560    // 128*20 floats
#define BSF 2176    // 16*136 floats
#define STGF (ASF + BSF)

template <int BIAS>
__global__ void __launch_bounds__(256) tgemm_pipe(
    const float* __restrict__ A,
    const float* __restrict__ B0, const float* __restrict__ B1,
    const float* __restrict__ B2, const float* __restrict__ bias,
    float* __restrict__ C0, float* __restrict__ C1, float* __restrict__ C2,
    int M, int K) {
    extern __shared__ float sm[];

    const int tid = threadIdx.x;
    const int which = blockIdx.x >> 2;
    const float* B = (which == 0) ? B0 : (which == 1) ? B1 : B2;
    float* C = (which == 0) ? C0 : (which == 1) ? C1 : C2;
    const int bn = (blockIdx.x & 3) << 7;
    const int bm = blockIdx.y << 7;

    const int lane = tid & 31;
    const int g = lane >> 2;
    const int tig = lane & 3;
    const int w = tid >> 5;
    const int wm = (w >> 2) * 64;
    const int wn = (w & 3) * 32;

    // cp.async source/dest indices
    const int arow = tid >> 1, acol = (tid & 1) << 3;        // A: 128x16
    const int brow = tid >> 4, bcol = (tid & 15) << 3;       // B: 16x128

    float acc[4][4][4];
    #pragma unroll
    for (int i = 0; i < 4; i++)
        #pragma unroll
        for (int j = 0; j < 4; j++)
            #pragma unroll
            for (int e = 0; e < 4; e++) acc[i][j][e] = 0.f;

    const int NK = K >> 4;

#define PIPE_ISSUE(stg, kk)                                                     \
    do {                                                                        \
        float* As_ = sm + (stg) * STGF;                                         \
        float* Bs_ = As_ + ASF;                                                 \
        const float* ga = A + (size_t)(bm + arow) * K + (kk) + acol;            \
        uint32_t sa = smaddr(As_ + arow * 20 + acol);                           \
        cpasync16(sa, ga);                                                      \
        cpasync16(sa + 16, ga + 4);                                             \
        const float* gb = B + (size_t)((kk) + brow) * CCH + bn + bcol;          \
        uint32_t sb = smaddr(Bs_ + brow * 136 + bcol);                          \
        cpasync16(sb, gb);                                                      \
        cpasync16(sb + 16, gb + 4);                                             \
        cp_commit();                                                            \
    } while (0)

    PIPE_ISSUE(0, 0);
    PIPE_ISSUE(1, 16);

    int stg = 0;
    for (int kt = 0; kt < NK; kt++) {
        if (kt + 1 < NK) asm volatile("cp.async.wait_group 1;");
        else             asm volatile("cp.async.wait_group 0;");
        __syncthreads();
        if (kt + 2 < NK) {
            int ns = stg + 2; if (ns >= 3) ns -= 3;
            PIPE_ISSUE(ns, (kt + 2) << 4);
        }
        const float* As_ = sm + stg * STGF;
        const float* Bs_ = As_ + ASF;
        #pragma unroll
        for (int ks = 0; ks < 2; ks++) {
            int kk = ks << 3;
            uint32_t af[4][4];
            #pragma unroll
            for (int mt = 0; mt < 4; mt++) {
                int m0 = wm + (mt << 4) + g;
                af[mt][0] = ld_tf32(As_ + m0 * 20 + kk + tig);
                af[mt][1] = ld_tf32(As_ + (m0 + 8) * 20 + kk + tig);
                af[mt][2] = ld_tf32(As_ + m0 * 20 + kk + tig + 4);
                af[mt][3] = ld_tf32(As_ + (m0 + 8) * 20 + kk + tig + 4);
            }
            uint32_t bf[4][2];
            #pragma unroll
            for (int nt = 0; nt < 4; nt++) {
                int n0 = wn + (nt << 3) + g;
                bf[nt][0] = ld_tf32(Bs_ + (kk + tig) * 136 + n0);
                bf[nt][1] = ld_tf32(Bs_ + (kk + tig + 4) * 136 + n0);
            }
            #pragma unroll
            for (int mt = 0; mt < 4; mt++)
                #pragma unroll
                for (int nt = 0; nt < 4; nt++)
                    mma_tf32(acc[mt][nt], af[mt], bf[nt]);
        }
        stg++; if (stg >= 3) stg = 0;
    }

    #pragma unroll
    for (int mt = 0; mt < 4; mt++) {
        int row = bm + wm + (mt << 4) + g;
        #pragma unroll
        for (int nt = 0; nt < 4; nt++) {
            int col = wn + (nt << 3) + (tig << 1);
            float b0 = 0.f, b1 = 0.f;
            if (BIAS) {
                b0 = bias[bn + col];
                b1 = bias[bn + col + 1];
            }
            float2 v0, v1;
            v0.x = acc[mt][nt][0] + b0; v0.y = acc[mt][nt][1] + b1;
            v1.x = acc[mt][nt][2] + b0; v1.y = acc[mt][nt][3] + b1;
            *reinterpret_cast<float2*>(C + (size_t)row * CCH + bn + col) = v0;
            *reinterpret_cast<float2*>(C + (size_t)(row + 8) * CCH + bn + col) = v1;
        }
    }
}

// -------------- pipelined symmetric XtX: upper-tri 128x128 tiles -------------
// smem: both tiles [k][m]/[k][n] pad 136, 3 stages.
#define XSTGF (2 * BSF)

__global__ void __launch_bounds__(256) xtx_pipe(
    const float* __restrict__ X, float* __restrict__ part) {
    extern __shared__ float sm[];
    const int tid = threadIdx.x;
    // tile id -> (row tile i, col tile j), i <= j
    const int til[10] = {0, 0, 0, 0, 1, 1, 1, 2, 2, 3};
    const int tjl[10] = {0, 1, 2, 3, 1, 2, 3, 2, 3, 3};
    const int m0 = til[blockIdx.x] << 7;
    const int n0 = tjl[blockIdx.x] << 7;
    const int kbase = blockIdx.y * 2048;

    const int lane = tid & 31;
    const int g = lane >> 2;
    const int tig = lane & 3;
    const int w = tid >> 5;
    const int wm = (w >> 2) * 64;
    const int wn = (w & 3) * 32;

    const int lrow = tid >> 4, lcol = (tid & 15) << 3;  // 16 rows x 128 cols

    float acc[4][4][4];
    #pragma unroll
    for (int i = 0; i < 4; i++)
        #pragma unroll
        for (int j = 0; j < 4; j++)
            #pragma unroll
            for (int e = 0; e < 4; e++) acc[i][j][e] = 0.f;

#define XPIPE_ISSUE(stg, kk)                                                    \
    do {                                                                        \
        float* As_ = sm + (stg) * XSTGF;                                        \
        float* Bs_ = As_ + BSF;                                                 \
        const float* xr = X + (size_t)(kbase + (kk) + lrow) * CCH;              \
        uint32_t sa = smaddr(As_ + lrow * 136 + lcol);                          \
        cpasync16(sa, xr + m0 + lcol);                                          \
        cpasync16(sa + 16, xr + m0 + lcol + 4);                                 \
        uint32_t sb = smaddr(Bs_ + lrow * 136 + lcol);                          \
        cpasync16(sb, xr + n0 + lcol);                                          \
        cpasync16(sb + 16, xr + n0 + lcol + 4);                                 \
        cp_commit();                                                            \
    } while (0)

    XPIPE_ISSUE(0, 0);
    XPIPE_ISSUE(1, 16);

    int stg = 0;
    for (int kt = 0; kt < 128; kt++) {
        if (kt + 1 < 128) asm volatile("cp.async.wait_group 1;");
        else              asm volatile("cp.async.wait_group 0;");
        __syncthreads();
        if (kt + 2 < 128) {
            int ns = stg + 2; if (ns >= 3) ns -= 3;
            XPIPE_ISSUE(ns, (kt + 2) << 4);
        }
        const float* As_ = sm + stg * XSTGF;
        const float* Bs_ = As_ + BSF;
        #pragma unroll
        for (int ks = 0; ks < 2; ks++) {
            int kk = ks << 3;
            uint32_t af[4][4];
            #pragma unroll
            for (int mt = 0; mt < 4; mt++) {
                int mm = wm + (mt << 4) + g;
                af[mt][0] = ld_tf32(As_ + (kk + tig) * 136 + mm);
                af[mt][1] = ld_tf32(As_ + (kk + tig) * 136 + mm + 8);
                af[mt][2] = ld_tf32(As_ + (kk + tig + 4) * 136 + mm);
                af[mt][3] = ld_tf32(As_ + (kk + tig + 4) * 136 + mm + 8);
            }
            uint32_t bf[4][2];
            #pragma unroll
            for (int nt = 0; nt < 4; nt++) {
                int nn = wn + (nt << 3) + g;
                bf[nt][0] = ld_tf32(Bs_ + (kk + tig) * 136 + nn);
                bf[nt][1] = ld_tf32(Bs_ + (kk + tig + 4) * 136 + nn);
            }
            #pragma unroll
            for (int mt = 0; mt < 4; mt++)
                #pragma unroll
                for (int nt = 0; nt < 4; nt++)
                    mma_tf32(acc[mt][nt], af[mt], bf[nt]);
        }
        stg++; if (stg >= 3) stg = 0;
    }

    float* pp = part + (size_t)blockIdx.y * 262144;
    #pragma unroll
    for (int mt = 0; mt < 4; mt++) {
        int row = m0 + wm + (mt << 4) + g;
        #pragma unroll
        for (int nt = 0; nt < 4; nt++) {
            int col = n0 + wn + (nt << 3) + (tig << 1);
            float2 v0, v1;
            v0.x = acc[mt][nt][0]; v0.y = acc[mt][nt][1];
            v1.x = acc[mt][nt][2]; v1.y = acc[mt][nt][3];
            *reinterpret_cast<float2*>(pp + (size_t)row * 512 + col) = v0;
            *reinterpret_cast<float2*>(pp + (size_t)(row + 8) * 512 + col) = v1;
        }
    }
}

// symmetric reduce: lower-tri tiles read mirrored partials
__global__ void xtx_reduce_sym(const float* __restrict__ part,
                               float* __restrict__ S) {
    int e = blockIdx.x * 1024 + threadIdx.x;
    int r = e >> 9, c = e & 511;
    int idx = ((r >> 7) <= (c >> 7)) ? e : ((c << 9) + r);
    float s = 0.f;
    #pragma unroll
    for (int ch = 0; ch < 32; ch++) s += part[(size_t)ch * 262144 + idx];
    S[e] = s;
}

// ----------------------- mask GEMM: K=80, dual B, sigmoid --------------------
// writes vm = (F@W1 + sigmoid(F@W2)) * v    (gating fused into epilogue)
__global__ void __launch_bounds__(256) maskgemm_kernel(
    const float* __restrict__ F, const float* __restrict__ W1,
    const float* __restrict__ W2, const float* __restrict__ V,
    float* __restrict__ vm) {
    __shared__ __align__(16) float As[2][16][136];
    __shared__ __align__(16) float Bs1[2][16][136];
    __shared__ __align__(16) float Bs2[2][16][136];

    const int tid = threadIdx.x;
    const int bn = blockIdx.x << 7;
    const int bm = blockIdx.y << 7;

    const int lane = tid & 31;
    const int g = lane >> 2;
    const int tig = lane & 3;
    const int w = tid >> 5;
    const int wm = (w >> 2) * 64;
    const int wn = (w & 3) * 32;

    const int ar = tid >> 2;
    const int ac = (tid & 3) << 2;
    const int br = tid >> 5;
    const int bc = (tid & 31) << 2;

    float acc1[4][4][4], acc2[4][4][4];
    #pragma unroll
    for (int i = 0; i < 4; i++)
        #pragma unroll
        for (int j = 0; j < 4; j++)
            #pragma unroll
            for (int e = 0; e < 4; e++) { acc1[i][j][e] = 0.f; acc2[i][j][e] = 0.f; }

#define MG_LOAD(buf, kk)                                                        \
    do {                                                                        \
        _Pragma("unroll")                                                       \
        for (int rr = 0; rr < 2; rr++) {                                        \
            int r = ar + (rr << 6);                                             \
            const float* ap = F + (size_t)(bm + r) * 80 + (kk) + ac;            \
            float4 va = *reinterpret_cast<const float4*>(ap);                   \
            As[buf][ac + 0][r] = f2tf32(va.x);                                  \
            As[buf][ac + 1][r] = f2tf32(va.y);                                  \
            As[buf][ac + 2][r] = f2tf32(va.z);                                  \
            As[buf][ac + 3][r] = f2tf32(va.w);                                  \
        }                                                                       \
        _Pragma("unroll")                                                       \
        for (int rr = 0; rr < 2; rr++) {                                        \
            int r = br + (rr << 3);                                             \
            const float* bp = W1 + (size_t)((kk) + r) * CCH + bn + bc;          \
            float4 vb = *reinterpret_cast<const float4*>(bp);                   \
            float4 vc;                                                          \
            vc.x = f2tf32(vb.x); vc.y = f2tf32(vb.y);                           \
            vc.z = f2tf32(vb.z); vc.w = f2tf32(vb.w);                           \
            *reinterpret_cast<float4*>(&Bs1[buf][r][bc]) = vc;                  \
            const float* bq = W2 + (size_t)((kk) + r) * CCH + bn + bc;          \
            float4 wb = *reinterpret_cast<const float4*>(bq);                   \
            float4 wc;                                                          \
            wc.x = f2tf32(wb.x); wc.y = f2tf32(wb.y);                           \
            wc.z = f2tf32(wb.z); wc.w = f2tf32(wb.w);                           \
            *reinterpret_cast<float4*>(&Bs2[buf][r][bc]) = wc;                  \
        }                                                                       \
    } while (0)

    MG_LOAD(0, 0);
    __syncthreads();
    for (int kt = 0; kt < 5; kt++) {
        int cur = kt & 1;
        if (kt + 1 < 5) MG_LOAD(cur ^ 1, (kt + 1) << 4);
        #pragma unroll
        for (int ks = 0; ks < 2; ks++) {
            int kk = ks << 3;
            uint32_t af[4][4];
            #pragma unroll
            for (int mt = 0; mt < 4; mt++) {
                int m0 = wm + (mt << 4);
                af[mt][0] = __float_as_uint(As[cur][kk + tig][m0 + g]);
                af[mt][1] = __float_as_uint(As[cur][kk + tig][m0 + g + 8]);
                af[mt][2] = __float_as_uint(As[cur][kk + tig + 4][m0 + g]);
                af[mt][3] = __float_as_uint(As[cur][kk + tig + 4][m0 + g + 8]);
            }
            #pragma unroll
            for (int nt = 0; nt < 4; nt++) {
                int n0 = wn + (nt << 3);
                uint32_t bf1[2], bf2[2];
                bf1[0] = __float_as_uint(Bs1[cur][kk + tig][n0 + g]);
                bf1[1] = __float_as_uint(Bs1[cur][kk + tig + 4][n0 + g]);
                bf2[0] = __float_as_uint(Bs2[cur][kk + tig][n0 + g]);
                bf2[1] = __float_as_uint(Bs2[cur][kk + tig + 4][n0 + g]);
                #pragma unroll
                for (int mt = 0; mt < 4; mt++) {
                    mma_tf32(acc1[mt][nt], af[mt], bf1);
                    mma_tf32(acc2[mt][nt], af[mt], bf2);
                }
            }
        }
        __syncthreads();
    }

    #pragma unroll
    for (int mt = 0; mt < 4; mt++) {
        int row = bm + wm + (mt << 4) + g;
        #pragma unroll
        for (int nt = 0; nt < 4; nt++) {
            int col = wn + (nt << 3) + (tig << 1);
            float2 va = *reinterpret_cast<const float2*>(
                V + (size_t)row * CCH + bn + col);
            float2 vb = *reinterpret_cast<const float2*>(
                V + (size_t)(row + 8) * CCH + bn + col);
            float2 v0, v1;
            v0.x = (acc1[mt][nt][0] + 1.f / (1.f + expf(-acc2[mt][nt][0]))) * va.x;
            v0.y = (acc1[mt][nt][1] + 1.f / (1.f + expf(-acc2[mt][nt][1]))) * va.y;
            v1.x = (acc1[mt][nt][2] + 1.f / (1.f + expf(-acc2[mt][nt][2]))) * vb.x;
            v1.y = (acc1[mt][nt][3] + 1.f / (1.f + expf(-acc2[mt][nt][3]))) * vb.y;
            *reinterpret_cast<float2*>(vm + (size_t)row * CCH + bn + col) = v0;
            *reinterpret_cast<float2*>(vm + (size_t)(row + 8) * CCH + bn + col) = v1;
        }
    }
}

// ---------------- per-head Gram from weights: G = Wk_h^T U_h ----------------
__global__ void __launch_bounds__(256) gramw_kernel(
    const float* __restrict__ Km, const float* __restrict__ Qm,
    float* __restrict__ gram) {
    int h = blockIdx.y;
    __shared__ float ks[64][64];
    __shared__ float qs[64][64];
    int tid = threadIdx.x;
    int lt = tid >> 2;
    int lc = (tid & 3) * 16;
    int i0 = (tid >> 4) * 4;
    int j0 = (tid & 15) * 4;
    float acc[4][4];
    #pragma unroll
    for (int i = 0; i < 4; i++)
        #pragma unroll
        for (int j = 0; j < 4; j++) acc[i][j] = 0.f;

    for (int sub = 0; sub < 8; sub++) {
        int row = sub * 64 + lt;
        const float* kp = Km + (size_t)row * CCH + h * 64 + lc;
        const float* qp = Qm + (size_t)row * CCH + h * 64 + lc;
        #pragma unroll
        for (int u = 0; u < 4; u++) {
            *reinterpret_cast<float4*>(&ks[lt][lc + u * 4]) =
                *reinterpret_cast<const float4*>(kp + u * 4);
            *reinterpret_cast<float4*>(&qs[lt][lc + u * 4]) =
                *reinterpret_cast<const float4*>(qp + u * 4);
        }
        __syncthreads();
        #pragma unroll
        for (int t = 0; t < 64; t++) {
            float4 kv = *reinterpret_cast<const float4*>(&ks[t][i0]);
            float4 qv = *reinterpret_cast<const float4*>(&qs[t][j0]);
            float kr[4] = {kv.x, kv.y, kv.z, kv.w};
            float qr[4] = {qv.x, qv.y, qv.z, qv.w};
            #pragma unroll
            for (int i = 0; i < 4; i++)
                #pragma unroll
                for (int j = 0; j < 4; j++) acc[i][j] += kr[i] * qr[j];
        }
        __syncthreads();
    }
    float* pp = gram + (size_t)h * 4096;
    #pragma unroll
    for (int i = 0; i < 4; i++)
        #pragma unroll
        for (int j = 0; j < 4; j++) pp[(i0 + i) * 64 + j0 + j] = acc[i][j];
}

__global__ void normdot_kernel(const float* __restrict__ Wk,
                               const float* __restrict__ T2,
                               const float* __restrict__ Wq,
                               const float* __restrict__ U,
                               float* __restrict__ norms) {
    int i = threadIdx.x;
    float s = 0.f;
    if (blockIdx.x == 0) {
        for (int c = 0; c < 512; c++) s += Wk[c * 512 + i] * T2[c * 512 + i];
        norms[i] = sqrtf(fmaxf(s, 0.f));
    } else {
        for (int c = 0; c < 512; c++) s += Wq[c * 512 + i] * U[c * 512 + i];
        norms[512 + i] = sqrtf(fmaxf(s, 0.f));
    }
}

// --------------------------- attention + fold into Wp -----------------------
__global__ void attn_kernel(const float* __restrict__ G,
                            const float* __restrict__ norms,
                            const float* __restrict__ rescale,
                            float* __restrict__ attn) {
    int h = blockIdx.x;
    int i = threadIdx.x;
    __shared__ float row[64][64];
    float nk = fmaxf(norms[h * 64 + i], 1e-12f);
    float rs = rescale[h];
    float mx = -1e30f;
    for (int j = 0; j < 64; j++) {
        float nq = fmaxf(norms[512 + h * 64 + j], 1e-12f);
        float vv = G[h * 4096 + i * 64 + j] * rs / (nk * nq);
        row[i][j] = vv;
        mx = fmaxf(mx, vv);
    }
    float s = 0.f;
    for (int j = 0; j < 64; j++) {
        float e = expf(row[i][j] - mx);
        row[i][j] = e;
        s += e;
    }
    float inv = 1.f / s;
    for (int j = 0; j < 64; j++)
        attn[h * 4096 + i * 64 + j] = row[i][j] * inv;
}

__global__ void wpeff_kernel(const float* __restrict__ attn,
                             const float* __restrict__ Wp,
                             float* __restrict__ wpe) {
    int cp = blockIdx.x;
    int h = cp >> 6, j = cp & 63;
    int t = threadIdx.x;
    float a0 = 0.f, a1 = 0.f, a2 = 0.f, a3 = 0.f;
    const float* at = attn + h * 4096 + j;
    for (int i = 0; i < 64; i++) {
        float a = at[i * 64];
        const float* w = Wp + (size_t)((h << 6) + i) * CCH;
        a0 += a * w[t];
        a1 += a * w[t + 128];
        a2 += a * w[t + 256];
        a3 += a * w[t + 384];
    }
    float* o = wpe + (size_t)cp * CCH;
    o[t] = a0; o[t + 128] = a1; o[t + 256] = a2; o[t + 384] = a3;
}

// --------------------- fused positional branch (dw-gelu-dw) ------------------
__global__ void __launch_bounds__(256) pe_fused_kernel(
    const float* __restrict__ V, const float* __restrict__ w1,
    const float* __restrict__ w2, float* __restrict__ out) {
    __shared__ float vt[20][20][16];
    __shared__ float mid[18][18][16];
    __shared__ float w1s[16][9], w2s[16][9];

    int x0 = blockIdx.x << 4, y0 = blockIdx.y << 4, c0 = blockIdx.z << 4;
    int tid = threadIdx.x;

    if (tid < 144) {
        int cc = tid / 9, kk = tid % 9;
        w1s[cc][kk] = w1[(c0 + cc) * 9 + kk];
        w2s[cc][kk] = w2[(c0 + cc) * 9 + kk];
    }
    for (int e = tid; e < 6400; e += 256) {
        int cc = e & 15;
        int rest = e >> 4;
        int px = rest % 20, py = rest / 20;
        int xx = x0 + px - 2, yy = y0 + py - 2;
        float v = 0.f;
        if (xx >= 0 && xx < WW && yy >= 0 && yy < HH)
            v = V[((size_t)(yy << 8) + xx) * CCH + c0 + cc];
        vt[py][px][cc] = v;
    }
    __syncthreads();
    for (int e = tid; e < 5184; e += 256) {
        int cc = e & 15;
        int rest = e >> 4;
        int mx = rest % 18, my = rest / 18;
        int gx = x0 + mx - 1, gy = y0 + my - 1;
        bool inimg = (gx >= 0 && gx < WW && gy >= 0 && gy < HH);
        float r = 0.f;
        if (inimg) {
            float acc = 0.f;
            #pragma unroll
            for (int ky = 0; ky < 3; ky++)
                #pragma unroll
                for (int kx = 0; kx < 3; kx++)
                    acc += w1s[cc][ky * 3 + kx] * vt[my + ky][mx + kx][cc];
            r = 0.5f * acc * (1.f + erff(acc * 0.70710678118654752f));
        }
        mid[my][mx][cc] = r;
    }
    __syncthreads();
    for (int e = tid; e < 4096; e += 256) {
        int cc = e & 15;
        int ox = (e >> 4) & 15;
        int oy = e >> 8;
        float acc = 0.f;
        #pragma unroll
        for (int ky = 0; ky < 3; ky++)
            #pragma unroll
            for (int kx = 0; kx < 3; kx++)
                acc += w2s[cc][ky * 3 + kx] * mid[oy + ky][ox + kx][cc];
        size_t oi = ((size_t)((y0 + oy) << 8) + x0 + ox) * CCH + c0 + cc;
        out[oi] += acc;
    }
}

// --------------------------------- launch -----------------------------------
extern "C" void kernel_launch(void* const* d_in, const int* in_sizes, int n_in,
                              void* d_out, int out_size) {
    const float* x       = (const float*)d_in[0];
    const float* sar     = (const float*)d_in[1];
    const float* Wq      = (const float*)d_in[2];
    const float* Wk      = (const float*)d_in[3];
    const float* Wv      = (const float*)d_in[4];
    const float* rescale = (const float*)d_in[5];
    const float* Wp      = (const float*)d_in[6];
    const float* bp      = (const float*)d_in[7];
    const float* pe1w    = (const float*)d_in[8];
    const float* pe2w    = (const float*)d_in[9];
    const float* conv3w  = (const float*)d_in[10];
    const float* conv3b  = (const float*)d_in[11];
    const float* bng     = (const float*)d_in[12];
    const float* bnb     = (const float*)d_in[13];
    const float* sobelb  = (const float*)d_in[14];
    const float* conv2w  = (const float*)d_in[15];
    const float* conv2b  = (const float*)d_in[16];
    const float* conv32w = (const float*)d_in[17];
    const float* conv32b = (const float*)d_in[18];
    const float* dconvw  = (const float*)d_in[19];
    const float* dconvb  = (const float*)d_in[20];
    float* out = (float*)d_out;

    float *v, *vm, *F, *W1, *W2, *a, *ss, *bnp, *gpart, *S, *U, *T2;
    float *gram, *norms, *attn, *wpeff;
    cudaGetSymbolAddress((void**)&v, g_v);
    cudaGetSymbolAddress((void**)&vm, g_mask);
    cudaGetSymbolAddress((void**)&F, g_F);
    cudaGetSymbolAddress((void**)&W1, g_W1);
    cudaGetSymbolAddress((void**)&W2, g_W2);
    cudaGetSymbolAddress((void**)&a, g_a);
    cudaGetSymbolAddress((void**)&ss, g_ss);
    cudaGetSymbolAddress((void**)&bnp, g_bnp);
    cudaGetSymbolAddress((void**)&gpart, g_gpart);
    cudaGetSymbolAddress((void**)&S, g_S);
    cudaGetSymbolAddress((void**)&U, g_U);
    cudaGetSymbolAddress((void**)&T2, g_T2);
    cudaGetSymbolAddress((void**)&gram, g_gram);
    cudaGetSymbolAddress((void**)&norms, g_norms);
    cudaGetSymbolAddress((void**)&attn, g_attn);
    cudaGetSymbolAddress((void**)&wpeff, g_wpeff);

    const int TG_SMEM = STGF * 3 * sizeof(float);   // 56832 B
    const int XT_SMEM = XSTGF * 3 * sizeof(float);  // 52224 B
    cudaFuncSetAttribute(tgemm_pipe<0>,
                         cudaFuncAttributeMaxDynamicSharedMemorySize, TG_SMEM);
    cudaFuncSetAttribute(tgemm_pipe<1>,
                         cudaFuncAttributeMaxDynamicSharedMemorySize, TG_SMEM);
    cudaFuncSetAttribute(xtx_pipe,
                         cudaFuncAttributeMaxDynamicSharedMemorySize, XT_SMEM);

    // SAR path -> mask features / weights
    conv3_kernel<<<256, 256>>>(sar, conv3w, conv3b, a);
    bnstats_kernel<<<2, 512>>>(a, bng, bnb, bnp);
    sobel_ss_kernel<<<256, 256>>>(a, bnp, sobelb, ss);
    fbuild_kernel<<<1024, 256>>>(ss, F);
    wbuild_kernel<<<1, 512>>>(conv2w, conv2b, conv32w, conv32b,
                              dconvw, dconvb, W1, W2);

    // V projection
    tgemm_pipe<0><<<dim3(4, 512), 256, TG_SMEM>>>(
        x, Wv, Wv, Wv, nullptr, v, v, v, NTOK, CCH);

    // vm = mask(F) * v  (gating fused into mask GEMM epilogue)
    maskgemm_kernel<<<dim3(4, 512), 256>>>(F, W1, W2, v, vm);

    // S = X^T X (symmetric, split-K); U = S@Wq; T2 = S@Wk
    xtx_pipe<<<dim3(10, 32), 256, XT_SMEM>>>(x, gpart);
    xtx_reduce_sym<<<256, 1024>>>(gpart, S);
    tgemm_pipe<0><<<dim3(8, 4), 256, TG_SMEM>>>(
        S, Wq, Wk, Wk, nullptr, U, T2, T2, 512, CCH);

    // per-head Gram + norms
    gramw_kernel<<<dim3(1, 8), 256>>>(Wk, U, gram);
    normdot_kernel<<<2, 512>>>(Wk, T2, Wq, U, norms);

    // attention folded into Wp
    attn_kernel<<<8, 64>>>(gram, norms, rescale, attn);
    wpeff_kernel<<<512, 128>>>(attn, Wp, wpeff);

    // out_c = vm @ Wp_eff + bp -> d_out
    tgemm_pipe<1><<<dim3(4, 512), 256, TG_SMEM>>>(
        vm, wpeff, wpeff, wpeff, bp, out, out, out, NTOK, CCH);

    // positional branch added into out
    pe_fused_kernel<<<dim3(16, 16, 32), 256>>>(v, pe1w, pe2w, out);
}

// round 7
// speedup vs baseline: 3.1495x; 1.1059x over previous
#include <cuda_runtime.h>
#include <cuda_bf16.h>
#include <math.h>
#include <stdint.h>

// ---------------------------------------------------------------------------
// MS_MSA — round 7: round-5 winner + dual-stream overlap inside graph capture
// (tcgen05 is unavailable: harness PTX target is compute_103, no 'a').
// Stream plan:
//   s1: SAR path -> [ev_sar] -> xtx -> reduce -> smallgemm -> gram -> norms
//       -> attn -> wpeff -> [ev_aux]
//   0 : vproj -> [ev_v] -> maskgemm ... wait(ev_aux, ev_pe) -> final gemm
//   s2: wait(ev_v) -> pe_fused -> peb -> [ev_pe]
// final gemm epilogue adds bias + peb (same fp32 add order as before).
// ---------------------------------------------------------------------------

#define NTOK 65536
#define CCH  512
#define HH   256
#define WW   256

// ------------------------- scratch (device globals) ------------------------
__device__ float g_v[33554432];      // v_inp [n, c]
__device__ float g_vm[33554432];     // vm = v * mask [n, c]
__device__ float g_peb[33554432];    // positional-branch output [n, c]
__device__ float g_F[5242880];       // mask features [n, 80]
__device__ float g_W1[40960];
__device__ float g_W2[40960];
__device__ float g_a[131072];
__device__ float g_ss[131072];
__device__ float g_bnp[4];
__device__ float g_gpart[8388608];
__device__ float g_S[262144];
__device__ float g_U[262144];
__device__ float g_T2[262144];
__device__ float g_gram[32768];
__device__ float g_norms[1024];
__device__ float g_attn[32768];
__device__ float g_wpeff[262144];

// ------------------------------ SAR path -----------------------------------

__global__ void conv3_kernel(const float* __restrict__ sar,
                             const float* __restrict__ w,
                             const float* __restrict__ b,
                             float* __restrict__ a) {
    int n = blockIdx.x * 256 + threadIdx.x;
    if (n >= NTOK) return;
    int y = n >> 8, x = n & 255;
    #pragma unroll
    for (int co = 0; co < 2; co++) {
        float acc = b[co];
        #pragma unroll
        for (int ci = 0; ci < 2; ci++) {
            #pragma unroll
            for (int ky = 0; ky < 3; ky++) {
                int yy = y + ky - 1;
                if (yy < 0 || yy >= HH) continue;
                #pragma unroll
                for (int kx = 0; kx < 3; kx++) {
                    int xx = x + kx - 1;
                    if (xx < 0 || xx >= WW) continue;
                    acc += w[((co * 2 + ci) * 3 + ky) * 3 + kx] *
                           sar[ci * NTOK + (yy << 8) + xx];
                }
            }
        }
        a[co * NTOK + n] = acc;
    }
}

__global__ void bnstats_kernel(const float* __restrict__ a,
                               const float* __restrict__ gg,
                               const float* __restrict__ bb,
                               float* __restrict__ bnp) {
    int c = blockIdx.x;
    __shared__ float sh[512], sh2[512];
    float s = 0.f, s2 = 0.f;
    for (int i = threadIdx.x; i < NTOK; i += 512) {
        float v = a[c * NTOK + i];
        s += v; s2 += v * v;
    }
    sh[threadIdx.x] = s; sh2[threadIdx.x] = s2;
    __syncthreads();
    for (int st = 256; st > 0; st >>= 1) {
        if (threadIdx.x < st) {
            sh[threadIdx.x] += sh[threadIdx.x + st];
            sh2[threadIdx.x] += sh2[threadIdx.x + st];
        }
        __syncthreads();
    }
    if (threadIdx.x == 0) {
        float mean = sh[0] * (1.f / NTOK);
        float var = sh2[0] * (1.f / NTOK) - mean * mean;
        float sc = gg[c] * rsqrtf(var + 1e-5f);
        bnp[c * 2] = sc;
        bnp[c * 2 + 1] = bb[c] - mean * sc;
    }
}

__global__ void sobel_ss_kernel(const float* __restrict__ a,
                                const float* __restrict__ bnp,
                                const float* __restrict__ sb,
                                float* __restrict__ ss) {
    int n = blockIdx.x * 256 + threadIdx.x;
    if (n >= NTOK) return;
    int y = n >> 8, x = n & 255;
    float sc0 = bnp[0], sh0 = bnp[1], sc1 = bnp[2], sh1 = bnp[3];
    float t[3][3];
    #pragma unroll
    for (int ky = 0; ky < 3; ky++) {
        int yy = y + ky - 1;
        #pragma unroll
        for (int kx = 0; kx < 3; kx++) {
            int xx = x + kx - 1;
            if (yy >= 0 && yy < HH && xx >= 0 && xx < WW) {
                int idx = (yy << 8) + xx;
                t[ky][kx] = a[idx] * sc0 + sh0 + a[NTOK + idx] * sc1 + sh1;
            } else t[ky][kx] = 0.f;
        }
    }
    float gy = -(t[0][0] + 2.f * t[0][1] + t[0][2]) + (t[2][0] + 2.f * t[2][1] + t[2][2]);
    float gx = -(t[0][0] + 2.f * t[1][0] + t[2][0]) + (t[0][2] + 2.f * t[1][2] + t[2][2]);
    float s0 = gy + sb[0], s1 = gx + sb[1], s2 = gy + sb[2], s3 = gx + sb[3];
    float bc0 = a[n] * sc0 + sh0;
    float bc1 = a[NTOK + n] * sc1 + sh1;
    ss[n]        = sqrtf(s0 * s0 + s1 * s1) + bc0;
    ss[NTOK + n] = sqrtf(s2 * s2 + s3 * s3) + bc1;
}

__global__ void __launch_bounds__(256) fbuild_kernel(
    const float* __restrict__ ss, float* __restrict__ F) {
    __shared__ float Fs[64 * 80];
    int p0 = blockIdx.x * 64;
    int tid = threadIdx.x;
    int pix = tid >> 2;
    int t4 = tid & 3;
    int n = p0 + pix;
    int y = n >> 8, x = n & 255;
    for (int t = t4; t < 25; t += 4) {
        int dy = t / 5, dx = t % 5;
        int yy = y + dy - 2, xx = x + dx - 2;
        bool ok = (yy >= 0 && yy < HH && xx >= 0 && xx < WW);
        float s0 = 0.f, s1 = 0.f;
        if (ok) {
            int idx = (yy << 8) + xx;
            s0 = ss[idx];
            s1 = ss[NTOK + idx];
        }
        Fs[pix * 80 + t] = s0;
        Fs[pix * 80 + 25 + t] = s1;
        Fs[pix * 80 + 50 + t] = ok ? 1.f : 0.f;
    }
    if (t4 == 0) {
        Fs[pix * 80 + 75] = 0.f;
        Fs[pix * 80 + 76] = 0.f;
        Fs[pix * 80 + 77] = 0.f;
        Fs[pix * 80 + 78] = 1.f;
        Fs[pix * 80 + 79] = 0.f;
    }
    __syncthreads();
    float* dst = F + (size_t)p0 * 80;
    for (int e = tid; e < 64 * 80; e += 256) dst[e] = Fs[e];
}

__global__ void wbuild_kernel(const float* __restrict__ w2c, const float* __restrict__ b2,
                              const float* __restrict__ w32, const float* __restrict__ b32,
                              const float* __restrict__ dw, const float* __restrict__ db,
                              float* __restrict__ W1, float* __restrict__ W2) {
    int c = threadIdx.x;
    float w20 = w2c[c * 2], w21 = w2c[c * 2 + 1], bb2 = b2[c], bbd = db[c];
    for (int t = 0; t < 25; t++) {
        float d = dw[c * 25 + t];
        float a0 = d * w20, a1 = d * w21, a2 = d * bb2;
        if (t == 12) { a0 += w20; a1 += w21; a2 += bb2; }
        W1[t * 512 + c] = a0;
        W1[(25 + t) * 512 + c] = a1;
        W1[(50 + t) * 512 + c] = a2;
        float e0 = 0.f, e1 = 0.f;
        int dy = t / 5, dx = t % 5;
        if (dy >= 1 && dy <= 3 && dx >= 1 && dx <= 3) {
            int kk = (dy - 1) * 3 + (dx - 1);
            e0 = w32[c * 18 + kk];
            e1 = w32[c * 18 + 9 + kk];
        }
        W2[t * 512 + c] = e0;
        W2[(25 + t) * 512 + c] = e1;
        W2[(50 + t) * 512 + c] = 0.f;
    }
    for (int kk = 75; kk < 80; kk++) {
        W1[kk * 512 + c] = (kk == 78) ? bbd : 0.f;
        W2[kk * 512 + c] = (kk == 78) ? b32[c] : 0.f;
    }
}

// -------------------------- TF32 MMA helpers --------------------------------
__device__ __forceinline__ float f2tf32(float x) {
    float r;
    asm("cvt.rna.tf32.f32 %0, %1;" : "=f"(r) : "f"(x));
    return r;
}

__device__ __forceinline__ uint32_t ld_tf32(const float* p) {
    return __float_as_uint(f2tf32(*p));
}

__device__ __forceinline__ void mma_tf32(float* c, const uint32_t* a,
                                         const uint32_t* b) {
    asm volatile(
        "mma.sync.aligned.m16n8k8.row.col.f32.tf32.tf32.f32 "
        "{%0,%1,%2,%3}, {%4,%5,%6,%7}, {%8,%9}, {%0,%1,%2,%3};"
        : "+f"(c[0]), "+f"(c[1]), "+f"(c[2]), "+f"(c[3])
        : "r"(a[0]), "r"(a[1]), "r"(a[2]), "r"(a[3]), "r"(b[0]), "r"(b[1]));
}

__device__ __forceinline__ uint32_t smaddr(const void* p) {
    return (uint32_t)__cvta_generic_to_shared(p);
}

__device__ __forceinline__ void cpasync16(uint32_t s, const void* g) {
    asm volatile("cp.async.cg.shared.global [%0], [%1], 16;" :: "r"(s), "l"(g));
}

__device__ __forceinline__ void cp_commit() {
    asm volatile("cp.async.commit_group;");
}

// ------------------ pipelined TF32 GEMM: C[M,512]=A[M,K]@B ------------------
// 128x128 tile, 256 thr, 3-stage cp.async pipeline.
// EPI=0: plain store. EPI=1: store acc + bias + peb (fused epilogue).
#define ASF 2560    // 128*20 floats
#define BSF 2176    // 16*136 floats
#define STGF (ASF + BSF)

template <int EPI>
__global__ void __launch_bounds__(256) tgemm_pipe(
    const float* __restrict__ A,
    const float* __restrict__ B0, const float* __restrict__ B1,
    const float* __restrict__ B2, const float* __restrict__ bias,
    const float* __restrict__ peb,
    float* __restrict__ C0, float* __restrict__ C1, float* __restrict__ C2,
    int M, int K) {
    extern __shared__ float sm[];

    const int tid = threadIdx.x;
    const int which = blockIdx.x >> 2;
    const float* B = (which == 0) ? B0 : (which == 1) ? B1 : B2;
    float* C = (which == 0) ? C0 : (which == 1) ? C1 : C2;
    const int bn = (blockIdx.x & 3) << 7;
    const int bm = blockIdx.y << 7;

    const int lane = tid & 31;
    const int g = lane >> 2;
    const int tig = lane & 3;
    const int w = tid >> 5;
    const int wm = (w >> 2) * 64;
    const int wn = (w & 3) * 32;

    const int arow = tid >> 1, acol = (tid & 1) << 3;
    const int brow = tid >> 4, bcol = (tid & 15) << 3;

    float acc[4][4][4];
    #pragma unroll
    for (int i = 0; i < 4; i++)
        #pragma unroll
        for (int j = 0; j < 4; j++)
            #pragma unroll
            for (int e = 0; e < 4; e++) acc[i][j][e] = 0.f;

    const int NK = K >> 4;

#define PIPE_ISSUE(stg, kk)                                                     \
    do {                                                                        \
        float* As_ = sm + (stg) * STGF;                                         \
        float* Bs_ = As_ + ASF;                                                 \
        const float* ga = A + (size_t)(bm + arow) * K + (kk) + acol;            \
        uint32_t sa = smaddr(As_ + arow * 20 + acol);                           \
        cpasync16(sa, ga);                                                      \
        cpasync16(sa + 16, ga + 4);                                             \
        const float* gb = B + (size_t)((kk) + brow) * CCH + bn + bcol;          \
        uint32_t sb = smaddr(Bs_ + brow * 136 + bcol);                          \
        cpasync16(sb, gb);                                                      \
        cpasync16(sb + 16, gb + 4);                                             \
        cp_commit();                                                            \
    } while (0)

    PIPE_ISSUE(0, 0);
    PIPE_ISSUE(1, 16);

    int stg = 0;
    for (int kt = 0; kt < NK; kt++) {
        if (kt + 1 < NK) asm volatile("cp.async.wait_group 1;");
        else             asm volatile("cp.async.wait_group 0;");
        __syncthreads();
        if (kt + 2 < NK) {
            int ns = stg + 2; if (ns >= 3) ns -= 3;
            PIPE_ISSUE(ns, (kt + 2) << 4);
        }
        const float* As_ = sm + stg * STGF;
        const float* Bs_ = As_ + ASF;
        #pragma unroll
        for (int ks = 0; ks < 2; ks++) {
            int kk = ks << 3;
            uint32_t af[4][4];
            #pragma unroll
            for (int mt = 0; mt < 4; mt++) {
                int m0 = wm + (mt << 4) + g;
                af[mt][0] = ld_tf32(As_ + m0 * 20 + kk + tig);
                af[mt][1] = ld_tf32(As_ + (m0 + 8) * 20 + kk + tig);
                af[mt][2] = ld_tf32(As_ + m0 * 20 + kk + tig + 4);
                af[mt][3] = ld_tf32(As_ + (m0 + 8) * 20 + kk + tig + 4);
            }
            uint32_t bf[4][2];
            #pragma unroll
            for (int nt = 0; nt < 4; nt++) {
                int n0 = wn + (nt << 3) + g;
                bf[nt][0] = ld_tf32(Bs_ + (kk + tig) * 136 + n0);
                bf[nt][1] = ld_tf32(Bs_ + (kk + tig + 4) * 136 + n0);
            }
            #pragma unroll
            for (int mt = 0; mt < 4; mt++)
                #pragma unroll
                for (int nt = 0; nt < 4; nt++)
                    mma_tf32(acc[mt][nt], af[mt], bf[nt]);
        }
        stg++; if (stg >= 3) stg = 0;
    }

    #pragma unroll
    for (int mt = 0; mt < 4; mt++) {
        int row = bm + wm + (mt << 4) + g;
        #pragma unroll
        for (int nt = 0; nt < 4; nt++) {
            int col = wn + (nt << 3) + (tig << 1);
            float2 v0, v1;
            v0.x = acc[mt][nt][0]; v0.y = acc[mt][nt][1];
            v1.x = acc[mt][nt][2]; v1.y = acc[mt][nt][3];
            if (EPI) {
                float b0 = bias[bn + col];
                float b1 = bias[bn + col + 1];
                float2 p0 = *reinterpret_cast<const float2*>(
                    peb + (size_t)row * CCH + bn + col);
                float2 p1 = *reinterpret_cast<const float2*>(
                    peb + (size_t)(row + 8) * CCH + bn + col);
                v0.x = (v0.x + b0) + p0.x; v0.y = (v0.y + b1) + p0.y;
                v1.x = (v1.x + b0) + p1.x; v1.y = (v1.y + b1) + p1.y;
            }
            *reinterpret_cast<float2*>(C + (size_t)row * CCH + bn + col) = v0;
            *reinterpret_cast<float2*>(C + (size_t)(row + 8) * CCH + bn + col) = v1;
        }
    }
}

// -------------- pipelined symmetric XtX: upper-tri 128x128 tiles -------------
#define XSTGF (2 * BSF)

__global__ void __launch_bounds__(256) xtx_pipe(
    const float* __restrict__ X, float* __restrict__ part) {
    extern __shared__ float sm[];
    const int tid = threadIdx.x;
    const int til[10] = {0, 0, 0, 0, 1, 1, 1, 2, 2, 3};
    const int tjl[10] = {0, 1, 2, 3, 1, 2, 3, 2, 3, 3};
    const int m0 = til[blockIdx.x] << 7;
    const int n0 = tjl[blockIdx.x] << 7;
    const int kbase = blockIdx.y * 2048;

    const int lane = tid & 31;
    const int g = lane >> 2;
    const int tig = lane & 3;
    const int w = tid >> 5;
    const int wm = (w >> 2) * 64;
    const int wn = (w & 3) * 32;

    const int lrow = tid >> 4, lcol = (tid & 15) << 3;

    float acc[4][4][4];
    #pragma unroll
    for (int i = 0; i < 4; i++)
        #pragma unroll
        for (int j = 0; j < 4; j++)
            #pragma unroll
            for (int e = 0; e < 4; e++) acc[i][j][e] = 0.f;

#define XPIPE_ISSUE(stg, kk)                                                    \
    do {                                                                        \
        float* As_ = sm + (stg) * XSTGF;                                        \
        float* Bs_ = As_ + BSF;                                                 \
        const float* xr = X + (size_t)(kbase + (kk) + lrow) * CCH;              \
        uint32_t sa = smaddr(As_ + lrow * 136 + lcol);                          \
        cpasync16(sa, xr + m0 + lcol);                                          \
        cpasync16(sa + 16, xr + m0 + lcol + 4);                                 \
        uint32_t sb = smaddr(Bs_ + lrow * 136 + lcol);                          \
        cpasync16(sb, xr + n0 + lcol);                                          \
        cpasync16(sb + 16, xr + n0 + lcol + 4);                                 \
        cp_commit();                                                            \
    } while (0)

    XPIPE_ISSUE(0, 0);
    XPIPE_ISSUE(1, 16);

    int stg = 0;
    for (int kt = 0; kt < 128; kt++) {
        if (kt + 1 < 128) asm volatile("cp.async.wait_group 1;");
        else              asm volatile("cp.async.wait_group 0;");
        __syncthreads();
        if (kt + 2 < 128) {
            int ns = stg + 2; if (ns >= 3) ns -= 3;
            XPIPE_ISSUE(ns, (kt + 2) << 4);
        }
        const float* As_ = sm + stg * XSTGF;
        const float* Bs_ = As_ + BSF;
        #pragma unroll
        for (int ks = 0; ks < 2; ks++) {
            int kk = ks << 3;
            uint32_t af[4][4];
            #pragma unroll
            for (int mt = 0; mt < 4; mt++) {
                int mm = wm + (mt << 4) + g;
                af[mt][0] = ld_tf32(As_ + (kk + tig) * 136 + mm);
                af[mt][1] = ld_tf32(As_ + (kk + tig) * 136 + mm + 8);
                af[mt][2] = ld_tf32(As_ + (kk + tig + 4) * 136 + mm);
                af[mt][3] = ld_tf32(As_ + (kk + tig + 4) * 136 + mm + 8);
            }
            uint32_t bf[4][2];
            #pragma unroll
            for (int nt = 0; nt < 4; nt++) {
                int nn = wn + (nt << 3) + g;
                bf[nt][0] = ld_tf32(Bs_ + (kk + tig) * 136 + nn);
                bf[nt][1] = ld_tf32(Bs_ + (kk + tig + 4) * 136 + nn);
            }
            #pragma unroll
            for (int mt = 0; mt < 4; mt++)
                #pragma unroll
                for (int nt = 0; nt < 4; nt++)
                    mma_tf32(acc[mt][nt], af[mt], bf[nt]);
        }
        stg++; if (stg >= 3) stg = 0;
    }

    float* pp = part + (size_t)blockIdx.y * 262144;
    #pragma unroll
    for (int mt = 0; mt < 4; mt++) {
        int row = m0 + wm + (mt << 4) + g;
        #pragma unroll
        for (int nt = 0; nt < 4; nt++) {
            int col = n0 + wn + (nt << 3) + (tig << 1);
            float2 v0, v1;
            v0.x = acc[mt][nt][0]; v0.y = acc[mt][nt][1];
            v1.x = acc[mt][nt][2]; v1.y = acc[mt][nt][3];
            *reinterpret_cast<float2*>(pp + (size_t)row * 512 + col) = v0;
            *reinterpret_cast<float2*>(pp + (size_t)(row + 8) * 512 + col) = v1;
        }
    }
}

__global__ void xtx_reduce_sym(const float* __restrict__ part,
                               float* __restrict__ S) {
    int e = blockIdx.x * 1024 + threadIdx.x;
    int r = e >> 9, c = e & 511;
    int idx = ((r >> 7) <= (c >> 7)) ? e : ((c << 9) + r);
    float s = 0.f;
    #pragma unroll
    for (int ch = 0; ch < 32; ch++) s += part[(size_t)ch * 262144 + idx];
    S[e] = s;
}

// ----------------------- mask GEMM: K=80, dual B, sigmoid --------------------
// writes vm = (F@W1 + sigmoid(F@W2)) * v
__global__ void __launch_bounds__(256) maskgemm_kernel(
    const float* __restrict__ F, const float* __restrict__ W1,
    const float* __restrict__ W2, const float* __restrict__ V,
    float* __restrict__ vm) {
    __shared__ __align__(16) float As[2][16][136];
    __shared__ __align__(16) float Bs1[2][16][136];
    __shared__ __align__(16) float Bs2[2][16][136];

    const int tid = threadIdx.x;
    const int bn = blockIdx.x << 7;
    const int bm = blockIdx.y << 7;

    const int lane = tid & 31;
    const int g = lane >> 2;
    const int tig = lane & 3;
    const int w = tid >> 5;
    const int wm = (w >> 2) * 64;
    const int wn = (w & 3) * 32;

    const int ar = tid >> 2;
    const int ac = (tid & 3) << 2;
    const int br = tid >> 5;
    const int bc = (tid & 31) << 2;

    float acc1[4][4][4], acc2[4][4][4];
    #pragma unroll
    for (int i = 0; i < 4; i++)
        #pragma unroll
        for (int j = 0; j < 4; j++)
            #pragma unroll
            for (int e = 0; e < 4; e++) { acc1[i][j][e] = 0.f; acc2[i][j][e] = 0.f; }

#define MG_LOAD(buf, kk)                                                        \
    do {                                                                        \
        _Pragma("unroll")                                                       \
        for (int rr = 0; rr < 2; rr++) {                                        \
            int r = ar + (rr << 6);                                             \
            const float* ap = F + (size_t)(bm + r) * 80 + (kk) + ac;            \
            float4 va = *reinterpret_cast<const float4*>(ap);                   \
            As[buf][ac + 0][r] = f2tf32(va.x);                                  \
            As[buf][ac + 1][r] = f2tf32(va.y);                                  \
            As[buf][ac + 2][r] = f2tf32(va.z);                                  \
            As[buf][ac + 3][r] = f2tf32(va.w);                                  \
        }                                                                       \
        _Pragma("unroll")                                                       \
        for (int rr = 0; rr < 2; rr++) {                                        \
            int r = br + (rr << 3);                                             \
            const float* bp = W1 + (size_t)((kk) + r) * CCH + bn + bc;          \
            float4 vb = *reinterpret_cast<const float4*>(bp);                   \
            float4 vc;                                                          \
            vc.x = f2tf32(vb.x); vc.y = f2tf32(vb.y);                           \
            vc.z = f2tf32(vb.z); vc.w = f2tf32(vb.w);                           \
            *reinterpret_cast<float4*>(&Bs1[buf][r][bc]) = vc;                  \
            const float* bq = W2 + (size_t)((kk) + r) * CCH + bn + bc;          \
            float4 wb = *reinterpret_cast<const float4*>(bq);                   \
            float4 wc;                                                          \
            wc.x = f2tf32(wb.x); wc.y = f2tf32(wb.y);                           \
            wc.z = f2tf32(wb.z); wc.w = f2tf32(wb.w);                           \
            *reinterpret_cast<float4*>(&Bs2[buf][r][bc]) = wc;                  \
        }                                                                       \
    } while (0)

    MG_LOAD(0, 0);
    __syncthreads();
    for (int kt = 0; kt < 5; kt++) {
        int cur = kt & 1;
        if (kt + 1 < 5) MG_LOAD(cur ^ 1, (kt + 1) << 4);
        #pragma unroll
        for (int ks = 0; ks < 2; ks++) {
            int kk = ks << 3;
            uint32_t af[4][4];
            #pragma unroll
            for (int mt = 0; mt < 4; mt++) {
                int m0 = wm + (mt << 4);
                af[mt][0] = __float_as_uint(As[cur][kk + tig][m0 + g]);
                af[mt][1] = __float_as_uint(As[cur][kk + tig][m0 + g + 8]);
                af[mt][2] = __float_as_uint(As[cur][kk + tig + 4][m0 + g]);
                af[mt][3] = __float_as_uint(As[cur][kk + tig + 4][m0 + g + 8]);
            }
            #pragma unroll
            for (int nt = 0; nt < 4; nt++) {
                int n0 = wn + (nt << 3);
                uint32_t bf1[2], bf2[2];
                bf1[0] = __float_as_uint(Bs1[cur][kk + tig][n0 + g]);
                bf1[1] = __float_as_uint(Bs1[cur][kk + tig + 4][n0 + g]);
                bf2[0] = __float_as_uint(Bs2[cur][kk + tig][n0 + g]);
                bf2[1] = __float_as_uint(Bs2[cur][kk + tig + 4][n0 + g]);
                #pragma unroll
                for (int mt = 0; mt < 4; mt++) {
                    mma_tf32(acc1[mt][nt], af[mt], bf1);
                    mma_tf32(acc2[mt][nt], af[mt], bf2);
                }
            }
        }
        __syncthreads();
    }

    #pragma unroll
    for (int mt = 0; mt < 4; mt++) {
        int row = bm + wm + (mt << 4) + g;
        #pragma unroll
        for (int nt = 0; nt < 4; nt++) {
            int col = wn + (nt << 3) + (tig << 1);
            float2 va = *reinterpret_cast<const float2*>(
                V + (size_t)row * CCH + bn + col);
            float2 vb = *reinterpret_cast<const float2*>(
                V + (size_t)(row + 8) * CCH + bn + col);
            float2 v0, v1;
            v0.x = (acc1[mt][nt][0] + 1.f / (1.f + expf(-acc2[mt][nt][0]))) * va.x;
            v0.y = (acc1[mt][nt][1] + 1.f / (1.f + expf(-acc2[mt][nt][1]))) * va.y;
            v1.x = (acc1[mt][nt][2] + 1.f / (1.f + expf(-acc2[mt][nt][2]))) * vb.x;
            v1.y = (acc1[mt][nt][3] + 1.f / (1.f + expf(-acc2[mt][nt][3]))) * vb.y;
            *reinterpret_cast<float2*>(vm + (size_t)row * CCH + bn + col) = v0;
            *reinterpret_cast<float2*>(vm + (size_t)(row + 8) * CCH + bn + col) = v1;
        }
    }
}

// ---------------- per-head Gram from weights: G = Wk_h^T U_h ----------------
__global__ void __launch_bounds__(256) gramw_kernel(
    const float* __restrict__ Km, const float* __restrict__ Qm,
    float* __restrict__ gram) {
    int h = blockIdx.y;
    __shared__ float ks[64][64];
    __shared__ float qs[64][64];
    int tid = threadIdx.x;
    int lt = tid >> 2;
    int lc = (tid & 3) * 16;
    int i0 = (tid >> 4) * 4;
    int j0 = (tid & 15) * 4;
    float acc[4][4];
    #pragma unroll
    for (int i = 0; i < 4; i++)
        #pragma unroll
        for (int j = 0; j < 4; j++) acc[i][j] = 0.f;

    for (int sub = 0; sub < 8; sub++) {
        int row = sub * 64 + lt;
        const float* kp = Km + (size_t)row * CCH + h * 64 + lc;
        const float* qp = Qm + (size_t)row * CCH + h * 64 + lc;
        #pragma unroll
        for (int u = 0; u < 4; u++) {
            *reinterpret_cast<float4*>(&ks[lt][lc + u * 4]) =
                *reinterpret_cast<const float4*>(kp + u * 4);
            *reinterpret_cast<float4*>(&qs[lt][lc + u * 4]) =
                *reinterpret_cast<const float4*>(qp + u * 4);
        }
        __syncthreads();
        #pragma unroll
        for (int t = 0; t < 64; t++) {
            float4 kv = *reinterpret_cast<const float4*>(&ks[t][i0]);
            float4 qv = *reinterpret_cast<const float4*>(&qs[t][j0]);
            float kr[4] = {kv.x, kv.y, kv.z, kv.w};
            float qr[4] = {qv.x, qv.y, qv.z, qv.w};
            #pragma unroll
            for (int i = 0; i < 4; i++)
                #pragma unroll
                for (int j = 0; j < 4; j++) acc[i][j] += kr[i] * qr[j];
        }
        __syncthreads();
    }
    float* pp = gram + (size_t)h * 4096;
    #pragma unroll
    for (int i = 0; i < 4; i++)
        #pragma unroll
        for (int j = 0; j < 4; j++) pp[(i0 + i) * 64 + j0 + j] = acc[i][j];
}

__global__ void normdot_kernel(const float* __restrict__ Wk,
                               const float* __restrict__ T2,
                               const float* __restrict__ Wq,
                               const float* __restrict__ U,
                               float* __restrict__ norms) {
    int i = threadIdx.x;
    float s = 0.f;
    if (blockIdx.x == 0) {
        for (int c = 0; c < 512; c++) s += Wk[c * 512 + i] * T2[c * 512 + i];
        norms[i] = sqrtf(fmaxf(s, 0.f));
    } else {
        for (int c = 0; c < 512; c++) s += Wq[c * 512 + i] * U[c * 512 + i];
        norms[512 + i] = sqrtf(fmaxf(s, 0.f));
    }
}

// --------------------------- attention + fold into Wp -----------------------
__global__ void attn_kernel(const float* __restrict__ G,
                            const float* __restrict__ norms,
                            const float* __restrict__ rescale,
                            float* __restrict__ attn) {
    int h = blockIdx.x;
    int i = threadIdx.x;
    __shared__ float row[64][64];
    float nk = fmaxf(norms[h * 64 + i], 1e-12f);
    float rs = rescale[h];
    float mx = -1e30f;
    for (int j = 0; j < 64; j++) {
        float nq = fmaxf(norms[512 + h * 64 + j], 1e-12f);
        float vv = G[h * 4096 + i * 64 + j] * rs / (nk * nq);
        row[i][j] = vv;
        mx = fmaxf(mx, vv);
    }
    float s = 0.f;
    for (int j = 0; j < 64; j++) {
        float e = expf(row[i][j] - mx);
        row[i][j] = e;
        s += e;
    }
    float inv = 1.f / s;
    for (int j = 0; j < 64; j++)
        attn[h * 4096 + i * 64 + j] = row[i][j] * inv;
}

__global__ void wpeff_kernel(const float* __restrict__ attn,
                             const float* __restrict__ Wp,
                             float* __restrict__ wpe) {
    int cp = blockIdx.x;
    int h = cp >> 6, j = cp & 63;
    int t = threadIdx.x;
    float a0 = 0.f, a1 = 0.f, a2 = 0.f, a3 = 0.f;
    const float* at = attn + h * 4096 + j;
    for (int i = 0; i < 64; i++) {
        float a = at[i * 64];
        const float* w = Wp + (size_t)((h << 6) + i) * CCH;
        a0 += a * w[t];
        a1 += a * w[t + 128];
        a2 += a * w[t + 256];
        a3 += a * w[t + 384];
    }
    float* o = wpe + (size_t)cp * CCH;
    o[t] = a0; o[t + 128] = a1; o[t + 256] = a2; o[t + 384] = a3;
}

// --------------------- fused positional branch (dw-gelu-dw) ------------------
// writes pe result into peb (added later by the final GEMM epilogue).
__global__ void __launch_bounds__(256) pe_fused_kernel(
    const float* __restrict__ V, const float* __restrict__ w1,
    const float* __restrict__ w2, float* __restrict__ peb) {
    __shared__ float vt[20][20][16];
    __shared__ float mid[18][18][16];
    __shared__ float w1s[16][9], w2s[16][9];

    int x0 = blockIdx.x << 4, y0 = blockIdx.y << 4, c0 = blockIdx.z << 4;
    int tid = threadIdx.x;

    if (tid < 144) {
        int cc = tid / 9, kk = tid % 9;
        w1s[cc][kk] = w1[(c0 + cc) * 9 + kk];
        w2s[cc][kk] = w2[(c0 + cc) * 9 + kk];
    }
    for (int e = tid; e < 6400; e += 256) {
        int cc = e & 15;
        int rest = e >> 4;
        int px = rest % 20, py = rest / 20;
        int xx = x0 + px - 2, yy = y0 + py - 2;
        float v = 0.f;
        if (xx >= 0 && xx < WW && yy >= 0 && yy < HH)
            v = V[((size_t)(yy << 8) + xx) * CCH + c0 + cc];
        vt[py][px][cc] = v;
    }
    __syncthreads();
    for (int e = tid; e < 5184; e += 256) {
        int cc = e & 15;
        int rest = e >> 4;
        int mx = rest % 18, my = rest / 18;
        int gx = x0 + mx - 1, gy = y0 + my - 1;
        bool inimg = (gx >= 0 && gx < WW && gy >= 0 && gy < HH);
        float r = 0.f;
        if (inimg) {
            float acc = 0.f;
            #pragma unroll
            for (int ky = 0; ky < 3; ky++)
                #pragma unroll
                for (int kx = 0; kx < 3; kx++)
                    acc += w1s[cc][ky * 3 + kx] * vt[my + ky][mx + kx][cc];
            r = 0.5f * acc * (1.f + erff(acc * 0.70710678118654752f));
        }
        mid[my][mx][cc] = r;
    }
    __syncthreads();
    for (int e = tid; e < 4096; e += 256) {
        int cc = e & 15;
        int ox = (e >> 4) & 15;
        int oy = e >> 8;
        float acc = 0.f;
        #pragma unroll
        for (int ky = 0; ky < 3; ky++)
            #pragma unroll
            for (int kx = 0; kx < 3; kx++)
                acc += w2s[cc][ky * 3 + kx] * mid[oy + ky][ox + kx][cc];
        size_t oi = ((size_t)((y0 + oy) << 8) + x0 + ox) * CCH + c0 + cc;
        peb[oi] = acc;
    }
}

// --------------------------------- launch -----------------------------------
extern "C" void kernel_launch(void* const* d_in, const int* in_sizes, int n_in,
                              void* d_out, int out_size) {
    const float* x       = (const float*)d_in[0];
    const float* sar     = (const float*)d_in[1];
    const float* Wq      = (const float*)d_in[2];
    const float* Wk      = (const float*)d_in[3];
    const float* Wv      = (const float*)d_in[4];
    const float* rescale = (const float*)d_in[5];
    const float* Wp      = (const float*)d_in[6];
    const float* bp      = (const float*)d_in[7];
    const float* pe1w    = (const float*)d_in[8];
    const float* pe2w    = (const float*)d_in[9];
    const float* conv3w  = (const float*)d_in[10];
    const float* conv3b  = (const float*)d_in[11];
    const float* bng     = (const float*)d_in[12];
    const float* bnb     = (const float*)d_in[13];
    const float* sobelb  = (const float*)d_in[14];
    const float* conv2w  = (const float*)d_in[15];
    const float* conv2b  = (const float*)d_in[16];
    const float* conv32w = (const float*)d_in[17];
    const float* conv32b = (const float*)d_in[18];
    const float* dconvw  = (const float*)d_in[19];
    const float* dconvb  = (const float*)d_in[20];
    float* out = (float*)d_out;

    float *v, *vm, *peb, *F, *W1, *W2, *a, *ss, *bnp, *gpart, *S, *U, *T2;
    float *gram, *norms, *attn, *wpeff;
    cudaGetSymbolAddress((void**)&v, g_v);
    cudaGetSymbolAddress((void**)&vm, g_vm);
    cudaGetSymbolAddress((void**)&peb, g_peb);
    cudaGetSymbolAddress((void**)&F, g_F);
    cudaGetSymbolAddress((void**)&W1, g_W1);
    cudaGetSymbolAddress((void**)&W2, g_W2);
    cudaGetSymbolAddress((void**)&a, g_a);
    cudaGetSymbolAddress((void**)&ss, g_ss);
    cudaGetSymbolAddress((void**)&bnp, g_bnp);
    cudaGetSymbolAddress((void**)&gpart, g_gpart);
    cudaGetSymbolAddress((void**)&S, g_S);
    cudaGetSymbolAddress((void**)&U, g_U);
    cudaGetSymbolAddress((void**)&T2, g_T2);
    cudaGetSymbolAddress((void**)&gram, g_gram);
    cudaGetSymbolAddress((void**)&norms, g_norms);
    cudaGetSymbolAddress((void**)&attn, g_attn);
    cudaGetSymbolAddress((void**)&wpeff, g_wpeff);

    const int SM_GEMM = STGF * 3 * sizeof(float);
    const int SM_XTX = XSTGF * 3 * sizeof(float);
    cudaFuncSetAttribute(tgemm_pipe<0>,
                         cudaFuncAttributeMaxDynamicSharedMemorySize, SM_GEMM);
    cudaFuncSetAttribute(tgemm_pipe<1>,
                         cudaFuncAttributeMaxDynamicSharedMemorySize, SM_GEMM);
    cudaFuncSetAttribute(xtx_pipe,
                         cudaFuncAttributeMaxDynamicSharedMemorySize, SM_XTX);

    // streams / events (created once, outside capture on the first call)
    static cudaStream_t s1 = nullptr, s2 = nullptr;
    static cudaEvent_t ev_fork = nullptr, ev_sar = nullptr, ev_v = nullptr,
                       ev_aux = nullptr, ev_pe = nullptr;
    if (!s1) {
        cudaStreamCreateWithFlags(&s1, cudaStreamNonBlocking);
        cudaStreamCreateWithFlags(&s2, cudaStreamNonBlocking);
        cudaEventCreateWithFlags(&ev_fork, cudaEventDisableTiming);
        cudaEventCreateWithFlags(&ev_sar, cudaEventDisableTiming);
        cudaEventCreateWithFlags(&ev_v, cudaEventDisableTiming);
        cudaEventCreateWithFlags(&ev_aux, cudaEventDisableTiming);
        cudaEventCreateWithFlags(&ev_pe, cudaEventDisableTiming);
    }
    cudaStream_t s0 = 0;

    // fork
    cudaEventRecord(ev_fork, s0);
    cudaStreamWaitEvent(s1, ev_fork, 0);
    cudaStreamWaitEvent(s2, ev_fork, 0);

    // ---- stream s1: SAR path + XtX/gram/attn/wpeff chain ----
    conv3_kernel<<<256, 256, 0, s1>>>(sar, conv3w, conv3b, a);
    bnstats_kernel<<<2, 512, 0, s1>>>(a, bng, bnb, bnp);
    sobel_ss_kernel<<<256, 256, 0, s1>>>(a, bnp, sobelb, ss);
    fbuild_kernel<<<1024, 256, 0, s1>>>(ss, F);
    wbuild_kernel<<<1, 512, 0, s1>>>(conv2w, conv2b, conv32w, conv32b,
                                     dconvw, dconvb, W1, W2);
    cudaEventRecord(ev_sar, s1);
    xtx_pipe<<<dim3(10, 32), 256, SM_XTX, s1>>>(x, gpart);
    xtx_reduce_sym<<<256, 1024, 0, s1>>>(gpart, S);
    tgemm_pipe<0><<<dim3(8, 4), 256, SM_GEMM, s1>>>(
        S, Wq, Wk, Wk, nullptr, nullptr, U, T2, T2, 512, CCH);
    gramw_kernel<<<dim3(1, 8), 256, 0, s1>>>(Wk, U, gram);
    normdot_kernel<<<2, 512, 0, s1>>>(Wk, T2, Wq, U, norms);
    attn_kernel<<<8, 64, 0, s1>>>(gram, norms, rescale, attn);
    wpeff_kernel<<<512, 128, 0, s1>>>(attn, Wp, wpeff);
    cudaEventRecord(ev_aux, s1);

    // ---- stream 0: V projection, then gated mask ----
    tgemm_pipe<0><<<dim3(4, 512), 256, SM_GEMM, s0>>>(
        x, Wv, Wv, Wv, nullptr, nullptr, v, v, v, NTOK, CCH);
    cudaEventRecord(ev_v, s0);
    cudaStreamWaitEvent(s0, ev_sar, 0);
    maskgemm_kernel<<<dim3(4, 512), 256, 0, s0>>>(F, W1, W2, v, vm);

    // ---- stream s2: positional branch (needs v only) ----
    cudaStreamWaitEvent(s2, ev_v, 0);
    pe_fused_kernel<<<dim3(16, 16, 32), 256, 0, s2>>>(v, pe1w, pe2w, peb);
    cudaEventRecord(ev_pe, s2);

    // ---- join: final GEMM with fused bias+pe epilogue ----
    cudaStreamWaitEvent(s0, ev_aux, 0);
    cudaStreamWaitEvent(s0, ev_pe, 0);
    tgemm_pipe<1><<<dim3(4, 512), 256, SM_GEMM, s0>>>(
        vm, wpeff, wpeff, wpeff, bp, peb, out, out, out, NTOK, CCH);
}

// round 8
// speedup vs baseline: 3.7700x; 1.1970x over previous
#include <cuda_runtime.h>
#include <cuda_bf16.h>
#include <cuda_fp16.h>
#include <math.h>
#include <stdint.h>

// ---------------------------------------------------------------------------
// MS_MSA — round 8: big GEMMs on fp16 HMMA (m16n8k16, fp32 accum; eps = tf32),
// keeping round-7 dual-stream overlap. xtx/small GEMM stay tf32.
// ---------------------------------------------------------------------------

#define NTOK 65536
#define CCH  512
#define HH   256
#define WW   256

// ------------------------- scratch (device globals) ------------------------
__device__ float  g_v[33554432];      // v_inp [n, c] fp32
__device__ __half g_xh[33554432];     // x in fp16
__device__ __half g_vmh[33554432];    // vm = v * mask, fp16
__device__ float  g_peb[33554432];    // positional-branch output fp32
__device__ __half g_Fh[5242880];      // mask features [n, 80] fp16
__device__ __half g_W1h[40960];       // [c][80] fp16
__device__ __half g_W2h[40960];       // [c][80] fp16
__device__ __half g_WvTh[262144];     // Wv^T [cout][cin] fp16
__device__ __half g_wpeTh[262144];    // Wp_eff^T [m][cp] fp16
__device__ float  g_a[131072];
__device__ float  g_ss[131072];
__device__ float  g_bnp[4];
__device__ float  g_gpart[8388608];
__device__ float  g_S[262144];
__device__ float  g_U[262144];
__device__ float  g_T2[262144];
__device__ float  g_gram[32768];
__device__ float  g_norms[1024];
__device__ float  g_attn[32768];

// ------------------------------ SAR path -----------------------------------

__global__ void conv3_kernel(const float* __restrict__ sar,
                             const float* __restrict__ w,
                             const float* __restrict__ b,
                             float* __restrict__ a) {
    int n = blockIdx.x * 256 + threadIdx.x;
    if (n >= NTOK) return;
    int y = n >> 8, x = n & 255;
    #pragma unroll
    for (int co = 0; co < 2; co++) {
        float acc = b[co];
        #pragma unroll
        for (int ci = 0; ci < 2; ci++) {
            #pragma unroll
            for (int ky = 0; ky < 3; ky++) {
                int yy = y + ky - 1;
                if (yy < 0 || yy >= HH) continue;
                #pragma unroll
                for (int kx = 0; kx < 3; kx++) {
                    int xx = x + kx - 1;
                    if (xx < 0 || xx >= WW) continue;
                    acc += w[((co * 2 + ci) * 3 + ky) * 3 + kx] *
                           sar[ci * NTOK + (yy << 8) + xx];
                }
            }
        }
        a[co * NTOK + n] = acc;
    }
}

__global__ void bnstats_kernel(const float* __restrict__ a,
                               const float* __restrict__ gg,
                               const float* __restrict__ bb,
                               float* __restrict__ bnp) {
    int c = blockIdx.x;
    __shared__ float sh[512], sh2[512];
    float s = 0.f, s2 = 0.f;
    for (int i = threadIdx.x; i < NTOK; i += 512) {
        float v = a[c * NTOK + i];
        s += v; s2 += v * v;
    }
    sh[threadIdx.x] = s; sh2[threadIdx.x] = s2;
    __syncthreads();
    for (int st = 256; st > 0; st >>= 1) {
        if (threadIdx.x < st) {
            sh[threadIdx.x] += sh[threadIdx.x + st];
            sh2[threadIdx.x] += sh2[threadIdx.x + st];
        }
        __syncthreads();
    }
    if (threadIdx.x == 0) {
        float mean = sh[0] * (1.f / NTOK);
        float var = sh2[0] * (1.f / NTOK) - mean * mean;
        float sc = gg[c] * rsqrtf(var + 1e-5f);
        bnp[c * 2] = sc;
        bnp[c * 2 + 1] = bb[c] - mean * sc;
    }
}

__global__ void sobel_ss_kernel(const float* __restrict__ a,
                                const float* __restrict__ bnp,
                                const float* __restrict__ sb,
                                float* __restrict__ ss) {
    int n = blockIdx.x * 256 + threadIdx.x;
    if (n >= NTOK) return;
    int y = n >> 8, x = n & 255;
    float sc0 = bnp[0], sh0 = bnp[1], sc1 = bnp[2], sh1 = bnp[3];
    float t[3][3];
    #pragma unroll
    for (int ky = 0; ky < 3; ky++) {
        int yy = y + ky - 1;
        #pragma unroll
        for (int kx = 0; kx < 3; kx++) {
            int xx = x + kx - 1;
            if (yy >= 0 && yy < HH && xx >= 0 && xx < WW) {
                int idx = (yy << 8) + xx;
                t[ky][kx] = a[idx] * sc0 + sh0 + a[NTOK + idx] * sc1 + sh1;
            } else t[ky][kx] = 0.f;
        }
    }
    float gy = -(t[0][0] + 2.f * t[0][1] + t[0][2]) + (t[2][0] + 2.f * t[2][1] + t[2][2]);
    float gx = -(t[0][0] + 2.f * t[1][0] + t[2][0]) + (t[0][2] + 2.f * t[1][2] + t[2][2]);
    float s0 = gy + sb[0], s1 = gx + sb[1], s2 = gy + sb[2], s3 = gx + sb[3];
    float bc0 = a[n] * sc0 + sh0;
    float bc1 = a[NTOK + n] * sc1 + sh1;
    ss[n]        = sqrtf(s0 * s0 + s1 * s1) + bc0;
    ss[NTOK + n] = sqrtf(s2 * s2 + s3 * s3) + bc1;
}

__global__ void __launch_bounds__(256) fbuild_kernel(
    const float* __restrict__ ss, __half* __restrict__ F) {
    __shared__ float Fs[64 * 80];
    int p0 = blockIdx.x * 64;
    int tid = threadIdx.x;
    int pix = tid >> 2;
    int t4 = tid & 3;
    int n = p0 + pix;
    int y = n >> 8, x = n & 255;
    for (int t = t4; t < 25; t += 4) {
        int dy = t / 5, dx = t % 5;
        int yy = y + dy - 2, xx = x + dx - 2;
        bool ok = (yy >= 0 && yy < HH && xx >= 0 && xx < WW);
        float s0 = 0.f, s1 = 0.f;
        if (ok) {
            int idx = (yy << 8) + xx;
            s0 = ss[idx];
            s1 = ss[NTOK + idx];
        }
        Fs[pix * 80 + t] = s0;
        Fs[pix * 80 + 25 + t] = s1;
        Fs[pix * 80 + 50 + t] = ok ? 1.f : 0.f;
    }
    if (t4 == 0) {
        Fs[pix * 80 + 75] = 0.f;
        Fs[pix * 80 + 76] = 0.f;
        Fs[pix * 80 + 77] = 0.f;
        Fs[pix * 80 + 78] = 1.f;
        Fs[pix * 80 + 79] = 0.f;
    }
    __syncthreads();
    __half* dst = F + (size_t)p0 * 80;
    for (int e = tid; e < 64 * 80; e += 256) dst[e] = __float2half(Fs[e]);
}

// W1h/W2h in [c][80] fp16 (BT layout for fp16 mask GEMM)
__global__ void wbuild_kernel(const float* __restrict__ w2c, const float* __restrict__ b2,
                              const float* __restrict__ w32, const float* __restrict__ b32,
                              const float* __restrict__ dw, const float* __restrict__ db,
                              __half* __restrict__ W1, __half* __restrict__ W2) {
    int c = threadIdx.x;
    float w20 = w2c[c * 2], w21 = w2c[c * 2 + 1], bb2 = b2[c], bbd = db[c];
    __half* o1 = W1 + c * 80;
    __half* o2 = W2 + c * 80;
    for (int t = 0; t < 25; t++) {
        float d = dw[c * 25 + t];
        float a0 = d * w20, a1 = d * w21, a2 = d * bb2;
        if (t == 12) { a0 += w20; a1 += w21; a2 += bb2; }
        o1[t] = __float2half(a0);
        o1[25 + t] = __float2half(a1);
        o1[50 + t] = __float2half(a2);
        float e0 = 0.f, e1 = 0.f;
        int dy = t / 5, dx = t % 5;
        if (dy >= 1 && dy <= 3 && dx >= 1 && dx <= 3) {
            int kk = (dy - 1) * 3 + (dx - 1);
            e0 = w32[c * 18 + kk];
            e1 = w32[c * 18 + 9 + kk];
        }
        o2[t] = __float2half(e0);
        o2[25 + t] = __float2half(e1);
        o2[50 + t] = __float2half(0.f);
    }
    for (int kk = 75; kk < 80; kk++) {
        o1[kk] = __float2half((kk == 78) ? bbd : 0.f);
        o2[kk] = __float2half((kk == 78) ? b32[c] : 0.f);
    }
}

// -------------------------- MMA / async helpers ------------------------------
__device__ __forceinline__ float f2tf32(float x) {
    float r;
    asm("cvt.rna.tf32.f32 %0, %1;" : "=f"(r) : "f"(x));
    return r;
}

__device__ __forceinline__ uint32_t ld_tf32(const float* p) {
    return __float_as_uint(f2tf32(*p));
}

__device__ __forceinline__ void mma_tf32(float* c, const uint32_t* a,
                                         const uint32_t* b) {
    asm volatile(
        "mma.sync.aligned.m16n8k8.row.col.f32.tf32.tf32.f32 "
        "{%0,%1,%2,%3}, {%4,%5,%6,%7}, {%8,%9}, {%0,%1,%2,%3};"
        : "+f"(c[0]), "+f"(c[1]), "+f"(c[2]), "+f"(c[3])
        : "r"(a[0]), "r"(a[1]), "r"(a[2]), "r"(a[3]), "r"(b[0]), "r"(b[1]));
}

__device__ __forceinline__ void mma_f16(float* c, const uint32_t* a,
                                        const uint32_t* b) {
    asm volatile(
        "mma.sync.aligned.m16n8k16.row.col.f32.f16.f16.f32 "
        "{%0,%1,%2,%3}, {%4,%5,%6,%7}, {%8,%9}, {%0,%1,%2,%3};"
        : "+f"(c[0]), "+f"(c[1]), "+f"(c[2]), "+f"(c[3])
        : "r"(a[0]), "r"(a[1]), "r"(a[2]), "r"(a[3]), "r"(b[0]), "r"(b[1]));
}

__device__ __forceinline__ uint32_t smaddr(const void* p) {
    return (uint32_t)__cvta_generic_to_shared(p);
}

__device__ __forceinline__ void cpasync16(uint32_t s, const void* g) {
    asm volatile("cp.async.cg.shared.global [%0], [%1], 16;" :: "r"(s), "l"(g));
}

__device__ __forceinline__ void cp_commit() {
    asm volatile("cp.async.commit_group;");
}

// -------------------- fp16 GEMM: C[M,512] = A[M,512] @ BT^T ------------------
// A [M][512] half row-major; BT [512][512] half row-major ([n][k]).
// 128x128 tile, 16 chunks of k32, 3 stages. smem row pad: 40 halves (80 B).
// EPI=0: store fp32 C. EPI=1: C = acc + bias + peb.
#define H_TILEB 10240                   // 128 rows x 80 B
#define H_STGB  (2 * H_TILEB)

template <int EPI>
__global__ void __launch_bounds__(256) hgemm_pipe(
    const __half* __restrict__ A, const __half* __restrict__ BT,
    const float* __restrict__ bias, const float* __restrict__ peb,
    float* __restrict__ C) {
    extern __shared__ char hsm[];
    const int tid = threadIdx.x;
    const int bn = (blockIdx.x & 3) << 7;
    const int bm = blockIdx.y << 7;

    const int lane = tid & 31;
    const int g = lane >> 2;
    const int tig = lane & 3;
    const int w = tid >> 5;
    const int wm = (w >> 2) * 64;
    const int wn = (w & 3) * 32;

    const int crow = tid >> 1;
    const int cseg = (tid & 1) << 4;        // half offset 0 or 16

    uint32_t sbase = smaddr(hsm);

    float acc[4][4][4];
    #pragma unroll
    for (int i = 0; i < 4; i++)
        #pragma unroll
        for (int j = 0; j < 4; j++)
            #pragma unroll
            for (int e = 0; e < 4; e++) acc[i][j][e] = 0.f;

#define H_ISSUE(cc, ss)                                                         \
    do {                                                                        \
        uint32_t ab_ = sbase + (ss) * H_STGB;                                   \
        uint32_t bb_ = ab_ + H_TILEB;                                           \
        int kk_ = (cc) << 5;                                                    \
        const __half* ga_ = A + (size_t)(bm + crow) * CCH + kk_ + cseg;         \
        uint32_t da_ = ab_ + crow * 80 + cseg * 2;                              \
        cpasync16(da_, ga_);                                                    \
        cpasync16(da_ + 16, ga_ + 8);                                           \
        const __half* gb_ = BT + (size_t)(bn + crow) * CCH + kk_ + cseg;        \
        uint32_t db_ = bb_ + crow * 80 + cseg * 2;                              \
        cpasync16(db_, gb_);                                                    \
        cpasync16(db_ + 16, gb_ + 8);                                           \
        cp_commit();                                                            \
    } while (0)

    H_ISSUE(0, 0);
    H_ISSUE(1, 1);

    int stg = 0;
    for (int c = 0; c < 16; c++) {
        if (c + 1 < 16) asm volatile("cp.async.wait_group 1;");
        else            asm volatile("cp.async.wait_group 0;");
        __syncthreads();
        if (c + 2 < 16) {
            int ns = stg + 2; if (ns >= 3) ns -= 3;
            H_ISSUE(c + 2, ns);
        }
        const __half* As_ = (const __half*)(hsm + stg * H_STGB);
        const __half* Bs_ = As_ + 5120;     // H_TILEB bytes = 5120 halves
        #pragma unroll
        for (int ks = 0; ks < 2; ks++) {
            int ko = ks << 4;
            uint32_t af[4][4];
            #pragma unroll
            for (int mt = 0; mt < 4; mt++) {
                int m = wm + (mt << 4) + g;
                af[mt][0] = *reinterpret_cast<const uint32_t*>(As_ + m * 40 + ko + 2 * tig);
                af[mt][1] = *reinterpret_cast<const uint32_t*>(As_ + (m + 8) * 40 + ko + 2 * tig);
                af[mt][2] = *reinterpret_cast<const uint32_t*>(As_ + m * 40 + ko + 2 * tig + 8);
                af[mt][3] = *reinterpret_cast<const uint32_t*>(As_ + (m + 8) * 40 + ko + 2 * tig + 8);
            }
            uint32_t bf[4][2];
            #pragma unroll
            for (int nt = 0; nt < 4; nt++) {
                int n = wn + (nt << 3) + g;
                bf[nt][0] = *reinterpret_cast<const uint32_t*>(Bs_ + n * 40 + ko + 2 * tig);
                bf[nt][1] = *reinterpret_cast<const uint32_t*>(Bs_ + n * 40 + ko + 2 * tig + 8);
            }
            #pragma unroll
            for (int mt = 0; mt < 4; mt++)
                #pragma unroll
                for (int nt = 0; nt < 4; nt++)
                    mma_f16(acc[mt][nt], af[mt], bf[nt]);
        }
        stg++; if (stg >= 3) stg = 0;
    }

    #pragma unroll
    for (int mt = 0; mt < 4; mt++) {
        int row = bm + wm + (mt << 4) + g;
        #pragma unroll
        for (int nt = 0; nt < 4; nt++) {
            int col = wn + (nt << 3) + (tig << 1);
            float2 v0, v1;
            v0.x = acc[mt][nt][0]; v0.y = acc[mt][nt][1];
            v1.x = acc[mt][nt][2]; v1.y = acc[mt][nt][3];
            if (EPI) {
                float b0 = bias[bn + col];
                float b1 = bias[bn + col + 1];
                float2 p0 = *reinterpret_cast<const float2*>(
                    peb + (size_t)row * CCH + bn + col);
                float2 p1 = *reinterpret_cast<const float2*>(
                    peb + (size_t)(row + 8) * CCH + bn + col);
                v0.x = (v0.x + b0) + p0.x; v0.y = (v0.y + b1) + p0.y;
                v1.x = (v1.x + b0) + p1.x; v1.y = (v1.y + b1) + p1.y;
            }
            *reinterpret_cast<float2*>(C + (size_t)row * CCH + bn + col) = v0;
            *reinterpret_cast<float2*>(C + (size_t)(row + 8) * CCH + bn + col) = v1;
        }
    }
}

// -------------- fp16 mask GEMM: K=80, dual B, sigmoid + gate -----------------
// A = F [n][80] half; B1/B2 = W1h/W2h [c][80] half. 5 chunks k16, 3 stages.
// vm_h = half((F@W1 + sigmoid(F@W2)) * v)
#define M_TILEB 6144                    // 128 rows x 48 B
#define M_STGB  (3 * M_TILEB)

__global__ void __launch_bounds__(256) maskgemm_h(
    const __half* __restrict__ F, const __half* __restrict__ W1,
    const __half* __restrict__ W2, const float* __restrict__ V,
    __half* __restrict__ vm) {
    extern __shared__ char hsm[];
    const int tid = threadIdx.x;
    const int bn = blockIdx.x << 7;
    const int bm = blockIdx.y << 7;

    const int lane = tid & 31;
    const int g = lane >> 2;
    const int tig = lane & 3;
    const int w = tid >> 5;
    const int wm = (w >> 2) * 64;
    const int wn = (w & 3) * 32;

    const int crow = tid >> 1;
    const int ch8 = (tid & 1) << 3;          // half offset 0 or 8
    uint32_t sbase = smaddr(hsm);

    float acc1[4][4][4], acc2[4][4][4];
    #pragma unroll
    for (int i = 0; i < 4; i++)
        #pragma unroll
        for (int j = 0; j < 4; j++)
            #pragma unroll
            for (int e = 0; e < 4; e++) { acc1[i][j][e] = 0.f; acc2[i][j][e] = 0.f; }

#define M_ISSUE(cc, ss)                                                         \
    do {                                                                        \
        uint32_t ab_ = sbase + (ss) * M_STGB;                                   \
        uint32_t b1_ = ab_ + M_TILEB;                                           \
        uint32_t b2_ = b1_ + M_TILEB;                                           \
        int kk_ = (cc) << 4;                                                    \
        uint32_t doff_ = crow * 48 + ch8 * 2;                                   \
        cpasync16(ab_ + doff_, F + (size_t)(bm + crow) * 80 + kk_ + ch8);       \
        cpasync16(b1_ + doff_, W1 + (size_t)(bn + crow) * 80 + kk_ + ch8);      \
        cpasync16(b2_ + doff_, W2 + (size_t)(bn + crow) * 80 + kk_ + ch8);      \
        cp_commit();                                                            \
    } while (0)

    M_ISSUE(0, 0);
    M_ISSUE(1, 1);

    int stg = 0;
    for (int c = 0; c < 5; c++) {
        if (c + 1 < 5) asm volatile("cp.async.wait_group 1;");
        else           asm volatile("cp.async.wait_group 0;");
        __syncthreads();
        if (c + 2 < 5) {
            int ns = stg + 2; if (ns >= 3) ns -= 3;
            M_ISSUE(c + 2, ns);
        }
        const __half* As_ = (const __half*)(hsm + stg * M_STGB);
        const __half* B1s = As_ + 3072;
        const __half* B2s = B1s + 3072;
        uint32_t af[4][4];
        #pragma unroll
        for (int mt = 0; mt < 4; mt++) {
            int m = wm + (mt << 4) + g;
            af[mt][0] = *reinterpret_cast<const uint32_t*>(As_ + m * 24 + 2 * tig);
            af[mt][1] = *reinterpret_cast<const uint32_t*>(As_ + (m + 8) * 24 + 2 * tig);
            af[mt][2] = *reinterpret_cast<const uint32_t*>(As_ + m * 24 + 2 * tig + 8);
            af[mt][3] = *reinterpret_cast<const uint32_t*>(As_ + (m + 8) * 24 + 2 * tig + 8);
        }
        #pragma unroll
        for (int nt = 0; nt < 4; nt++) {
            int n = wn + (nt << 3) + g;
            uint32_t bf1[2], bf2[2];
            bf1[0] = *reinterpret_cast<const uint32_t*>(B1s + n * 24 + 2 * tig);
            bf1[1] = *reinterpret_cast<const uint32_t*>(B1s + n * 24 + 2 * tig + 8);
            bf2[0] = *reinterpret_cast<const uint32_t*>(B2s + n * 24 + 2 * tig);
            bf2[1] = *reinterpret_cast<const uint32_t*>(B2s + n * 24 + 2 * tig + 8);
            #pragma unroll
            for (int mt = 0; mt < 4; mt++) {
                mma_f16(acc1[mt][nt], af[mt], bf1);
                mma_f16(acc2[mt][nt], af[mt], bf2);
            }
        }
        stg++; if (stg >= 3) stg = 0;
    }

    #pragma unroll
    for (int mt = 0; mt < 4; mt++) {
        int row = bm + wm + (mt << 4) + g;
        #pragma unroll
        for (int nt = 0; nt < 4; nt++) {
            int col = wn + (nt << 3) + (tig << 1);
            float2 va = *reinterpret_cast<const float2*>(
                V + (size_t)row * CCH + bn + col);
            float2 vb = *reinterpret_cast<const float2*>(
                V + (size_t)(row + 8) * CCH + bn + col);
            float m0 = (acc1[mt][nt][0] + 1.f / (1.f + expf(-acc2[mt][nt][0]))) * va.x;
            float m1 = (acc1[mt][nt][1] + 1.f / (1.f + expf(-acc2[mt][nt][1]))) * va.y;
            float m2 = (acc1[mt][nt][2] + 1.f / (1.f + expf(-acc2[mt][nt][2]))) * vb.x;
            float m3 = (acc1[mt][nt][3] + 1.f / (1.f + expf(-acc2[mt][nt][3]))) * vb.y;
            __half2 h0 = __floats2half2_rn(m0, m1);
            __half2 h1 = __floats2half2_rn(m2, m3);
            *reinterpret_cast<__half2*>(vm + (size_t)row * CCH + bn + col) = h0;
            *reinterpret_cast<__half2*>(vm + (size_t)(row + 8) * CCH + bn + col) = h1;
        }
    }
}

// ---------------------- conversion / transpose kernels -----------------------
__global__ void x2h_kernel(const float* __restrict__ x,
                           __half* __restrict__ xh) {
    size_t i = ((size_t)blockIdx.x * 256 + threadIdx.x) * 8;
    float4 v0 = *reinterpret_cast<const float4*>(x + i);
    float4 v1 = *reinterpret_cast<const float4*>(x + i + 4);
    __half2 h[4];
    h[0] = __floats2half2_rn(v0.x, v0.y);
    h[1] = __floats2half2_rn(v0.z, v0.w);
    h[2] = __floats2half2_rn(v1.x, v1.y);
    h[3] = __floats2half2_rn(v1.z, v1.w);
    *reinterpret_cast<uint4*>(xh + i) = *reinterpret_cast<uint4*>(h);
}

__global__ void transpose_h_kernel(const float* __restrict__ W,
                                   __half* __restrict__ WT) {
    __shared__ float t[32][33];
    int bx = blockIdx.x << 5, by = blockIdx.y << 5;
    int tx = threadIdx.x, ty = threadIdx.y;  // 32 x 8
    #pragma unroll
    for (int r = 0; r < 32; r += 8)
        t[ty + r][tx] = W[(size_t)(by + ty + r) * CCH + bx + tx];
    __syncthreads();
    #pragma unroll
    for (int r = 0; r < 32; r += 8)
        WT[(size_t)(bx + ty + r) * CCH + by + tx] = __float2half(t[tx][ty + r]);
}

// -------------------------- legacy TF32 GEMM (small) -------------------------
#define ASF 2560
#define BSF 2176
#define STGF (ASF + BSF)

__global__ void __launch_bounds__(256) tgemm_pipe(
    const float* __restrict__ A,
    const float* __restrict__ B0, const float* __restrict__ B1,
    float* __restrict__ C0, float* __restrict__ C1, int M, int K) {
    extern __shared__ float sm[];

    const int tid = threadIdx.x;
    const int which = blockIdx.x >> 2;
    const float* B = (which == 0) ? B0 : B1;
    float* C = (which == 0) ? C0 : C1;
    const int bn = (blockIdx.x & 3) << 7;
    const int bm = blockIdx.y << 7;

    const int lane = tid & 31;
    const int g = lane >> 2;
    const int tig = lane & 3;
    const int w = tid >> 5;
    const int wm = (w >> 2) * 64;
    const int wn = (w & 3) * 32;

    const int arow = tid >> 1, acol = (tid & 1) << 3;
    const int brow = tid >> 4, bcol = (tid & 15) << 3;

    float acc[4][4][4];
    #pragma unroll
    for (int i = 0; i < 4; i++)
        #pragma unroll
        for (int j = 0; j < 4; j++)
            #pragma unroll
            for (int e = 0; e < 4; e++) acc[i][j][e] = 0.f;

    const int NK = K >> 4;

#define PIPE_ISSUE(stg, kk)                                                     \
    do {                                                                        \
        float* As_ = sm + (stg) * STGF;                                         \
        float* Bs_ = As_ + ASF;                                                 \
        const float* ga = A + (size_t)(bm + arow) * K + (kk) + acol;            \
        uint32_t sa = smaddr(As_ + arow * 20 + acol);                           \
        cpasync16(sa, ga);                                                      \
        cpasync16(sa + 16, ga + 4);                                             \
        const float* gb = B + (size_t)((kk) + brow) * CCH + bn + bcol;          \
        uint32_t sb = smaddr(Bs_ + brow * 136 + bcol);                          \
        cpasync16(sb, gb);                                                      \
        cpasync16(sb + 16, gb + 4);                                             \
        cp_commit();                                                            \
    } while (0)

    PIPE_ISSUE(0, 0);
    PIPE_ISSUE(1, 16);

    int stg = 0;
    for (int kt = 0; kt < NK; kt++) {
        if (kt + 1 < NK) asm volatile("cp.async.wait_group 1;");
        else             asm volatile("cp.async.wait_group 0;");
        __syncthreads();
        if (kt + 2 < NK) {
            int ns = stg + 2; if (ns >= 3) ns -= 3;
            PIPE_ISSUE(ns, (kt + 2) << 4);
        }
        const float* As_ = sm + stg * STGF;
        const float* Bs_ = As_ + ASF;
        #pragma unroll
        for (int ks = 0; ks < 2; ks++) {
            int kk = ks << 3;
            uint32_t af[4][4];
            #pragma unroll
            for (int mt = 0; mt < 4; mt++) {
                int m0 = wm + (mt << 4) + g;
                af[mt][0] = ld_tf32(As_ + m0 * 20 + kk + tig);
                af[mt][1] = ld_tf32(As_ + (m0 + 8) * 20 + kk + tig);
                af[mt][2] = ld_tf32(As_ + m0 * 20 + kk + tig + 4);
                af[mt][3] = ld_tf32(As_ + (m0 + 8) * 20 + kk + tig + 4);
            }
            uint32_t bf[4][2];
            #pragma unroll
            for (int nt = 0; nt < 4; nt++) {
                int n0 = wn + (nt << 3) + g;
                bf[nt][0] = ld_tf32(Bs_ + (kk + tig) * 136 + n0);
                bf[nt][1] = ld_tf32(Bs_ + (kk + tig + 4) * 136 + n0);
            }
            #pragma unroll
            for (int mt = 0; mt < 4; mt++)
                #pragma unroll
                for (int nt = 0; nt < 4; nt++)
                    mma_tf32(acc[mt][nt], af[mt], bf[nt]);
        }
        stg++; if (stg >= 3) stg = 0;
    }

    #pragma unroll
    for (int mt = 0; mt < 4; mt++) {
        int row = bm + wm + (mt << 4) + g;
        #pragma unroll
        for (int nt = 0; nt < 4; nt++) {
            int col = wn + (nt << 3) + (tig << 1);
            float2 v0, v1;
            v0.x = acc[mt][nt][0]; v0.y = acc[mt][nt][1];
            v1.x = acc[mt][nt][2]; v1.y = acc[mt][nt][3];
            *reinterpret_cast<float2*>(C + (size_t)row * CCH + bn + col) = v0;
            *reinterpret_cast<float2*>(C + (size_t)(row + 8) * CCH + bn + col) = v1;
        }
    }
}

// -------------- pipelined symmetric XtX: upper-tri 128x128 tiles -------------
#define XSTGF (2 * BSF)

__global__ void __launch_bounds__(256) xtx_pipe(
    const float* __restrict__ X, float* __restrict__ part) {
    extern __shared__ float sm[];
    const int tid = threadIdx.x;
    const int til[10] = {0, 0, 0, 0, 1, 1, 1, 2, 2, 3};
    const int tjl[10] = {0, 1, 2, 3, 1, 2, 3, 2, 3, 3};
    const int m0 = til[blockIdx.x] << 7;
    const int n0 = tjl[blockIdx.x] << 7;
    const int kbase = blockIdx.y * 2048;

    const int lane = tid & 31;
    const int g = lane >> 2;
    const int tig = lane & 3;
    const int w = tid >> 5;
    const int wm = (w >> 2) * 64;
    const int wn = (w & 3) * 32;

    const int lrow = tid >> 4, lcol = (tid & 15) << 3;

    float acc[4][4][4];
    #pragma unroll
    for (int i = 0; i < 4; i++)
        #pragma unroll
        for (int j = 0; j < 4; j++)
            #pragma unroll
            for (int e = 0; e < 4; e++) acc[i][j][e] = 0.f;

#define XPIPE_ISSUE(stg, kk)                                                    \
    do {                                                                        \
        float* As_ = sm + (stg) * XSTGF;                                        \
        float* Bs_ = As_ + BSF;                                                 \
        const float* xr = X + (size_t)(kbase + (kk) + lrow) * CCH;              \
        uint32_t sa = smaddr(As_ + lrow * 136 + lcol);                          \
        cpasync16(sa, xr + m0 + lcol);                                          \
        cpasync16(sa + 16, xr + m0 + lcol + 4);                                 \
        uint32_t sb = smaddr(Bs_ + lrow * 136 + lcol);                          \
        cpasync16(sb, xr + n0 + lcol);                                          \
        cpasync16(sb + 16, xr + n0 + lcol + 4);                                 \
        cp_commit();                                                            \
    } while (0)

    XPIPE_ISSUE(0, 0);
    XPIPE_ISSUE(1, 16);

    int stg = 0;
    for (int kt = 0; kt < 128; kt++) {
        if (kt + 1 < 128) asm volatile("cp.async.wait_group 1;");
        else              asm volatile("cp.async.wait_group 0;");
        __syncthreads();
        if (kt + 2 < 128) {
            int ns = stg + 2; if (ns >= 3) ns -= 3;
            XPIPE_ISSUE(ns, (kt + 2) << 4);
        }
        const float* As_ = sm + stg * XSTGF;
        const float* Bs_ = As_ + BSF;
        #pragma unroll
        for (int ks = 0; ks < 2; ks++) {
            int kk = ks << 3;
            uint32_t af[4][4];
            #pragma unroll
            for (int mt = 0; mt < 4; mt++) {
                int mm = wm + (mt << 4) + g;
                af[mt][0] = ld_tf32(As_ + (kk + tig) * 136 + mm);
                af[mt][1] = ld_tf32(As_ + (kk + tig) * 136 + mm + 8);
                af[mt][2] = ld_tf32(As_ + (kk + tig + 4) * 136 + mm);
                af[mt][3] = ld_tf32(As_ + (kk + tig + 4) * 136 + mm + 8);
            }
            uint32_t bf[4][2];
            #pragma unroll
            for (int nt = 0; nt < 4; nt++) {
                int nn = wn + (nt << 3) + g;
                bf[nt][0] = ld_tf32(Bs_ + (kk + tig) * 136 + nn);
                bf[nt][1] = ld_tf32(Bs_ + (kk + tig + 4) * 136 + nn);
            }
            #pragma unroll
            for (int mt = 0; mt < 4; mt++)
                #pragma unroll
                for (int nt = 0; nt < 4; nt++)
                    mma_tf32(acc[mt][nt], af[mt], bf[nt]);
        }
        stg++; if (stg >= 3) stg = 0;
    }

    float* pp = part + (size_t)blockIdx.y * 262144;
    #pragma unroll
    for (int mt = 0; mt < 4; mt++) {
        int row = m0 + wm + (mt << 4) + g;
        #pragma unroll
        for (int nt = 0; nt < 4; nt++) {
            int col = n0 + wn + (nt << 3) + (tig << 1);
            float2 v0, v1;
            v0.x = acc[mt][nt][0]; v0.y = acc[mt][nt][1];
            v1.x = acc[mt][nt][2]; v1.y = acc[mt][nt][3];
            *reinterpret_cast<float2*>(pp + (size_t)row * 512 + col) = v0;
            *reinterpret_cast<float2*>(pp + (size_t)(row + 8) * 512 + col) = v1;
        }
    }
}

__global__ void xtx_reduce_sym(const float* __restrict__ part,
                               float* __restrict__ S) {
    int e = blockIdx.x * 1024 + threadIdx.x;
    int r = e >> 9, c = e & 511;
    int idx = ((r >> 7) <= (c >> 7)) ? e : ((c << 9) + r);
    float s = 0.f;
    #pragma unroll
    for (int ch = 0; ch < 32; ch++) s += part[(size_t)ch * 262144 + idx];
    S[e] = s;
}

// ---------------- per-head Gram from weights: G = Wk_h^T U_h ----------------
__global__ void __launch_bounds__(256) gramw_kernel(
    const float* __restrict__ Km, const float* __restrict__ Qm,
    float* __restrict__ gram) {
    int h = blockIdx.y;
    __shared__ float ks[64][64];
    __shared__ float qs[64][64];
    int tid = threadIdx.x;
    int lt = tid >> 2;
    int lc = (tid & 3) * 16;
    int i0 = (tid >> 4) * 4;
    int j0 = (tid & 15) * 4;
    float acc[4][4];
    #pragma unroll
    for (int i = 0; i < 4; i++)
        #pragma unroll
        for (int j = 0; j < 4; j++) acc[i][j] = 0.f;

    for (int sub = 0; sub < 8; sub++) {
        int row = sub * 64 + lt;
        const float* kp = Km + (size_t)row * CCH + h * 64 + lc;
        const float* qp = Qm + (size_t)row * CCH + h * 64 + lc;
        #pragma unroll
        for (int u = 0; u < 4; u++) {
            *reinterpret_cast<float4*>(&ks[lt][lc + u * 4]) =
                *reinterpret_cast<const float4*>(kp + u * 4);
            *reinterpret_cast<float4*>(&qs[lt][lc + u * 4]) =
                *reinterpret_cast<const float4*>(qp + u * 4);
        }
        __syncthreads();
        #pragma unroll
        for (int t = 0; t < 64; t++) {
            float4 kv = *reinterpret_cast<const float4*>(&ks[t][i0]);
            float4 qv = *reinterpret_cast<const float4*>(&qs[t][j0]);
            float kr[4] = {kv.x, kv.y, kv.z, kv.w};
            float qr[4] = {qv.x, qv.y, qv.z, qv.w};
            #pragma unroll
            for (int i = 0; i < 4; i++)
                #pragma unroll
                for (int j = 0; j < 4; j++) acc[i][j] += kr[i] * qr[j];
        }
        __syncthreads();
    }
    float* pp = gram + (size_t)h * 4096;
    #pragma unroll
    for (int i = 0; i < 4; i++)
        #pragma unroll
        for (int j = 0; j < 4; j++) pp[(i0 + i) * 64 + j0 + j] = acc[i][j];
}

__global__ void normdot_kernel(const float* __restrict__ Wk,
                               const float* __restrict__ T2,
                               const float* __restrict__ Wq,
                               const float* __restrict__ U,
                               float* __restrict__ norms) {
    int i = threadIdx.x;
    float s = 0.f;
    if (blockIdx.x == 0) {
        for (int c = 0; c < 512; c++) s += Wk[c * 512 + i] * T2[c * 512 + i];
        norms[i] = sqrtf(fmaxf(s, 0.f));
    } else {
        for (int c = 0; c < 512; c++) s += Wq[c * 512 + i] * U[c * 512 + i];
        norms[512 + i] = sqrtf(fmaxf(s, 0.f));
    }
}

// --------------------------- attention + fold into Wp -----------------------
__global__ void attn_kernel(const float* __restrict__ G,
                            const float* __restrict__ norms,
                            const float* __restrict__ rescale,
                            float* __restrict__ attn) {
    int h = blockIdx.x;
    int i = threadIdx.x;
    __shared__ float row[64][64];
    float nk = fmaxf(norms[h * 64 + i], 1e-12f);
    float rs = rescale[h];
    float mx = -1e30f;
    for (int j = 0; j < 64; j++) {
        float nq = fmaxf(norms[512 + h * 64 + j], 1e-12f);
        float vv = G[h * 4096 + i * 64 + j] * rs / (nk * nq);
        row[i][j] = vv;
        mx = fmaxf(mx, vv);
    }
    float s = 0.f;
    for (int j = 0; j < 64; j++) {
        float e = expf(row[i][j] - mx);
        row[i][j] = e;
        s += e;
    }
    float inv = 1.f / s;
    for (int j = 0; j < 64; j++)
        attn[h * 4096 + i * 64 + j] = row[i][j] * inv;
}

// Wp_eff^T[m][h*64+j] (fp16) for the fp16 final GEMM
__global__ void wpeffT_kernel(const float* __restrict__ attn,
                              const float* __restrict__ Wp,
                              __half* __restrict__ wpeT) {
    int cp = blockIdx.x;
    int h = cp >> 6, j = cp & 63;
    int t = threadIdx.x;
    float a0 = 0.f, a1 = 0.f, a2 = 0.f, a3 = 0.f;
    const float* at = attn + h * 4096 + j;
    for (int i = 0; i < 64; i++) {
        float a = at[i * 64];
        const float* w = Wp + (size_t)((h << 6) + i) * CCH;
        a0 += a * w[t];
        a1 += a * w[t + 128];
        a2 += a * w[t + 256];
        a3 += a * w[t + 384];
    }
    wpeT[(size_t)(t) * CCH + cp]       = __float2half(a0);
    wpeT[(size_t)(t + 128) * CCH + cp] = __float2half(a1);
    wpeT[(size_t)(t + 256) * CCH + cp] = __float2half(a2);
    wpeT[(size_t)(t + 384) * CCH + cp] = __float2half(a3);
}

// --------------------- fused positional branch (dw-gelu-dw) ------------------
__global__ void __launch_bounds__(256) pe_fused_kernel(
    const float* __restrict__ V, const float* __restrict__ w1,
    const float* __restrict__ w2, float* __restrict__ peb) {
    __shared__ float vt[20][20][16];
    __shared__ float mid[18][18][16];
    __shared__ float w1s[16][9], w2s[16][9];

    int x0 = blockIdx.x << 4, y0 = blockIdx.y << 4, c0 = blockIdx.z << 4;
    int tid = threadIdx.x;

    if (tid < 144) {
        int cc = tid / 9, kk = tid % 9;
        w1s[cc][kk] = w1[(c0 + cc) * 9 + kk];
        w2s[cc][kk] = w2[(c0 + cc) * 9 + kk];
    }
    for (int e = tid; e < 6400; e += 256) {
        int cc = e & 15;
        int rest = e >> 4;
        int px = rest % 20, py = rest / 20;
        int xx = x0 + px - 2, yy = y0 + py - 2;
        float v = 0.f;
        if (xx >= 0 && xx < WW && yy >= 0 && yy < HH)
            v = V[((size_t)(yy << 8) + xx) * CCH + c0 + cc];
        vt[py][px][cc] = v;
    }
    __syncthreads();
    for (int e = tid; e < 5184; e += 256) {
        int cc = e & 15;
        int rest = e >> 4;
        int mx = rest % 18, my = rest / 18;
        int gx = x0 + mx - 1, gy = y0 + my - 1;
        bool inimg = (gx >= 0 && gx < WW && gy >= 0 && gy < HH);
        float r = 0.f;
        if (inimg) {
            float acc = 0.f;
            #pragma unroll
            for (int ky = 0; ky < 3; ky++)
                #pragma unroll
                for (int kx = 0; kx < 3; kx++)
                    acc += w1s[cc][ky * 3 + kx] * vt[my + ky][mx + kx][cc];
            r = 0.5f * acc * (1.f + erff(acc * 0.70710678118654752f));
        }
        mid[my][mx][cc] = r;
    }
    __syncthreads();
    for (int e = tid; e < 4096; e += 256) {
        int cc = e & 15;
        int ox = (e >> 4) & 15;
        int oy = e >> 8;
        float acc = 0.f;
        #pragma unroll
        for (int ky = 0; ky < 3; ky++)
            #pragma unroll
            for (int kx = 0; kx < 3; kx++)
                acc += w2s[cc][ky * 3 + kx] * mid[oy + ky][ox + kx][cc];
        size_t oi = ((size_t)((y0 + oy) << 8) + x0 + ox) * CCH + c0 + cc;
        peb[oi] = acc;
    }
}

// --------------------------------- launch -----------------------------------
extern "C" void kernel_launch(void* const* d_in, const int* in_sizes, int n_in,
                              void* d_out, int out_size) {
    const float* x       = (const float*)d_in[0];
    const float* sar     = (const float*)d_in[1];
    const float* Wq      = (const float*)d_in[2];
    const float* Wk      = (const float*)d_in[3];
    const float* Wv      = (const float*)d_in[4];
    const float* rescale = (const float*)d_in[5];
    const float* Wp      = (const float*)d_in[6];
    const float* bp      = (const float*)d_in[7];
    const float* pe1w    = (const float*)d_in[8];
    const float* pe2w    = (const float*)d_in[9];
    const float* conv3w  = (const float*)d_in[10];
    const float* conv3b  = (const float*)d_in[11];
    const float* bng     = (const float*)d_in[12];
    const float* bnb     = (const float*)d_in[13];
    const float* sobelb  = (const float*)d_in[14];
    const float* conv2w  = (const float*)d_in[15];
    const float* conv2b  = (const float*)d_in[16];
    const float* conv32w = (const float*)d_in[17];
    const float* conv32b = (const float*)d_in[18];
    const float* dconvw  = (const float*)d_in[19];
    const float* dconvb  = (const float*)d_in[20];
    float* out = (float*)d_out;

    float *v, *peb, *a, *ss, *bnp, *gpart, *S, *U, *T2, *gram, *norms, *attn;
    __half *xh, *vmh, *Fh, *W1h, *W2h, *WvTh, *wpeTh;
    cudaGetSymbolAddress((void**)&v, g_v);
    cudaGetSymbolAddress((void**)&peb, g_peb);
    cudaGetSymbolAddress((void**)&a, g_a);
    cudaGetSymbolAddress((void**)&ss, g_ss);
    cudaGetSymbolAddress((void**)&bnp, g_bnp);
    cudaGetSymbolAddress((void**)&gpart, g_gpart);
    cudaGetSymbolAddress((void**)&S, g_S);
    cudaGetSymbolAddress((void**)&U, g_U);
    cudaGetSymbolAddress((void**)&T2, g_T2);
    cudaGetSymbolAddress((void**)&gram, g_gram);
    cudaGetSymbolAddress((void**)&norms, g_norms);
    cudaGetSymbolAddress((void**)&attn, g_attn);
    cudaGetSymbolAddress((void**)&xh, g_xh);
    cudaGetSymbolAddress((void**)&vmh, g_vmh);
    cudaGetSymbolAddress((void**)&Fh, g_Fh);
    cudaGetSymbolAddress((void**)&W1h, g_W1h);
    cudaGetSymbolAddress((void**)&W2h, g_W2h);
    cudaGetSymbolAddress((void**)&WvTh, g_WvTh);
    cudaGetSymbolAddress((void**)&wpeTh, g_wpeTh);

    const int SM_GEMM = STGF * 3 * sizeof(float);   // tf32 small GEMM
    const int SM_XTX = XSTGF * 3 * sizeof(float);
    const int SM_H = 3 * H_STGB;                    // 61440
    const int SM_M = 3 * M_STGB;                    // 55296
    cudaFuncSetAttribute(tgemm_pipe,
                         cudaFuncAttributeMaxDynamicSharedMemorySize, SM_GEMM);
    cudaFuncSetAttribute(xtx_pipe,
                         cudaFuncAttributeMaxDynamicSharedMemorySize, SM_XTX);
    cudaFuncSetAttribute(hgemm_pipe<0>,
                         cudaFuncAttributeMaxDynamicSharedMemorySize, SM_H);
    cudaFuncSetAttribute(hgemm_pipe<1>,
                         cudaFuncAttributeMaxDynamicSharedMemorySize, SM_H);
    cudaFuncSetAttribute(maskgemm_h,
                         cudaFuncAttributeMaxDynamicSharedMemorySize, SM_M);

    // streams / events (created once, outside capture on the first call)
    static cudaStream_t s1 = nullptr, s2 = nullptr;
    static cudaEvent_t ev_fork = nullptr, ev_sar = nullptr, ev_v = nullptr,
                       ev_aux = nullptr, ev_pe = nullptr;
    if (!s1) {
        cudaStreamCreateWithFlags(&s1, cudaStreamNonBlocking);
        cudaStreamCreateWithFlags(&s2, cudaStreamNonBlocking);
        cudaEventCreateWithFlags(&ev_fork, cudaEventDisableTiming);
        cudaEventCreateWithFlags(&ev_sar, cudaEventDisableTiming);
        cudaEventCreateWithFlags(&ev_v, cudaEventDisableTiming);
        cudaEventCreateWithFlags(&ev_aux, cudaEventDisableTiming);
        cudaEventCreateWithFlags(&ev_pe, cudaEventDisableTiming);
    }
    cudaStream_t s0 = 0;

    // fork
    cudaEventRecord(ev_fork, s0);
    cudaStreamWaitEvent(s1, ev_fork, 0);
    cudaStreamWaitEvent(s2, ev_fork, 0);

    // ---- stream s1: SAR path + XtX/gram/attn/wpeff chain ----
    conv3_kernel<<<256, 256, 0, s1>>>(sar, conv3w, conv3b, a);
    bnstats_kernel<<<2, 512, 0, s1>>>(a, bng, bnb, bnp);
    sobel_ss_kernel<<<256, 256, 0, s1>>>(a, bnp, sobelb, ss);
    fbuild_kernel<<<1024, 256, 0, s1>>>(ss, Fh);
    wbuild_kernel<<<1, 512, 0, s1>>>(conv2w, conv2b, conv32w, conv32b,
                                     dconvw, dconvb, W1h, W2h);
    cudaEventRecord(ev_sar, s1);
    xtx_pipe<<<dim3(10, 32), 256, SM_XTX, s1>>>(x, gpart);
    xtx_reduce_sym<<<256, 1024, 0, s1>>>(gpart, S);
    tgemm_pipe<<<dim3(8, 4), 256, SM_GEMM, s1>>>(S, Wq, Wk, U, T2, 512, CCH);
    gramw_kernel<<<dim3(1, 8), 256, 0, s1>>>(Wk, U, gram);
    normdot_kernel<<<2, 512, 0, s1>>>(Wk, T2, Wq, U, norms);
    attn_kernel<<<8, 64, 0, s1>>>(gram, norms, rescale, attn);
    wpeffT_kernel<<<512, 128, 0, s1>>>(attn, Wp, wpeTh);
    cudaEventRecord(ev_aux, s1);

    // ---- stream 0: fp16 conversions, V projection, gated mask ----
    x2h_kernel<<<16384, 256, 0, s0>>>(x, xh);
    transpose_h_kernel<<<dim3(16, 16), dim3(32, 8), 0, s0>>>(Wv, WvTh);
    hgemm_pipe<0><<<dim3(4, 512), 256, SM_H, s0>>>(xh, WvTh, nullptr, nullptr, v);
    cudaEventRecord(ev_v, s0);
    cudaStreamWaitEvent(s0, ev_sar, 0);
    maskgemm_h<<<dim3(4, 512), 256, SM_M, s0>>>(Fh, W1h, W2h, v, vmh);

    // ---- stream s2: positional branch (needs v only) ----
    cudaStreamWaitEvent(s2, ev_v, 0);
    pe_fused_kernel<<<dim3(16, 16, 32), 256, 0, s2>>>(v, pe1w, pe2w, peb);
    cudaEventRecord(ev_pe, s2);

    // ---- join: final fp16 GEMM with fused bias+pe epilogue ----
    cudaStreamWaitEvent(s0, ev_aux, 0);
    cudaStreamWaitEvent(s0, ev_pe, 0);
    hgemm_pipe<1><<<dim3(4, 512), 256, SM_H, s0>>>(vmh, wpeTh, bp, peb, out);
}

// round 9
// speedup vs baseline: 3.9889x; 1.0580x over previous
#include <cuda_runtime.h>
#include <cuda_bf16.h>
#include <cuda_fp16.h>
#include <math.h>
#include <stdint.h>

// ---------------------------------------------------------------------------
// MS_MSA — round 9: all big tensor work on fp16 HMMA (incl. XtX via x^T),
// fp16 v/peb traffic, dual-stream overlap.
// ---------------------------------------------------------------------------

#define NTOK 65536
#define CCH  512
#define HH   256
#define WW   256

// ------------------------- scratch (device globals) ------------------------
__device__ __half g_vh[33554432];     // v_inp fp16 [n, c]
__device__ __half g_xh[33554432];     // x fp16 [n, c]
__device__ __half g_xhT[33554432];    // x^T fp16 [c, n]
__device__ __half g_vmh[33554432];    // vm fp16 [n, c]
__device__ __half g_pebh[33554432];   // positional branch fp16 [n, c]
__device__ __half g_Fh[5242880];      // mask features [n, 80]
__device__ __half g_W1h[40960];       // [c][80]
__device__ __half g_W2h[40960];       // [c][80]
__device__ __half g_WvTh[262144];     // Wv^T [cout][cin]
__device__ __half g_wpeTh[262144];    // Wp_eff^T [m][cp]
__device__ float  g_a[131072];
__device__ float  g_ss[131072];
__device__ float  g_bnp[4];
__device__ float  g_gpart[4194304];   // XtX partials [16][512*512]
__device__ float  g_S[262144];
__device__ float  g_U[262144];
__device__ float  g_T2[262144];
__device__ float  g_gram[32768];
__device__ float  g_norms[1024];
__device__ float  g_attn[32768];

// ------------------------------ SAR path -----------------------------------

__global__ void conv3_kernel(const float* __restrict__ sar,
                             const float* __restrict__ w,
                             const float* __restrict__ b,
                             float* __restrict__ a) {
    int n = blockIdx.x * 256 + threadIdx.x;
    if (n >= NTOK) return;
    int y = n >> 8, x = n & 255;
    #pragma unroll
    for (int co = 0; co < 2; co++) {
        float acc = b[co];
        #pragma unroll
        for (int ci = 0; ci < 2; ci++) {
            #pragma unroll
            for (int ky = 0; ky < 3; ky++) {
                int yy = y + ky - 1;
                if (yy < 0 || yy >= HH) continue;
                #pragma unroll
                for (int kx = 0; kx < 3; kx++) {
                    int xx = x + kx - 1;
                    if (xx < 0 || xx >= WW) continue;
                    acc += w[((co * 2 + ci) * 3 + ky) * 3 + kx] *
                           sar[ci * NTOK + (yy << 8) + xx];
                }
            }
        }
        a[co * NTOK + n] = acc;
    }
}

__global__ void bnstats_kernel(const float* __restrict__ a,
                               const float* __restrict__ gg,
                               const float* __restrict__ bb,
                               float* __restrict__ bnp) {
    int c = blockIdx.x;
    __shared__ float sh[512], sh2[512];
    float s = 0.f, s2 = 0.f;
    for (int i = threadIdx.x; i < NTOK; i += 512) {
        float v = a[c * NTOK + i];
        s += v; s2 += v * v;
    }
    sh[threadIdx.x] = s; sh2[threadIdx.x] = s2;
    __syncthreads();
    for (int st = 256; st > 0; st >>= 1) {
        if (threadIdx.x < st) {
            sh[threadIdx.x] += sh[threadIdx.x + st];
            sh2[threadIdx.x] += sh2[threadIdx.x + st];
        }
        __syncthreads();
    }
    if (threadIdx.x == 0) {
        float mean = sh[0] * (1.f / NTOK);
        float var = sh2[0] * (1.f / NTOK) - mean * mean;
        float sc = gg[c] * rsqrtf(var + 1e-5f);
        bnp[c * 2] = sc;
        bnp[c * 2 + 1] = bb[c] - mean * sc;
    }
}

__global__ void sobel_ss_kernel(const float* __restrict__ a,
                                const float* __restrict__ bnp,
                                const float* __restrict__ sb,
                                float* __restrict__ ss) {
    int n = blockIdx.x * 256 + threadIdx.x;
    if (n >= NTOK) return;
    int y = n >> 8, x = n & 255;
    float sc0 = bnp[0], sh0 = bnp[1], sc1 = bnp[2], sh1 = bnp[3];
    float t[3][3];
    #pragma unroll
    for (int ky = 0; ky < 3; ky++) {
        int yy = y + ky - 1;
        #pragma unroll
        for (int kx = 0; kx < 3; kx++) {
            int xx = x + kx - 1;
            if (yy >= 0 && yy < HH && xx >= 0 && xx < WW) {
                int idx = (yy << 8) + xx;
                t[ky][kx] = a[idx] * sc0 + sh0 + a[NTOK + idx] * sc1 + sh1;
            } else t[ky][kx] = 0.f;
        }
    }
    float gy = -(t[0][0] + 2.f * t[0][1] + t[0][2]) + (t[2][0] + 2.f * t[2][1] + t[2][2]);
    float gx = -(t[0][0] + 2.f * t[1][0] + t[2][0]) + (t[0][2] + 2.f * t[1][2] + t[2][2]);
    float s0 = gy + sb[0], s1 = gx + sb[1], s2 = gy + sb[2], s3 = gx + sb[3];
    float bc0 = a[n] * sc0 + sh0;
    float bc1 = a[NTOK + n] * sc1 + sh1;
    ss[n]        = sqrtf(s0 * s0 + s1 * s1) + bc0;
    ss[NTOK + n] = sqrtf(s2 * s2 + s3 * s3) + bc1;
}

__global__ void __launch_bounds__(256) fbuild_kernel(
    const float* __restrict__ ss, __half* __restrict__ F) {
    __shared__ float Fs[64 * 80];
    int p0 = blockIdx.x * 64;
    int tid = threadIdx.x;
    int pix = tid >> 2;
    int t4 = tid & 3;
    int n = p0 + pix;
    int y = n >> 8, x = n & 255;
    for (int t = t4; t < 25; t += 4) {
        int dy = t / 5, dx = t % 5;
        int yy = y + dy - 2, xx = x + dx - 2;
        bool ok = (yy >= 0 && yy < HH && xx >= 0 && xx < WW);
        float s0 = 0.f, s1 = 0.f;
        if (ok) {
            int idx = (yy << 8) + xx;
            s0 = ss[idx];
            s1 = ss[NTOK + idx];
        }
        Fs[pix * 80 + t] = s0;
        Fs[pix * 80 + 25 + t] = s1;
        Fs[pix * 80 + 50 + t] = ok ? 1.f : 0.f;
    }
    if (t4 == 0) {
        Fs[pix * 80 + 75] = 0.f;
        Fs[pix * 80 + 76] = 0.f;
        Fs[pix * 80 + 77] = 0.f;
        Fs[pix * 80 + 78] = 1.f;
        Fs[pix * 80 + 79] = 0.f;
    }
    __syncthreads();
    __half* dst = F + (size_t)p0 * 80;
    for (int e = tid; e < 64 * 80; e += 256) dst[e] = __float2half(Fs[e]);
}

__global__ void wbuild_kernel(const float* __restrict__ w2c, const float* __restrict__ b2,
                              const float* __restrict__ w32, const float* __restrict__ b32,
                              const float* __restrict__ dw, const float* __restrict__ db,
                              __half* __restrict__ W1, __half* __restrict__ W2) {
    int c = threadIdx.x;
    float w20 = w2c[c * 2], w21 = w2c[c * 2 + 1], bb2 = b2[c], bbd = db[c];
    __half* o1 = W1 + c * 80;
    __half* o2 = W2 + c * 80;
    for (int t = 0; t < 25; t++) {
        float d = dw[c * 25 + t];
        float a0 = d * w20, a1 = d * w21, a2 = d * bb2;
        if (t == 12) { a0 += w20; a1 += w21; a2 += bb2; }
        o1[t] = __float2half(a0);
        o1[25 + t] = __float2half(a1);
        o1[50 + t] = __float2half(a2);
        float e0 = 0.f, e1 = 0.f;
        int dy = t / 5, dx = t % 5;
        if (dy >= 1 && dy <= 3 && dx >= 1 && dx <= 3) {
            int kk = (dy - 1) * 3 + (dx - 1);
            e0 = w32[c * 18 + kk];
            e1 = w32[c * 18 + 9 + kk];
        }
        o2[t] = __float2half(e0);
        o2[25 + t] = __float2half(e1);
        o2[50 + t] = __float2half(0.f);
    }
    for (int kk = 75; kk < 80; kk++) {
        o1[kk] = __float2half((kk == 78) ? bbd : 0.f);
        o2[kk] = __float2half((kk == 78) ? b32[c] : 0.f);
    }
}

// -------------------------- MMA / async helpers ------------------------------
__device__ __forceinline__ float f2tf32(float x) {
    float r;
    asm("cvt.rna.tf32.f32 %0, %1;" : "=f"(r) : "f"(x));
    return r;
}

__device__ __forceinline__ uint32_t ld_tf32(const float* p) {
    return __float_as_uint(f2tf32(*p));
}

__device__ __forceinline__ void mma_tf32(float* c, const uint32_t* a,
                                         const uint32_t* b) {
    asm volatile(
        "mma.sync.aligned.m16n8k8.row.col.f32.tf32.tf32.f32 "
        "{%0,%1,%2,%3}, {%4,%5,%6,%7}, {%8,%9}, {%0,%1,%2,%3};"
        : "+f"(c[0]), "+f"(c[1]), "+f"(c[2]), "+f"(c[3])
        : "r"(a[0]), "r"(a[1]), "r"(a[2]), "r"(a[3]), "r"(b[0]), "r"(b[1]));
}

__device__ __forceinline__ void mma_f16(float* c, const uint32_t* a,
                                        const uint32_t* b) {
    asm volatile(
        "mma.sync.aligned.m16n8k16.row.col.f32.f16.f16.f32 "
        "{%0,%1,%2,%3}, {%4,%5,%6,%7}, {%8,%9}, {%0,%1,%2,%3};"
        : "+f"(c[0]), "+f"(c[1]), "+f"(c[2]), "+f"(c[3])
        : "r"(a[0]), "r"(a[1]), "r"(a[2]), "r"(a[3]), "r"(b[0]), "r"(b[1]));
}

__device__ __forceinline__ uint32_t smaddr(const void* p) {
    return (uint32_t)__cvta_generic_to_shared(p);
}

__device__ __forceinline__ void cpasync16(uint32_t s, const void* g) {
    asm volatile("cp.async.cg.shared.global [%0], [%1], 16;" :: "r"(s), "l"(g));
}

__device__ __forceinline__ void cp_commit() {
    asm volatile("cp.async.commit_group;");
}

// -------------------- fp16 GEMM: C[M,512] = A[M,512] @ BT^T ------------------
// MODE 0: store C as fp16. MODE 1: store fp32 C = acc + bias + half(peb).
#define H_TILEB 10240                   // 128 rows x 80 B
#define H_STGB  (2 * H_TILEB)

template <int MODE>
__global__ void __launch_bounds__(256) hgemm_pipe(
    const __half* __restrict__ A, const __half* __restrict__ BT,
    const float* __restrict__ bias, const __half* __restrict__ peb,
    void* __restrict__ Cv) {
    extern __shared__ char hsm[];
    const int tid = threadIdx.x;
    const int bn = (blockIdx.x & 3) << 7;
    const int bm = blockIdx.y << 7;

    const int lane = tid & 31;
    const int g = lane >> 2;
    const int tig = lane & 3;
    const int w = tid >> 5;
    const int wm = (w >> 2) * 64;
    const int wn = (w & 3) * 32;

    const int crow = tid >> 1;
    const int cseg = (tid & 1) << 4;

    uint32_t sbase = smaddr(hsm);

    float acc[4][4][4];
    #pragma unroll
    for (int i = 0; i < 4; i++)
        #pragma unroll
        for (int j = 0; j < 4; j++)
            #pragma unroll
            for (int e = 0; e < 4; e++) acc[i][j][e] = 0.f;

#define H_ISSUE(cc, ss)                                                         \
    do {                                                                        \
        uint32_t ab_ = sbase + (ss) * H_STGB;                                   \
        uint32_t bb_ = ab_ + H_TILEB;                                           \
        int kk_ = (cc) << 5;                                                    \
        const __half* ga_ = A + (size_t)(bm + crow) * CCH + kk_ + cseg;         \
        uint32_t da_ = ab_ + crow * 80 + cseg * 2;                              \
        cpasync16(da_, ga_);                                                    \
        cpasync16(da_ + 16, ga_ + 8);                                           \
        const __half* gb_ = BT + (size_t)(bn + crow) * CCH + kk_ + cseg;        \
        uint32_t db_ = bb_ + crow * 80 + cseg * 2;                              \
        cpasync16(db_, gb_);                                                    \
        cpasync16(db_ + 16, gb_ + 8);                                           \
        cp_commit();                                                            \
    } while (0)

    H_ISSUE(0, 0);
    H_ISSUE(1, 1);

    int stg = 0;
    for (int c = 0; c < 16; c++) {
        if (c + 1 < 16) asm volatile("cp.async.wait_group 1;");
        else            asm volatile("cp.async.wait_group 0;");
        __syncthreads();
        if (c + 2 < 16) {
            int ns = stg + 2; if (ns >= 3) ns -= 3;
            H_ISSUE(c + 2, ns);
        }
        const __half* As_ = (const __half*)(hsm + stg * H_STGB);
        const __half* Bs_ = As_ + 5120;
        #pragma unroll
        for (int ks = 0; ks < 2; ks++) {
            int ko = ks << 4;
            uint32_t af[4][4];
            #pragma unroll
            for (int mt = 0; mt < 4; mt++) {
                int m = wm + (mt << 4) + g;
                af[mt][0] = *reinterpret_cast<const uint32_t*>(As_ + m * 40 + ko + 2 * tig);
                af[mt][1] = *reinterpret_cast<const uint32_t*>(As_ + (m + 8) * 40 + ko + 2 * tig);
                af[mt][2] = *reinterpret_cast<const uint32_t*>(As_ + m * 40 + ko + 2 * tig + 8);
                af[mt][3] = *reinterpret_cast<const uint32_t*>(As_ + (m + 8) * 40 + ko + 2 * tig + 8);
            }
            uint32_t bf[4][2];
            #pragma unroll
            for (int nt = 0; nt < 4; nt++) {
                int n = wn + (nt << 3) + g;
                bf[nt][0] = *reinterpret_cast<const uint32_t*>(Bs_ + n * 40 + ko + 2 * tig);
                bf[nt][1] = *reinterpret_cast<const uint32_t*>(Bs_ + n * 40 + ko + 2 * tig + 8);
            }
            #pragma unroll
            for (int mt = 0; mt < 4; mt++)
                #pragma unroll
                for (int nt = 0; nt < 4; nt++)
                    mma_f16(acc[mt][nt], af[mt], bf[nt]);
        }
        stg++; if (stg >= 3) stg = 0;
    }

    #pragma unroll
    for (int mt = 0; mt < 4; mt++) {
        int row = bm + wm + (mt << 4) + g;
        #pragma unroll
        for (int nt = 0; nt < 4; nt++) {
            int col = wn + (nt << 3) + (tig << 1);
            if (MODE == 0) {
                __half* C = (__half*)Cv;
                __half2 h0 = __floats2half2_rn(acc[mt][nt][0], acc[mt][nt][1]);
                __half2 h1 = __floats2half2_rn(acc[mt][nt][2], acc[mt][nt][3]);
                *reinterpret_cast<__half2*>(C + (size_t)row * CCH + bn + col) = h0;
                *reinterpret_cast<__half2*>(C + (size_t)(row + 8) * CCH + bn + col) = h1;
            } else {
                float* C = (float*)Cv;
                float b0 = bias[bn + col];
                float b1 = bias[bn + col + 1];
                float2 p0 = __half22float2(*reinterpret_cast<const __half2*>(
                    peb + (size_t)row * CCH + bn + col));
                float2 p1 = __half22float2(*reinterpret_cast<const __half2*>(
                    peb + (size_t)(row + 8) * CCH + bn + col));
                float2 v0, v1;
                v0.x = (acc[mt][nt][0] + b0) + p0.x;
                v0.y = (acc[mt][nt][1] + b1) + p0.y;
                v1.x = (acc[mt][nt][2] + b0) + p1.x;
                v1.y = (acc[mt][nt][3] + b1) + p1.y;
                *reinterpret_cast<float2*>(C + (size_t)row * CCH + bn + col) = v0;
                *reinterpret_cast<float2*>(C + (size_t)(row + 8) * CCH + bn + col) = v1;
            }
        }
    }
}

// ----------------- fp16 XtX: S-partials from x^T (split-K) -------------------
// A = B = xhT [512][NTOK]; tile (i,j) upper-tri (10 tiles), kchunk 16 of 4096.
__global__ void __launch_bounds__(256) xtx_h(
    const __half* __restrict__ XT, float* __restrict__ part) {
    extern __shared__ char hsm[];
    const int tid = threadIdx.x;
    const int til[10] = {0, 0, 0, 0, 1, 1, 1, 2, 2, 3};
    const int tjl[10] = {0, 1, 2, 3, 1, 2, 3, 2, 3, 3};
    const int m0 = til[blockIdx.x] << 7;
    const int n0 = tjl[blockIdx.x] << 7;
    const size_t kbase = (size_t)blockIdx.y * 4096;

    const int lane = tid & 31;
    const int g = lane >> 2;
    const int tig = lane & 3;
    const int w = tid >> 5;
    const int wm = (w >> 2) * 64;
    const int wn = (w & 3) * 32;

    const int crow = tid >> 1;
    const int cseg = (tid & 1) << 4;
    uint32_t sbase = smaddr(hsm);

    float acc[4][4][4];
    #pragma unroll
    for (int i = 0; i < 4; i++)
        #pragma unroll
        for (int j = 0; j < 4; j++)
            #pragma unroll
            for (int e = 0; e < 4; e++) acc[i][j][e] = 0.f;

#define XH_ISSUE(cc, ss)                                                        \
    do {                                                                        \
        uint32_t ab_ = sbase + (ss) * H_STGB;                                   \
        uint32_t bb_ = ab_ + H_TILEB;                                           \
        size_t kk_ = kbase + ((size_t)(cc) << 5);                               \
        const __half* ga_ = XT + (size_t)(m0 + crow) * NTOK + kk_ + cseg;       \
        uint32_t da_ = ab_ + crow * 80 + cseg * 2;                              \
        cpasync16(da_, ga_);                                                    \
        cpasync16(da_ + 16, ga_ + 8);                                           \
        const __half* gb_ = XT + (size_t)(n0 + crow) * NTOK + kk_ + cseg;       \
        uint32_t db_ = bb_ + crow * 80 + cseg * 2;                              \
        cpasync16(db_, gb_);                                                    \
        cpasync16(db_ + 16, gb_ + 8);                                           \
        cp_commit();                                                            \
    } while (0)

    XH_ISSUE(0, 0);
    XH_ISSUE(1, 1);

    int stg = 0;
    for (int c = 0; c < 128; c++) {
        if (c + 1 < 128) asm volatile("cp.async.wait_group 1;");
        else             asm volatile("cp.async.wait_group 0;");
        __syncthreads();
        if (c + 2 < 128) {
            int ns = stg + 2; if (ns >= 3) ns -= 3;
            XH_ISSUE(c + 2, ns);
        }
        const __half* As_ = (const __half*)(hsm + stg * H_STGB);
        const __half* Bs_ = As_ + 5120;
        #pragma unroll
        for (int ks = 0; ks < 2; ks++) {
            int ko = ks << 4;
            uint32_t af[4][4];
            #pragma unroll
            for (int mt = 0; mt < 4; mt++) {
                int m = wm + (mt << 4) + g;
                af[mt][0] = *reinterpret_cast<const uint32_t*>(As_ + m * 40 + ko + 2 * tig);
                af[mt][1] = *reinterpret_cast<const uint32_t*>(As_ + (m + 8) * 40 + ko + 2 * tig);
                af[mt][2] = *reinterpret_cast<const uint32_t*>(As_ + m * 40 + ko + 2 * tig + 8);
                af[mt][3] = *reinterpret_cast<const uint32_t*>(As_ + (m + 8) * 40 + ko + 2 * tig + 8);
            }
            uint32_t bf[4][2];
            #pragma unroll
            for (int nt = 0; nt < 4; nt++) {
                int n = wn + (nt << 3) + g;
                bf[nt][0] = *reinterpret_cast<const uint32_t*>(Bs_ + n * 40 + ko + 2 * tig);
                bf[nt][1] = *reinterpret_cast<const uint32_t*>(Bs_ + n * 40 + ko + 2 * tig + 8);
            }
            #pragma unroll
            for (int mt = 0; mt < 4; mt++)
                #pragma unroll
                for (int nt = 0; nt < 4; nt++)
                    mma_f16(acc[mt][nt], af[mt], bf[nt]);
        }
        stg++; if (stg >= 3) stg = 0;
    }

    float* pp = part + (size_t)blockIdx.y * 262144;
    #pragma unroll
    for (int mt = 0; mt < 4; mt++) {
        int row = m0 + wm + (mt << 4) + g;
        #pragma unroll
        for (int nt = 0; nt < 4; nt++) {
            int col = n0 + wn + (nt << 3) + (tig << 1);
            float2 v0, v1;
            v0.x = acc[mt][nt][0]; v0.y = acc[mt][nt][1];
            v1.x = acc[mt][nt][2]; v1.y = acc[mt][nt][3];
            *reinterpret_cast<float2*>(pp + (size_t)row * 512 + col) = v0;
            *reinterpret_cast<float2*>(pp + (size_t)(row + 8) * 512 + col) = v1;
        }
    }
}

__global__ void xtx_reduce_sym(const float* __restrict__ part,
                               float* __restrict__ S) {
    int e = blockIdx.x * 1024 + threadIdx.x;
    int r = e >> 9, c = e & 511;
    int idx = ((r >> 7) <= (c >> 7)) ? e : ((c << 9) + r);
    float s = 0.f;
    #pragma unroll
    for (int ch = 0; ch < 16; ch++) s += part[(size_t)ch * 262144 + idx];
    S[e] = s;
}

// -------------- fp16 mask GEMM: K=80, dual B, sigmoid + gate -----------------
#define M_TILEB 6144
#define M_STGB  (3 * M_TILEB)

__global__ void __launch_bounds__(256) maskgemm_h(
    const __half* __restrict__ F, const __half* __restrict__ W1,
    const __half* __restrict__ W2, const __half* __restrict__ V,
    __half* __restrict__ vm) {
    extern __shared__ char hsm[];
    const int tid = threadIdx.x;
    const int bn = blockIdx.x << 7;
    const int bm = blockIdx.y << 7;

    const int lane = tid & 31;
    const int g = lane >> 2;
    const int tig = lane & 3;
    const int w = tid >> 5;
    const int wm = (w >> 2) * 64;
    const int wn = (w & 3) * 32;

    const int crow = tid >> 1;
    const int ch8 = (tid & 1) << 3;
    uint32_t sbase = smaddr(hsm);

    float acc1[4][4][4], acc2[4][4][4];
    #pragma unroll
    for (int i = 0; i < 4; i++)
        #pragma unroll
        for (int j = 0; j < 4; j++)
            #pragma unroll
            for (int e = 0; e < 4; e++) { acc1[i][j][e] = 0.f; acc2[i][j][e] = 0.f; }

#define M_ISSUE(cc, ss)                                                         \
    do {                                                                        \
        uint32_t ab_ = sbase + (ss) * M_STGB;                                   \
        uint32_t b1_ = ab_ + M_TILEB;                                           \
        uint32_t b2_ = b1_ + M_TILEB;                                           \
        int kk_ = (cc) << 4;                                                    \
        uint32_t doff_ = crow * 48 + ch8 * 2;                                   \
        cpasync16(ab_ + doff_, F + (size_t)(bm + crow) * 80 + kk_ + ch8);       \
        cpasync16(b1_ + doff_, W1 + (size_t)(bn + crow) * 80 + kk_ + ch8);      \
        cpasync16(b2_ + doff_, W2 + (size_t)(bn + crow) * 80 + kk_ + ch8);      \
        cp_commit();                                                            \
    } while (0)

    M_ISSUE(0, 0);
    M_ISSUE(1, 1);

    int stg = 0;
    for (int c = 0; c < 5; c++) {
        if (c + 1 < 5) asm volatile("cp.async.wait_group 1;");
        else           asm volatile("cp.async.wait_group 0;");
        __syncthreads();
        if (c + 2 < 5) {
            int ns = stg + 2; if (ns >= 3) ns -= 3;
            M_ISSUE(c + 2, ns);
        }
        const __half* As_ = (const __half*)(hsm + stg * M_STGB);
        const __half* B1s = As_ + 3072;
        const __half* B2s = B1s + 3072;
        uint32_t af[4][4];
        #pragma unroll
        for (int mt = 0; mt < 4; mt++) {
            int m = wm + (mt << 4) + g;
            af[mt][0] = *reinterpret_cast<const uint32_t*>(As_ + m * 24 + 2 * tig);
            af[mt][1] = *reinterpret_cast<const uint32_t*>(As_ + (m + 8) * 24 + 2 * tig);
            af[mt][2] = *reinterpret_cast<const uint32_t*>(As_ + m * 24 + 2 * tig + 8);
            af[mt][3] = *reinterpret_cast<const uint32_t*>(As_ + (m + 8) * 24 + 2 * tig + 8);
        }
        #pragma unroll
        for (int nt = 0; nt < 4; nt++) {
            int n = wn + (nt << 3) + g;
            uint32_t bf1[2], bf2[2];
            bf1[0] = *reinterpret_cast<const uint32_t*>(B1s + n * 24 + 2 * tig);
            bf1[1] = *reinterpret_cast<const uint32_t*>(B1s + n * 24 + 2 * tig + 8);
            bf2[0] = *reinterpret_cast<const uint32_t*>(B2s + n * 24 + 2 * tig);
            bf2[1] = *reinterpret_cast<const uint32_t*>(B2s + n * 24 + 2 * tig + 8);
            #pragma unroll
            for (int mt = 0; mt < 4; mt++) {
                mma_f16(acc1[mt][nt], af[mt], bf1);
                mma_f16(acc2[mt][nt], af[mt], bf2);
            }
        }
        stg++; if (stg >= 3) stg = 0;
    }

    #pragma unroll
    for (int mt = 0; mt < 4; mt++) {
        int row = bm + wm + (mt << 4) + g;
        #pragma unroll
        for (int nt = 0; nt < 4; nt++) {
            int col = wn + (nt << 3) + (tig << 1);
            float2 va = __half22float2(*reinterpret_cast<const __half2*>(
                V + (size_t)row * CCH + bn + col));
            float2 vb = __half22float2(*reinterpret_cast<const __half2*>(
                V + (size_t)(row + 8) * CCH + bn + col));
            float m0 = (acc1[mt][nt][0] + 1.f / (1.f + expf(-acc2[mt][nt][0]))) * va.x;
            float m1 = (acc1[mt][nt][1] + 1.f / (1.f + expf(-acc2[mt][nt][1]))) * va.y;
            float m2 = (acc1[mt][nt][2] + 1.f / (1.f + expf(-acc2[mt][nt][2]))) * vb.x;
            float m3 = (acc1[mt][nt][3] + 1.f / (1.f + expf(-acc2[mt][nt][3]))) * vb.y;
            __half2 h0 = __floats2half2_rn(m0, m1);
            __half2 h1 = __floats2half2_rn(m2, m3);
            *reinterpret_cast<__half2*>(vm + (size_t)row * CCH + bn + col) = h0;
            *reinterpret_cast<__half2*>(vm + (size_t)(row + 8) * CCH + bn + col) = h1;
        }
    }
}

// ---------------------- conversion / transpose kernels -----------------------
__global__ void x2h_kernel(const float* __restrict__ x,
                           __half* __restrict__ xh) {
    size_t i = ((size_t)blockIdx.x * 256 + threadIdx.x) * 8;
    float4 v0 = *reinterpret_cast<const float4*>(x + i);
    float4 v1 = *reinterpret_cast<const float4*>(x + i + 4);
    __half2 h[4];
    h[0] = __floats2half2_rn(v0.x, v0.y);
    h[1] = __floats2half2_rn(v0.z, v0.w);
    h[2] = __floats2half2_rn(v1.x, v1.y);
    h[3] = __floats2half2_rn(v1.z, v1.w);
    *reinterpret_cast<uint4*>(xh + i) = *reinterpret_cast<uint4*>(h);
}

// x [NTOK][512] f32 -> xhT [512][NTOK] half
__global__ void xT2h_kernel(const float* __restrict__ x,
                            __half* __restrict__ xhT) {
    __shared__ float t[32][33];
    int c0 = blockIdx.x << 5;       // channel tile
    int t0 = blockIdx.y << 5;       // token tile
    int tx = threadIdx.x, ty = threadIdx.y;  // 32 x 8
    #pragma unroll
    for (int r = 0; r < 32; r += 8)
        t[ty + r][tx] = x[(size_t)(t0 + ty + r) * CCH + c0 + tx];
    __syncthreads();
    #pragma unroll
    for (int r = 0; r < 32; r += 8)
        xhT[(size_t)(c0 + ty + r) * NTOK + t0 + tx] = __float2half(t[tx][ty + r]);
}

__global__ void transpose_h_kernel(const float* __restrict__ W,
                                   __half* __restrict__ WT) {
    __shared__ float t[32][33];
    int bx = blockIdx.x << 5, by = blockIdx.y << 5;
    int tx = threadIdx.x, ty = threadIdx.y;
    #pragma unroll
    for (int r = 0; r < 32; r += 8)
        t[ty + r][tx] = W[(size_t)(by + ty + r) * CCH + bx + tx];
    __syncthreads();
    #pragma unroll
    for (int r = 0; r < 32; r += 8)
        WT[(size_t)(bx + ty + r) * CCH + by + tx] = __float2half(t[tx][ty + r]);
}

// -------------------------- legacy TF32 GEMM (small) -------------------------
#define ASF 2560
#define BSF 2176
#define STGF (ASF + BSF)

__global__ void __launch_bounds__(256) tgemm_pipe(
    const float* __restrict__ A,
    const float* __restrict__ B0, const float* __restrict__ B1,
    float* __restrict__ C0, float* __restrict__ C1, int M, int K) {
    extern __shared__ float sm[];

    const int tid = threadIdx.x;
    const int which = blockIdx.x >> 2;
    const float* B = (which == 0) ? B0 : B1;
    float* C = (which == 0) ? C0 : C1;
    const int bn = (blockIdx.x & 3) << 7;
    const int bm = blockIdx.y << 7;

    const int lane = tid & 31;
    const int g = lane >> 2;
    const int tig = lane & 3;
    const int w = tid >> 5;
    const int wm = (w >> 2) * 64;
    const int wn = (w & 3) * 32;

    const int arow = tid >> 1, acol = (tid & 1) << 3;
    const int brow = tid >> 4, bcol = (tid & 15) << 3;

    float acc[4][4][4];
    #pragma unroll
    for (int i = 0; i < 4; i++)
        #pragma unroll
        for (int j = 0; j < 4; j++)
            #pragma unroll
            for (int e = 0; e < 4; e++) acc[i][j][e] = 0.f;

    const int NK = K >> 4;

#define PIPE_ISSUE(stg, kk)                                                     \
    do {                                                                        \
        float* As_ = sm + (stg) * STGF;                                         \
        float* Bs_ = As_ + ASF;                                                 \
        const float* ga = A + (size_t)(bm + arow) * K + (kk) + acol;            \
        uint32_t sa = smaddr(As_ + arow * 20 + acol);                           \
        cpasync16(sa, ga);                                                      \
        cpasync16(sa + 16, ga + 4);                                             \
        const float* gb = B + (size_t)((kk) + brow) * CCH + bn + bcol;          \
        uint32_t sb = smaddr(Bs_ + brow * 136 + bcol);                          \
        cpasync16(sb, gb);                                                      \
        cpasync16(sb + 16, gb + 4);                                             \
        cp_commit();                                                            \
    } while (0)

    PIPE_ISSUE(0, 0);
    PIPE_ISSUE(1, 16);

    int stg = 0;
    for (int kt = 0; kt < NK; kt++) {
        if (kt + 1 < NK) asm volatile("cp.async.wait_group 1;");
        else             asm volatile("cp.async.wait_group 0;");
        __syncthreads();
        if (kt + 2 < NK) {
            int ns = stg + 2; if (ns >= 3) ns -= 3;
            PIPE_ISSUE(ns, (kt + 2) << 4);
        }
        const float* As_ = sm + stg * STGF;
        const float* Bs_ = As_ + ASF;
        #pragma unroll
        for (int ks = 0; ks < 2; ks++) {
            int kk = ks << 3;
            uint32_t af[4][4];
            #pragma unroll
            for (int mt = 0; mt < 4; mt++) {
                int m0 = wm + (mt << 4) + g;
                af[mt][0] = ld_tf32(As_ + m0 * 20 + kk + tig);
                af[mt][1] = ld_tf32(As_ + (m0 + 8) * 20 + kk + tig);
                af[mt][2] = ld_tf32(As_ + m0 * 20 + kk + tig + 4);
                af[mt][3] = ld_tf32(As_ + (m0 + 8) * 20 + kk + tig + 4);
            }
            uint32_t bf[4][2];
            #pragma unroll
            for (int nt = 0; nt < 4; nt++) {
                int n0 = wn + (nt << 3) + g;
                bf[nt][0] = ld_tf32(Bs_ + (kk + tig) * 136 + n0);
                bf[nt][1] = ld_tf32(Bs_ + (kk + tig + 4) * 136 + n0);
            }
            #pragma unroll
            for (int mt = 0; mt < 4; mt++)
                #pragma unroll
                for (int nt = 0; nt < 4; nt++)
                    mma_tf32(acc[mt][nt], af[mt], bf[nt]);
        }
        stg++; if (stg >= 3) stg = 0;
    }

    #pragma unroll
    for (int mt = 0; mt < 4; mt++) {
        int row = bm + wm + (mt << 4) + g;
        #pragma unroll
        for (int nt = 0; nt < 4; nt++) {
            int col = wn + (nt << 3) + (tig << 1);
            float2 v0, v1;
            v0.x = acc[mt][nt][0]; v0.y = acc[mt][nt][1];
            v1.x = acc[mt][nt][2]; v1.y = acc[mt][nt][3];
            *reinterpret_cast<float2*>(C + (size_t)row * CCH + bn + col) = v0;
            *reinterpret_cast<float2*>(C + (size_t)(row + 8) * CCH + bn + col) = v1;
        }
    }
}

// ---------------- per-head Gram from weights: G = Wk_h^T U_h ----------------
__global__ void __launch_bounds__(256) gramw_kernel(
    const float* __restrict__ Km, const float* __restrict__ Qm,
    float* __restrict__ gram) {
    int h = blockIdx.y;
    __shared__ float ks[64][64];
    __shared__ float qs[64][64];
    int tid = threadIdx.x;
    int lt = tid >> 2;
    int lc = (tid & 3) * 16;
    int i0 = (tid >> 4) * 4;
    int j0 = (tid & 15) * 4;
    float acc[4][4];
    #pragma unroll
    for (int i = 0; i < 4; i++)
        #pragma unroll
        for (int j = 0; j < 4; j++) acc[i][j] = 0.f;

    for (int sub = 0; sub < 8; sub++) {
        int row = sub * 64 + lt;
        const float* kp = Km + (size_t)row * CCH + h * 64 + lc;
        const float* qp = Qm + (size_t)row * CCH + h * 64 + lc;
        #pragma unroll
        for (int u = 0; u < 4; u++) {
            *reinterpret_cast<float4*>(&ks[lt][lc + u * 4]) =
                *reinterpret_cast<const float4*>(kp + u * 4);
            *reinterpret_cast<float4*>(&qs[lt][lc + u * 4]) =
                *reinterpret_cast<const float4*>(qp + u * 4);
        }
        __syncthreads();
        #pragma unroll
        for (int t = 0; t < 64; t++) {
            float4 kv = *reinterpret_cast<const float4*>(&ks[t][i0]);
            float4 qv = *reinterpret_cast<const float4*>(&qs[t][j0]);
            float kr[4] = {kv.x, kv.y, kv.z, kv.w};
            float qr[4] = {qv.x, qv.y, qv.z, qv.w};
            #pragma unroll
            for (int i = 0; i < 4; i++)
                #pragma unroll
                for (int j = 0; j < 4; j++) acc[i][j] += kr[i] * qr[j];
        }
        __syncthreads();
    }
    float* pp = gram + (size_t)h * 4096;
    #pragma unroll
    for (int i = 0; i < 4; i++)
        #pragma unroll
        for (int j = 0; j < 4; j++) pp[(i0 + i) * 64 + j0 + j] = acc[i][j];
}

__global__ void normdot_kernel(const float* __restrict__ Wk,
                               const float* __restrict__ T2,
                               const float* __restrict__ Wq,
                               const float* __restrict__ U,
                               float* __restrict__ norms) {
    int i = threadIdx.x;
    float s = 0.f;
    if (blockIdx.x == 0) {
        for (int c = 0; c < 512; c++) s += Wk[c * 512 + i] * T2[c * 512 + i];
        norms[i] = sqrtf(fmaxf(s, 0.f));
    } else {
        for (int c = 0; c < 512; c++) s += Wq[c * 512 + i] * U[c * 512 + i];
        norms[512 + i] = sqrtf(fmaxf(s, 0.f));
    }
}

// --------------------------- attention + fold into Wp -----------------------
__global__ void attn_kernel(const float* __restrict__ G,
                            const float* __restrict__ norms,
                            const float* __restrict__ rescale,
                            float* __restrict__ attn) {
    int h = blockIdx.x;
    int i = threadIdx.x;
    __shared__ float row[64][64];
    float nk = fmaxf(norms[h * 64 + i], 1e-12f);
    float rs = rescale[h];
    float mx = -1e30f;
    for (int j = 0; j < 64; j++) {
        float nq = fmaxf(norms[512 + h * 64 + j], 1e-12f);
        float vv = G[h * 4096 + i * 64 + j] * rs / (nk * nq);
        row[i][j] = vv;
        mx = fmaxf(mx, vv);
    }
    float s = 0.f;
    for (int j = 0; j < 64; j++) {
        float e = expf(row[i][j] - mx);
        row[i][j] = e;
        s += e;
    }
    float inv = 1.f / s;
    for (int j = 0; j < 64; j++)
        attn[h * 4096 + i * 64 + j] = row[i][j] * inv;
}

__global__ void wpeffT_kernel(const float* __restrict__ attn,
                              const float* __restrict__ Wp,
                              __half* __restrict__ wpeT) {
    int cp = blockIdx.x;
    int h = cp >> 6, j = cp & 63;
    int t = threadIdx.x;
    float a0 = 0.f, a1 = 0.f, a2 = 0.f, a3 = 0.f;
    const float* at = attn + h * 4096 + j;
    for (int i = 0; i < 64; i++) {
        float a = at[i * 64];
        const float* w = Wp + (size_t)((h << 6) + i) * CCH;
        a0 += a * w[t];
        a1 += a * w[t + 128];
        a2 += a * w[t + 256];
        a3 += a * w[t + 384];
    }
    wpeT[(size_t)(t) * CCH + cp]       = __float2half(a0);
    wpeT[(size_t)(t + 128) * CCH + cp] = __float2half(a1);
    wpeT[(size_t)(t + 256) * CCH + cp] = __float2half(a2);
    wpeT[(size_t)(t + 384) * CCH + cp] = __float2half(a3);
}

// --------------------- fused positional branch (dw-gelu-dw) ------------------
__global__ void __launch_bounds__(256) pe_fused_kernel(
    const __half* __restrict__ V, const float* __restrict__ w1,
    const float* __restrict__ w2, __half* __restrict__ peb) {
    __shared__ float vt[20][20][16];
    __shared__ float mid[18][18][16];
    __shared__ float w1s[16][9], w2s[16][9];

    int x0 = blockIdx.x << 4, y0 = blockIdx.y << 4, c0 = blockIdx.z << 4;
    int tid = threadIdx.x;

    if (tid < 144) {
        int cc = tid / 9, kk = tid % 9;
        w1s[cc][kk] = w1[(c0 + cc) * 9 + kk];
        w2s[cc][kk] = w2[(c0 + cc) * 9 + kk];
    }
    for (int e = tid; e < 6400; e += 256) {
        int cc = e & 15;
        int rest = e >> 4;
        int px = rest % 20, py = rest / 20;
        int xx = x0 + px - 2, yy = y0 + py - 2;
        float v = 0.f;
        if (xx >= 0 && xx < WW && yy >= 0 && yy < HH)
            v = __half2float(V[((size_t)(yy << 8) + xx) * CCH + c0 + cc]);
        vt[py][px][cc] = v;
    }
    __syncthreads();
    for (int e = tid; e < 5184; e += 256) {
        int cc = e & 15;
        int rest = e >> 4;
        int mx = rest % 18, my = rest / 18;
        int gx = x0 + mx - 1, gy = y0 + my - 1;
        bool inimg = (gx >= 0 && gx < WW && gy >= 0 && gy < HH);
        float r = 0.f;
        if (inimg) {
            float acc = 0.f;
            #pragma unroll
            for (int ky = 0; ky < 3; ky++)
                #pragma unroll
                for (int kx = 0; kx < 3; kx++)
                    acc += w1s[cc][ky * 3 + kx] * vt[my + ky][mx + kx][cc];
            r = 0.5f * acc * (1.f + erff(acc * 0.70710678118654752f));
        }
        mid[my][mx][cc] = r;
    }
    __syncthreads();
    for (int e = tid; e < 4096; e += 256) {
        int cc = e & 15;
        int ox = (e >> 4) & 15;
        int oy = e >> 8;
        float acc = 0.f;
        #pragma unroll
        for (int ky = 0; ky < 3; ky++)
            #pragma unroll
            for (int kx = 0; kx < 3; kx++)
                acc += w2s[cc][ky * 3 + kx] * mid[oy + ky][ox + kx][cc];
        size_t oi = ((size_t)((y0 + oy) << 8) + x0 + ox) * CCH + c0 + cc;
        peb[oi] = __float2half(acc);
    }
}

// --------------------------------- launch -----------------------------------
extern "C" void kernel_launch(void* const* d_in, const int* in_sizes, int n_in,
                              void* d_out, int out_size) {
    const float* x       = (const float*)d_in[0];
    const float* sar     = (const float*)d_in[1];
    const float* Wq      = (const float*)d_in[2];
    const float* Wk      = (const float*)d_in[3];
    const float* Wv      = (const float*)d_in[4];
    const float* rescale = (const float*)d_in[5];
    const float* Wp      = (const float*)d_in[6];
    const float* bp      = (const float*)d_in[7];
    const float* pe1w    = (const float*)d_in[8];
    const float* pe2w    = (const float*)d_in[9];
    const float* conv3w  = (const float*)d_in[10];
    const float* conv3b  = (const float*)d_in[11];
    const float* bng     = (const float*)d_in[12];
    const float* bnb     = (const float*)d_in[13];
    const float* sobelb  = (const float*)d_in[14];
    const float* conv2w  = (const float*)d_in[15];
    const float* conv2b  = (const float*)d_in[16];
    const float* conv32w = (const float*)d_in[17];
    const float* conv32b = (const float*)d_in[18];
    const float* dconvw  = (const float*)d_in[19];
    const float* dconvb  = (const float*)d_in[20];
    float* out = (float*)d_out;

    float *a, *ss, *bnp, *gpart, *S, *U, *T2, *gram, *norms, *attn;
    __half *vh, *xh, *xhT, *vmh, *pebh, *Fh, *W1h, *W2h, *WvTh, *wpeTh;
    cudaGetSymbolAddress((void**)&a, g_a);
    cudaGetSymbolAddress((void**)&ss, g_ss);
    cudaGetSymbolAddress((void**)&bnp, g_bnp);
    cudaGetSymbolAddress((void**)&gpart, g_gpart);
    cudaGetSymbolAddress((void**)&S, g_S);
    cudaGetSymbolAddress((void**)&U, g_U);
    cudaGetSymbolAddress((void**)&T2, g_T2);
    cudaGetSymbolAddress((void**)&gram, g_gram);
    cudaGetSymbolAddress((void**)&norms, g_norms);
    cudaGetSymbolAddress((void**)&attn, g_attn);
    cudaGetSymbolAddress((void**)&vh, g_vh);
    cudaGetSymbolAddress((void**)&xh, g_xh);
    cudaGetSymbolAddress((void**)&xhT, g_xhT);
    cudaGetSymbolAddress((void**)&vmh, g_vmh);
    cudaGetSymbolAddress((void**)&pebh, g_pebh);
    cudaGetSymbolAddress((void**)&Fh, g_Fh);
    cudaGetSymbolAddress((void**)&W1h, g_W1h);
    cudaGetSymbolAddress((void**)&W2h, g_W2h);
    cudaGetSymbolAddress((void**)&WvTh, g_WvTh);
    cudaGetSymbolAddress((void**)&wpeTh, g_wpeTh);

    const int SM_GEMM = STGF * 3 * sizeof(float);
    const int SM_H = 3 * H_STGB;
    const int SM_M = 3 * M_STGB;
    cudaFuncSetAttribute(tgemm_pipe,
                         cudaFuncAttributeMaxDynamicSharedMemorySize, SM_GEMM);
    cudaFuncSetAttribute(hgemm_pipe<0>,
                         cudaFuncAttributeMaxDynamicSharedMemorySize, SM_H);
    cudaFuncSetAttribute(hgemm_pipe<1>,
                         cudaFuncAttributeMaxDynamicSharedMemorySize, SM_H);
    cudaFuncSetAttribute(xtx_h,
                         cudaFuncAttributeMaxDynamicSharedMemorySize, SM_H);
    cudaFuncSetAttribute(maskgemm_h,
                         cudaFuncAttributeMaxDynamicSharedMemorySize, SM_M);

    static cudaStream_t s1 = nullptr, s2 = nullptr;
    static cudaEvent_t ev_fork = nullptr, ev_sar = nullptr, ev_v = nullptr,
                       ev_aux = nullptr, ev_pe = nullptr;
    if (!s1) {
        cudaStreamCreateWithFlags(&s1, cudaStreamNonBlocking);
        cudaStreamCreateWithFlags(&s2, cudaStreamNonBlocking);
        cudaEventCreateWithFlags(&ev_fork, cudaEventDisableTiming);
        cudaEventCreateWithFlags(&ev_sar, cudaEventDisableTiming);
        cudaEventCreateWithFlags(&ev_v, cudaEventDisableTiming);
        cudaEventCreateWithFlags(&ev_aux, cudaEventDisableTiming);
        cudaEventCreateWithFlags(&ev_pe, cudaEventDisableTiming);
    }
    cudaStream_t s0 = 0;

    cudaEventRecord(ev_fork, s0);
    cudaStreamWaitEvent(s1, ev_fork, 0);
    cudaStreamWaitEvent(s2, ev_fork, 0);

    // ---- stream s1: x^T (for XtX) + SAR path + gram/attn chain ----
    xT2h_kernel<<<dim3(16, 2048), dim3(32, 8), 0, s1>>>(x, xhT);
    conv3_kernel<<<256, 256, 0, s1>>>(sar, conv3w, conv3b, a);
    bnstats_kernel<<<2, 512, 0, s1>>>(a, bng, bnb, bnp);
    sobel_ss_kernel<<<256, 256, 0, s1>>>(a, bnp, sobelb, ss);
    fbuild_kernel<<<1024, 256, 0, s1>>>(ss, Fh);
    wbuild_kernel<<<1, 512, 0, s1>>>(conv2w, conv2b, conv32w, conv32b,
                                     dconvw, dconvb, W1h, W2h);
    cudaEventRecord(ev_sar, s1);
    xtx_h<<<dim3(10, 16), 256, SM_H, s1>>>(xhT, gpart);
    xtx_reduce_sym<<<256, 1024, 0, s1>>>(gpart, S);
    tgemm_pipe<<<dim3(8, 4), 256, SM_GEMM, s1>>>(S, Wq, Wk, U, T2, 512, CCH);
    gramw_kernel<<<dim3(1, 8), 256, 0, s1>>>(Wk, U, gram);
    normdot_kernel<<<2, 512, 0, s1>>>(Wk, T2, Wq, U, norms);
    attn_kernel<<<8, 64, 0, s1>>>(gram, norms, rescale, attn);
    wpeffT_kernel<<<512, 128, 0, s1>>>(attn, Wp, wpeTh);
    cudaEventRecord(ev_aux, s1);

    // ---- stream 0: fp16 conversions, V projection (fp16 out), gated mask ----
    x2h_kernel<<<16384, 256, 0, s0>>>(x, xh);
    transpose_h_kernel<<<dim3(16, 16), dim3(32, 8), 0, s0>>>(Wv, WvTh);
    hgemm_pipe<0><<<dim3(4, 512), 256, SM_H, s0>>>(xh, WvTh, nullptr, nullptr, vh);
    cudaEventRecord(ev_v, s0);
    cudaStreamWaitEvent(s0, ev_sar, 0);
    maskgemm_h<<<dim3(4, 512), 256, SM_M, s0>>>(Fh, W1h, W2h, vh, vmh);

    // ---- stream s2: positional branch (fp16 in/out) ----
    cudaStreamWaitEvent(s2, ev_v, 0);
    pe_fused_kernel<<<dim3(16, 16, 32), 256, 0, s2>>>(vh, pe1w, pe2w, pebh);
    cudaEventRecord(ev_pe, s2);

    // ---- join: final fp16 GEMM with fused bias+pe epilogue ----
    cudaStreamWaitEvent(s0, ev_aux, 0);
    cudaStreamWaitEvent(s0, ev_pe, 0);
    hgemm_pipe<1><<<dim3(4, 512), 256, SM_H, s0>>>(vmh, wpeTh, bp, pebh, out);
}